// round 1
// baseline (speedup 1.0000x reference)
#include <cuda_runtime.h>

// Problem constants
#define Bk   32
#define Nk   1025
#define Dk   768
#define Hh   12
#define dh   64
#define Tt   256          // tiles
#define Kc   257          // context length (R + T)
#define NKp  (Nk*Kc)      // 263425
#define MQ   (Bk*Nk)      // 32800
#define MKV  (Bk*Kc)      // 8224
#define KPAD 68           // padded row stride for K/V smem tiles

// Scratch (device globals — no allocation in kernel_launch)
__device__ float g_ctx [MKV*Dk];       // [B,K,D]  pooled context
__device__ float g_Q   [MQ*Dk];        // [B*N, D]
__device__ float g_KV  [MKV*2*Dk];     // [B*K, 2D]
__device__ float g_bias[(size_t)Hh*NKp]; // [H,N,K]
__device__ float g_O   [MQ*Dk];        // [B*N, D] attention output

// ---------------------------------------------------------------------------
// Pooling: build ctx[b,k,:]. t==Tt copies register token; else softmax-pool 2x2.
// ---------------------------------------------------------------------------
__global__ void pool_kernel(const float* __restrict__ x,
                            const float* __restrict__ wl,
                            float* __restrict__ ctx) {
    int t = blockIdx.x;            // 0..256 (256 == register-token copy)
    int b = blockIdx.y;
    int tid = threadIdx.x;
    const float* xb = x + (size_t)b * Nk * Dk;
    if (t == Tt) {
        float* dst = ctx + (size_t)b * Kc * Dk;
        for (int dd = tid; dd < Dk; dd += 256) dst[dd] = xb[dd];
        return;
    }
    int gy = t >> 4, gx = t & 15;
    int n0 = 1 + (gy * 2) * 32 + gx * 2;
    int rows[4] = { n0, n0 + 1, n0 + 32, n0 + 33 };

    float p[4] = {0.f, 0.f, 0.f, 0.f};
    for (int dd = tid; dd < Dk; dd += 256) {
        float wv = wl[dd];
        p[0] += xb[(size_t)rows[0]*Dk + dd] * wv;
        p[1] += xb[(size_t)rows[1]*Dk + dd] * wv;
        p[2] += xb[(size_t)rows[2]*Dk + dd] * wv;
        p[3] += xb[(size_t)rows[3]*Dk + dd] * wv;
    }
    __shared__ float wred[4][8];
    __shared__ float sw4[4];
    int lane = tid & 31, w = tid >> 5;
    #pragma unroll
    for (int i = 0; i < 4; i++) {
        float v = p[i];
        #pragma unroll
        for (int off = 16; off; off >>= 1) v += __shfl_xor_sync(0xffffffffu, v, off);
        if (lane == 0) wred[i][w] = v;
    }
    __syncthreads();
    if (tid == 0) {
        float s[4];
        #pragma unroll
        for (int i = 0; i < 4; i++) {
            float a = 0.f;
            for (int ww = 0; ww < 8; ww++) a += wred[i][ww];   // fixed order: deterministic
            s[i] = a;
        }
        float m = fmaxf(fmaxf(s[0], s[1]), fmaxf(s[2], s[3]));
        float e[4], su = 0.f;
        #pragma unroll
        for (int i = 0; i < 4; i++) { e[i] = expf(s[i] - m); su += e[i]; }
        float inv = 1.f / su;
        #pragma unroll
        for (int i = 0; i < 4; i++) sw4[i] = e[i] * inv;
    }
    __syncthreads();
    float w0 = sw4[0], w1 = sw4[1], w2 = sw4[2], w3 = sw4[3];
    float* dst = ctx + ((size_t)b * Kc + 1 + t) * Dk;
    for (int dd = tid; dd < Dk; dd += 256)
        dst[dd] = w0 * xb[(size_t)rows[0]*Dk + dd] + w1 * xb[(size_t)rows[1]*Dk + dd]
                + w2 * xb[(size_t)rows[2]*Dk + dd] + w3 * xb[(size_t)rows[3]*Dk + dd];
}

// ---------------------------------------------------------------------------
// CPB bias: bias[h,n,k] = (gelu(feats@w1^T+b1) @ w2^T + b2) * mask
// ---------------------------------------------------------------------------
__global__ void cpb_kernel(const float* __restrict__ feats, const float* __restrict__ mask,
                           const float* __restrict__ w1, const float* __restrict__ b1,
                           const float* __restrict__ w2, const float* __restrict__ b2,
                           float* __restrict__ bias) {
    __shared__ float sw1[64], sb1[32], sw2[12*32], sb2[12];
    int tid = threadIdx.x;
    if (tid < 64) sw1[tid] = w1[tid];
    if (tid >= 64 && tid < 96) sb1[tid - 64] = b1[tid - 64];
    if (tid >= 96 && tid < 108) sb2[tid - 96] = b2[tid - 96];
    for (int i = tid; i < 384; i += 256) sw2[i] = w2[i];
    __syncthreads();
    int idx = blockIdx.x * 256 + tid;
    if (idx >= NKp) return;
    float f0 = feats[2*idx], f1 = feats[2*idx + 1];
    float m = mask[idx];
    float acc[12];
    #pragma unroll
    for (int h = 0; h < 12; h++) acc[h] = sb2[h];
    #pragma unroll
    for (int j = 0; j < 32; j++) {
        float tt = f0 * sw1[2*j] + f1 * sw1[2*j + 1] + sb1[j];
        float g = 0.5f * tt * (1.0f + erff(tt * 0.7071067811865475f));  // exact gelu
        #pragma unroll
        for (int h = 0; h < 12; h++) acc[h] += sw2[h*32 + j] * g;
    }
    #pragma unroll
    for (int h = 0; h < 12; h++) bias[(size_t)h * NKp + idx] = acc[h] * m;
}

// ---------------------------------------------------------------------------
// SGEMM: C[M,Nn] = A[M,Kd] @ W[Nn,Kd]^T (+bias over Nn). 128x128x8, 8x8/thread.
// Nn must be a multiple of 128, Kd a multiple of 8. M-tail guarded.
// ---------------------------------------------------------------------------
__global__ void __launch_bounds__(256, 2)
sgemm_tn(const float* __restrict__ A, const float* __restrict__ W,
         const float* __restrict__ bias, float* __restrict__ C,
         int M, int Nn, int Kd) {
    __shared__ float As[8][128];
    __shared__ float Bs[8][128];
    int tid = threadIdx.x;
    int row0 = blockIdx.y * 128, col0 = blockIdx.x * 128;
    int lr = tid >> 1;
    int lk = (tid & 1) * 4;
    int tx = tid & 15, ty = tid >> 4;
    const float* Ap = A + (size_t)(row0 + lr) * Kd + lk;
    const float* Wp = W + (size_t)(col0 + lr) * Kd + lk;
    bool aval = (row0 + lr) < M;

    float acc[8][8];
    #pragma unroll
    for (int i = 0; i < 8; i++)
        #pragma unroll
        for (int j = 0; j < 8; j++) acc[i][j] = 0.f;

    for (int k0 = 0; k0 < Kd; k0 += 8) {
        float4 av = aval ? *(const float4*)(Ap + k0) : make_float4(0.f,0.f,0.f,0.f);
        float4 wv = *(const float4*)(Wp + k0);
        __syncthreads();
        As[lk+0][lr] = av.x; As[lk+1][lr] = av.y; As[lk+2][lr] = av.z; As[lk+3][lr] = av.w;
        Bs[lk+0][lr] = wv.x; Bs[lk+1][lr] = wv.y; Bs[lk+2][lr] = wv.z; Bs[lk+3][lr] = wv.w;
        __syncthreads();
        #pragma unroll
        for (int kk = 0; kk < 8; kk++) {
            float a[8], bb[8];
            *(float4*)&a[0]  = *(const float4*)&As[kk][ty*8];
            *(float4*)&a[4]  = *(const float4*)&As[kk][ty*8 + 4];
            *(float4*)&bb[0] = *(const float4*)&Bs[kk][tx*8];
            *(float4*)&bb[4] = *(const float4*)&Bs[kk][tx*8 + 4];
            #pragma unroll
            for (int i = 0; i < 8; i++)
                #pragma unroll
                for (int j = 0; j < 8; j++)
                    acc[i][j] = fmaf(a[i], bb[j], acc[i][j]);
        }
    }
    #pragma unroll
    for (int i = 0; i < 8; i++) {
        int m = row0 + ty*8 + i;
        if (m >= M) continue;
        float* cp = C + (size_t)m * Nn + col0 + tx*8;
        #pragma unroll
        for (int j = 0; j < 8; j++) {
            float v = acc[i][j];
            if (bias) v += bias[col0 + tx*8 + j];
            cp[j] = v;
        }
    }
}

// ---------------------------------------------------------------------------
// Attention: block = (row-chunk, b*h). K/V for the (b,h) pair resident in smem.
// One warp per query row: q fully in registers, logits via smem K reads,
// softmax via shuffles, PV via smem V with broadcast p from per-warp buffer.
// ---------------------------------------------------------------------------
__global__ void __launch_bounds__(256)
attn_kernel(const float* __restrict__ Q, const float* __restrict__ KV,
            const float* __restrict__ biasb, float* __restrict__ O) {
    extern __shared__ float sm[];
    float* Ks   = sm;                    // [Kc][KPAD]
    float* Vs   = Ks + Kc * KPAD;        // [Kc][KPAD]
    float* pbuf = Vs + Kc * KPAD;        // 8 warps x 272
    int bh = blockIdx.y;
    int b = bh / Hh, h = bh - b * Hh;
    int tid = threadIdx.x, w = tid >> 5, lane = tid & 31;

    const float* kvbase = KV + (size_t)b * Kc * (2*Dk) + h * dh;
    for (int i = tid; i < Kc * dh; i += 256) {
        int kk = i >> 6, dd = i & 63;
        const float* p = kvbase + (size_t)kk * (2*Dk) + dd;
        Ks[kk*KPAD + dd] = p[0];
        Vs[kk*KPAD + dd] = p[Dk];
    }
    __syncthreads();

    float* pw = pbuf + w * 272;
    for (int r = 0; r < 16; r++) {
        int n = blockIdx.x * 128 + w * 16 + r;
        if (n >= Nk) break;
        const float* qp = Q + ((size_t)b * Nk + n) * Dk + h * dh;
        float q[64];
        #pragma unroll
        for (int j = 0; j < 64; j += 4) {
            float4 v = *(const float4*)(qp + j);
            q[j] = v.x; q[j+1] = v.y; q[j+2] = v.z; q[j+3] = v.w;
        }
        const float* brow = biasb + ((size_t)h * Nk + n) * Kc;
        float l[9];
        float mx = -3e38f;
        #pragma unroll
        for (int i = 0; i < 9; i++) {
            int kk = lane + i * 32;
            float s = -3e38f;
            if (kk < Kc) {
                const float* kr = Ks + kk * KPAD;
                float s0 = 0.f;
                #pragma unroll
                for (int j = 0; j < 64; j += 4) {
                    float4 kv4 = *(const float4*)(kr + j);
                    s0 = fmaf(q[j],   kv4.x,
                         fmaf(q[j+1], kv4.y,
                         fmaf(q[j+2], kv4.z,
                         fmaf(q[j+3], kv4.w, s0))));
                }
                s = s0 * 0.125f + brow[kk];
            }
            l[i] = s;
            mx = fmaxf(mx, s);
        }
        #pragma unroll
        for (int off = 16; off; off >>= 1)
            mx = fmaxf(mx, __shfl_xor_sync(0xffffffffu, mx, off));
        float sum = 0.f;
        #pragma unroll
        for (int i = 0; i < 9; i++) {
            int kk = lane + i * 32;
            if (kk < Kc) {
                float e = __expf(l[i] - mx);
                sum += e;
                pw[kk] = e;
            }
        }
        #pragma unroll
        for (int off = 16; off; off >>= 1)
            sum += __shfl_xor_sync(0xffffffffu, sum, off);
        float inv = 1.f / sum;
        __syncwarp();

        float acc0 = 0.f, acc1 = 0.f;
        #pragma unroll 4
        for (int k4 = 0; k4 < 256; k4 += 4) {
            float4 p4 = *(const float4*)&pw[k4];
            acc0 = fmaf(p4.x, Vs[(k4+0)*KPAD + lane],      acc0);
            acc1 = fmaf(p4.x, Vs[(k4+0)*KPAD + lane + 32], acc1);
            acc0 = fmaf(p4.y, Vs[(k4+1)*KPAD + lane],      acc0);
            acc1 = fmaf(p4.y, Vs[(k4+1)*KPAD + lane + 32], acc1);
            acc0 = fmaf(p4.z, Vs[(k4+2)*KPAD + lane],      acc0);
            acc1 = fmaf(p4.z, Vs[(k4+2)*KPAD + lane + 32], acc1);
            acc0 = fmaf(p4.w, Vs[(k4+3)*KPAD + lane],      acc0);
            acc1 = fmaf(p4.w, Vs[(k4+3)*KPAD + lane + 32], acc1);
        }
        {
            float pl = pw[256];
            acc0 = fmaf(pl, Vs[256*KPAD + lane],      acc0);
            acc1 = fmaf(pl, Vs[256*KPAD + lane + 32], acc1);
        }
        float* op = O + ((size_t)b * Nk + n) * Dk + h * dh;
        op[lane]      = acc0 * inv;
        op[lane + 32] = acc1 * inv;
        __syncwarp();
    }
}

// ---------------------------------------------------------------------------
// Launch
// ---------------------------------------------------------------------------
extern "C" void kernel_launch(void* const* d_in, const int* in_sizes, int n_in,
                              void* d_out, int out_size) {
    const float* x       = (const float*)d_in[0];
    const float* W_logit = (const float*)d_in[1];
    const float* Wq      = (const float*)d_in[2];
    const float* Wkv     = (const float*)d_in[3];
    const float* Wo      = (const float*)d_in[4];
    const float* bo      = (const float*)d_in[5];
    const float* cw1     = (const float*)d_in[6];
    const float* cb1     = (const float*)d_in[7];
    const float* cw2     = (const float*)d_in[8];
    const float* cb2     = (const float*)d_in[9];
    const float* feats   = (const float*)d_in[10];
    const float* maskp   = (const float*)d_in[11];
    float* out = (float*)d_out;

    float *ctx, *Qb, *KVb, *biasb, *Ob;
    cudaGetSymbolAddress((void**)&ctx,   g_ctx);
    cudaGetSymbolAddress((void**)&Qb,    g_Q);
    cudaGetSymbolAddress((void**)&KVb,   g_KV);
    cudaGetSymbolAddress((void**)&biasb, g_bias);
    cudaGetSymbolAddress((void**)&Ob,    g_O);

    // 1) pooled context
    pool_kernel<<<dim3(Tt + 1, Bk), 256>>>(x, W_logit, ctx);
    // 2) CPB bias table [H,N,K]
    cpb_kernel<<<(NKp + 255) / 256, 256>>>(feats, maskp, cw1, cb1, cw2, cb2, biasb);
    // 3) Q = x @ Wq^T
    sgemm_tn<<<dim3(Dk/128, (MQ + 127)/128), 256>>>(x, Wq, nullptr, Qb, MQ, Dk, Dk);
    // 4) KV = ctx @ Wkv^T
    sgemm_tn<<<dim3((2*Dk)/128, (MKV + 127)/128), 256>>>(ctx, Wkv, nullptr, KVb, MKV, 2*Dk, Dk);
    // 5) attention
    const size_t ATTN_SMEM = (size_t)(2 * Kc * KPAD + 8 * 272) * sizeof(float);
    cudaFuncSetAttribute(attn_kernel, cudaFuncAttributeMaxDynamicSharedMemorySize,
                         (int)ATTN_SMEM);
    attn_kernel<<<dim3(9, Bk * Hh), 256, ATTN_SMEM>>>(Qb, KVb, biasb, Ob);
    // 6) out = O @ Wo^T + bo
    sgemm_tn<<<dim3(Dk/128, (MQ + 127)/128), 256>>>(Ob, Wo, bo, out, MQ, Dk, Dk);
}

// round 2
// speedup vs baseline: 1.1055x; 1.1055x over previous
#include <cuda_runtime.h>
#include <cstdint>

// Problem constants
#define Bk   32
#define Nk   1025
#define Dk   768
#define Hh   12
#define dh   64
#define Tt   256          // tiles
#define Kc   257          // context length (R + T)
#define NKp  (Nk*Kc)      // 263425
#define MQ   (Bk*Nk)      // 32800
#define MKV  (Bk*Kc)      // 8224
#define KPAD 68           // padded row stride for K/V smem tiles (conflict-free for LDS.128)

// Scratch (device globals — no allocation in kernel_launch)
__device__ float g_ctx [MKV*Dk];       // [B,K,D]  pooled context
__device__ float g_Q   [MQ*Dk];        // [B*N, D]
__device__ float g_KV  [MKV*2*Dk];     // [B*K, 2D]
__device__ float g_bias[(size_t)Hh*NKp]; // [H,N,K]
__device__ float g_O   [MQ*Dk];        // [B*N, D] attention output

// ---------------------------------------------------------------------------
// Pooling: build ctx[b,k,:]. t==Tt copies register token; else softmax-pool 2x2.
// ---------------------------------------------------------------------------
__global__ void pool_kernel(const float* __restrict__ x,
                            const float* __restrict__ wl,
                            float* __restrict__ ctx) {
    int t = blockIdx.x;            // 0..256 (256 == register-token copy)
    int b = blockIdx.y;
    int tid = threadIdx.x;
    const float* xb = x + (size_t)b * Nk * Dk;
    if (t == Tt) {
        float* dst = ctx + (size_t)b * Kc * Dk;
        for (int dd = tid; dd < Dk; dd += 256) dst[dd] = xb[dd];
        return;
    }
    int gy = t >> 4, gx = t & 15;
    int n0 = 1 + (gy * 2) * 32 + gx * 2;
    int rows[4] = { n0, n0 + 1, n0 + 32, n0 + 33 };

    float p[4] = {0.f, 0.f, 0.f, 0.f};
    for (int dd = tid; dd < Dk; dd += 256) {
        float wv = wl[dd];
        p[0] += xb[(size_t)rows[0]*Dk + dd] * wv;
        p[1] += xb[(size_t)rows[1]*Dk + dd] * wv;
        p[2] += xb[(size_t)rows[2]*Dk + dd] * wv;
        p[3] += xb[(size_t)rows[3]*Dk + dd] * wv;
    }
    __shared__ float wred[4][8];
    __shared__ float sw4[4];
    int lane = tid & 31, w = tid >> 5;
    #pragma unroll
    for (int i = 0; i < 4; i++) {
        float v = p[i];
        #pragma unroll
        for (int off = 16; off; off >>= 1) v += __shfl_xor_sync(0xffffffffu, v, off);
        if (lane == 0) wred[i][w] = v;
    }
    __syncthreads();
    if (tid == 0) {
        float s[4];
        #pragma unroll
        for (int i = 0; i < 4; i++) {
            float a = 0.f;
            for (int ww = 0; ww < 8; ww++) a += wred[i][ww];   // fixed order: deterministic
            s[i] = a;
        }
        float m = fmaxf(fmaxf(s[0], s[1]), fmaxf(s[2], s[3]));
        float e[4], su = 0.f;
        #pragma unroll
        for (int i = 0; i < 4; i++) { e[i] = expf(s[i] - m); su += e[i]; }
        float inv = 1.f / su;
        #pragma unroll
        for (int i = 0; i < 4; i++) sw4[i] = e[i] * inv;
    }
    __syncthreads();
    float w0 = sw4[0], w1 = sw4[1], w2 = sw4[2], w3 = sw4[3];
    float* dst = ctx + ((size_t)b * Kc + 1 + t) * Dk;
    for (int dd = tid; dd < Dk; dd += 256)
        dst[dd] = w0 * xb[(size_t)rows[0]*Dk + dd] + w1 * xb[(size_t)rows[1]*Dk + dd]
                + w2 * xb[(size_t)rows[2]*Dk + dd] + w3 * xb[(size_t)rows[3]*Dk + dd];
}

// ---------------------------------------------------------------------------
// CPB bias: bias[h,n,k] = (gelu(feats@w1^T+b1) @ w2^T + b2) * mask
// ---------------------------------------------------------------------------
__global__ void cpb_kernel(const float* __restrict__ feats, const float* __restrict__ mask,
                           const float* __restrict__ w1, const float* __restrict__ b1,
                           const float* __restrict__ w2, const float* __restrict__ b2,
                           float* __restrict__ bias) {
    __shared__ float sw1[64], sb1[32], sw2[12*32], sb2[12];
    int tid = threadIdx.x;
    if (tid < 64) sw1[tid] = w1[tid];
    if (tid >= 64 && tid < 96) sb1[tid - 64] = b1[tid - 64];
    if (tid >= 96 && tid < 108) sb2[tid - 96] = b2[tid - 96];
    for (int i = tid; i < 384; i += 256) sw2[i] = w2[i];
    __syncthreads();
    int idx = blockIdx.x * 256 + tid;
    if (idx >= NKp) return;
    float f0 = feats[2*idx], f1 = feats[2*idx + 1];
    float m = mask[idx];
    float acc[12];
    #pragma unroll
    for (int h = 0; h < 12; h++) acc[h] = sb2[h];
    #pragma unroll
    for (int j = 0; j < 32; j++) {
        float tt = f0 * sw1[2*j] + f1 * sw1[2*j + 1] + sb1[j];
        float g = 0.5f * tt * (1.0f + erff(tt * 0.7071067811865475f));  // exact gelu
        #pragma unroll
        for (int h = 0; h < 12; h++) acc[h] += sw2[h*32 + j] * g;
    }
    #pragma unroll
    for (int h = 0; h < 12; h++) bias[(size_t)h * NKp + idx] = acc[h] * m;
}

// ---------------------------------------------------------------------------
// Tensor-core GEMM (tf32 3x): C[M,Nn] = A[M,Kd] @ W[Nn,Kd]^T (+bias over Nn).
// Block 128x128, K-chunk 16. 8 warps: 4 (M) x 2 (N), warp tile 32x64.
// mma.sync.m16n8k8 tf32, each product done as hi*hi + hi*lo + lo*hi (3xTF32)
// so accuracy stays ~1e-6 while math runs on the tensor pipe.
// Requires Nn % 128 == 0, Kd % 16 == 0; M-tail guarded.
// ---------------------------------------------------------------------------
#define SPAD 136   // smem row stride (floats): bank = (8*c + r) -> conflict-free frags

__device__ __forceinline__ void split_tf32(float x, uint32_t& hi, uint32_t& lo) {
    asm("cvt.rna.tf32.f32 %0, %1;" : "=r"(hi) : "f"(x));
    float hf = __uint_as_float(hi);
    asm("cvt.rna.tf32.f32 %0, %1;" : "=r"(lo) : "f"(x - hf));
}

__device__ __forceinline__ void mma8(float* d, const uint32_t* a, const uint32_t* b) {
    asm volatile(
        "mma.sync.aligned.m16n8k8.row.col.f32.tf32.tf32.f32 "
        "{%0,%1,%2,%3}, {%4,%5,%6,%7}, {%8,%9}, {%0,%1,%2,%3};"
        : "+f"(d[0]), "+f"(d[1]), "+f"(d[2]), "+f"(d[3])
        : "r"(a[0]), "r"(a[1]), "r"(a[2]), "r"(a[3]), "r"(b[0]), "r"(b[1]));
}

__global__ void __launch_bounds__(256)
gemm_tf32(const float* __restrict__ A, const float* __restrict__ W,
          const float* __restrict__ bias, float* __restrict__ C,
          int M, int Nn, int Kd) {
    __shared__ float As[16 * SPAD];
    __shared__ float Bs[16 * SPAD];
    int tid  = threadIdx.x;
    int warp = tid >> 5, lane = tid & 31;
    int wm = warp & 3, wn = warp >> 2;
    int r = lane >> 2, c = lane & 3;
    int row0 = blockIdx.y * 128, col0 = blockIdx.x * 128;

    // global-load assignment: thread covers (row0+lm, k = lk..lk+7) via two float4
    int lm = tid & 127;
    int lk = (tid >> 7) * 8;
    const float* Ap = A + (size_t)(row0 + lm) * Kd + lk;
    const float* Wp = W + (size_t)(col0 + lm) * Kd + lk;
    bool aval = (row0 + lm) < M;

    float acc[2][8][4];
    #pragma unroll
    for (int mt = 0; mt < 2; mt++)
        #pragma unroll
        for (int nt = 0; nt < 8; nt++)
            #pragma unroll
            for (int i = 0; i < 4; i++) acc[mt][nt][i] = 0.f;

    float4 pa0 = aval ? *(const float4*)(Ap)     : make_float4(0,0,0,0);
    float4 pa1 = aval ? *(const float4*)(Ap + 4) : make_float4(0,0,0,0);
    float4 pw0 = *(const float4*)(Wp);
    float4 pw1 = *(const float4*)(Wp + 4);

    for (int kc = 0; kc < Kd; kc += 16) {
        // stage to smem (transposed: [k][m])
        As[(lk+0)*SPAD + lm] = pa0.x; As[(lk+1)*SPAD + lm] = pa0.y;
        As[(lk+2)*SPAD + lm] = pa0.z; As[(lk+3)*SPAD + lm] = pa0.w;
        As[(lk+4)*SPAD + lm] = pa1.x; As[(lk+5)*SPAD + lm] = pa1.y;
        As[(lk+6)*SPAD + lm] = pa1.z; As[(lk+7)*SPAD + lm] = pa1.w;
        Bs[(lk+0)*SPAD + lm] = pw0.x; Bs[(lk+1)*SPAD + lm] = pw0.y;
        Bs[(lk+2)*SPAD + lm] = pw0.z; Bs[(lk+3)*SPAD + lm] = pw0.w;
        Bs[(lk+4)*SPAD + lm] = pw1.x; Bs[(lk+5)*SPAD + lm] = pw1.y;
        Bs[(lk+6)*SPAD + lm] = pw1.z; Bs[(lk+7)*SPAD + lm] = pw1.w;
        __syncthreads();

        if (kc + 16 < Kd) {
            pa0 = aval ? *(const float4*)(Ap + kc + 16)     : make_float4(0,0,0,0);
            pa1 = aval ? *(const float4*)(Ap + kc + 16 + 4) : make_float4(0,0,0,0);
            pw0 = *(const float4*)(Wp + kc + 16);
            pw1 = *(const float4*)(Wp + kc + 16 + 4);
        }

        #pragma unroll
        for (int ks = 0; ks < 16; ks += 8) {
            // A fragments (2 M-tiles), hi/lo split
            uint32_t ahi[2][4], alo[2][4];
            #pragma unroll
            for (int mt = 0; mt < 2; mt++) {
                int m0 = wm * 32 + mt * 16;
                float e0 = As[(ks + c)     * SPAD + m0 + r];
                float e1 = As[(ks + c)     * SPAD + m0 + r + 8];
                float e2 = As[(ks + c + 4) * SPAD + m0 + r];
                float e3 = As[(ks + c + 4) * SPAD + m0 + r + 8];
                split_tf32(e0, ahi[mt][0], alo[mt][0]);
                split_tf32(e1, ahi[mt][1], alo[mt][1]);
                split_tf32(e2, ahi[mt][2], alo[mt][2]);
                split_tf32(e3, ahi[mt][3], alo[mt][3]);
            }
            // B fragments (8 N-tiles), hi/lo split
            uint32_t bhi[8][2], blo[8][2];
            #pragma unroll
            for (int nt = 0; nt < 8; nt++) {
                int n0 = wn * 64 + nt * 8;
                float f0 = Bs[(ks + c)     * SPAD + n0 + r];
                float f1 = Bs[(ks + c + 4) * SPAD + n0 + r];
                split_tf32(f0, bhi[nt][0], blo[nt][0]);
                split_tf32(f1, bhi[nt][1], blo[nt][1]);
            }
            #pragma unroll
            for (int mt = 0; mt < 2; mt++)
                #pragma unroll
                for (int nt = 0; nt < 8; nt++) {
                    mma8(acc[mt][nt], ahi[mt], bhi[nt]);
                    mma8(acc[mt][nt], ahi[mt], blo[nt]);
                    mma8(acc[mt][nt], alo[mt], bhi[nt]);
                }
        }
        __syncthreads();
    }

    // epilogue
    #pragma unroll
    for (int mt = 0; mt < 2; mt++) {
        int rowa = row0 + wm * 32 + mt * 16 + r;
        #pragma unroll
        for (int nt = 0; nt < 8; nt++) {
            int colb = col0 + wn * 64 + nt * 8 + 2 * c;
            float bv0 = bias ? bias[colb]     : 0.f;
            float bv1 = bias ? bias[colb + 1] : 0.f;
            if (rowa < M) {
                float2 v = make_float2(acc[mt][nt][0] + bv0, acc[mt][nt][1] + bv1);
                *(float2*)&C[(size_t)rowa * Nn + colb] = v;
            }
            if (rowa + 8 < M) {
                float2 v = make_float2(acc[mt][nt][2] + bv0, acc[mt][nt][3] + bv1);
                *(float2*)&C[(size_t)(rowa + 8) * Nn + colb] = v;
            }
        }
    }
}

// ---------------------------------------------------------------------------
// Attention: block = (row-chunk, b*h). K/V for the (b,h) pair resident in smem.
// ---------------------------------------------------------------------------
__global__ void __launch_bounds__(256)
attn_kernel(const float* __restrict__ Q, const float* __restrict__ KV,
            const float* __restrict__ biasb, float* __restrict__ O) {
    extern __shared__ float sm[];
    float* Ks   = sm;                    // [Kc][KPAD]
    float* Vs   = Ks + Kc * KPAD;        // [Kc][KPAD]
    float* pbuf = Vs + Kc * KPAD;        // 8 warps x 272
    int bh = blockIdx.y;
    int b = bh / Hh, h = bh - b * Hh;
    int tid = threadIdx.x, w = tid >> 5, lane = tid & 31;

    const float* kvbase = KV + (size_t)b * Kc * (2*Dk) + h * dh;
    for (int i = tid; i < Kc * dh; i += 256) {
        int kk = i >> 6, dd = i & 63;
        const float* p = kvbase + (size_t)kk * (2*Dk) + dd;
        Ks[kk*KPAD + dd] = p[0];
        Vs[kk*KPAD + dd] = p[Dk];
    }
    __syncthreads();

    float* pw = pbuf + w * 272;
    for (int r = 0; r < 16; r++) {
        int n = blockIdx.x * 128 + w * 16 + r;
        if (n >= Nk) break;
        const float* qp = Q + ((size_t)b * Nk + n) * Dk + h * dh;
        float q[64];
        #pragma unroll
        for (int j = 0; j < 64; j += 4) {
            float4 v = *(const float4*)(qp + j);
            q[j] = v.x; q[j+1] = v.y; q[j+2] = v.z; q[j+3] = v.w;
        }
        const float* brow = biasb + ((size_t)h * Nk + n) * Kc;
        float l[9];
        float mx = -3e38f;
        #pragma unroll
        for (int i = 0; i < 9; i++) {
            int kk = lane + i * 32;
            float s = -3e38f;
            if (kk < Kc) {
                const float* kr = Ks + kk * KPAD;
                float s0 = 0.f;
                #pragma unroll
                for (int j = 0; j < 64; j += 4) {
                    float4 kv4 = *(const float4*)(kr + j);
                    s0 = fmaf(q[j],   kv4.x,
                         fmaf(q[j+1], kv4.y,
                         fmaf(q[j+2], kv4.z,
                         fmaf(q[j+3], kv4.w, s0))));
                }
                s = s0 * 0.125f + brow[kk];
            }
            l[i] = s;
            mx = fmaxf(mx, s);
        }
        #pragma unroll
        for (int off = 16; off; off >>= 1)
            mx = fmaxf(mx, __shfl_xor_sync(0xffffffffu, mx, off));
        float sum = 0.f;
        #pragma unroll
        for (int i = 0; i < 9; i++) {
            int kk = lane + i * 32;
            if (kk < Kc) {
                float e = __expf(l[i] - mx);
                sum += e;
                pw[kk] = e;
            }
        }
        #pragma unroll
        for (int off = 16; off; off >>= 1)
            sum += __shfl_xor_sync(0xffffffffu, sum, off);
        float inv = 1.f / sum;
        __syncwarp();

        float acc0 = 0.f, acc1 = 0.f;
        #pragma unroll 4
        for (int k4 = 0; k4 < 256; k4 += 4) {
            float4 p4 = *(const float4*)&pw[k4];
            acc0 = fmaf(p4.x, Vs[(k4+0)*KPAD + lane],      acc0);
            acc1 = fmaf(p4.x, Vs[(k4+0)*KPAD + lane + 32], acc1);
            acc0 = fmaf(p4.y, Vs[(k4+1)*KPAD + lane],      acc0);
            acc1 = fmaf(p4.y, Vs[(k4+1)*KPAD + lane + 32], acc1);
            acc0 = fmaf(p4.z, Vs[(k4+2)*KPAD + lane],      acc0);
            acc1 = fmaf(p4.z, Vs[(k4+2)*KPAD + lane + 32], acc1);
            acc0 = fmaf(p4.w, Vs[(k4+3)*KPAD + lane],      acc0);
            acc1 = fmaf(p4.w, Vs[(k4+3)*KPAD + lane + 32], acc1);
        }
        {
            float pl = pw[256];
            acc0 = fmaf(pl, Vs[256*KPAD + lane],      acc0);
            acc1 = fmaf(pl, Vs[256*KPAD + lane + 32], acc1);
        }
        float* op = O + ((size_t)b * Nk + n) * Dk + h * dh;
        op[lane]      = acc0 * inv;
        op[lane + 32] = acc1 * inv;
        __syncwarp();
    }
}

// ---------------------------------------------------------------------------
// Launch
// ---------------------------------------------------------------------------
extern "C" void kernel_launch(void* const* d_in, const int* in_sizes, int n_in,
                              void* d_out, int out_size) {
    const float* x       = (const float*)d_in[0];
    const float* W_logit = (const float*)d_in[1];
    const float* Wq      = (const float*)d_in[2];
    const float* Wkv     = (const float*)d_in[3];
    const float* Wo      = (const float*)d_in[4];
    const float* bo      = (const float*)d_in[5];
    const float* cw1     = (const float*)d_in[6];
    const float* cb1     = (const float*)d_in[7];
    const float* cw2     = (const float*)d_in[8];
    const float* cb2     = (const float*)d_in[9];
    const float* feats   = (const float*)d_in[10];
    const float* maskp   = (const float*)d_in[11];
    float* out = (float*)d_out;

    float *ctx, *Qb, *KVb, *biasb, *Ob;
    cudaGetSymbolAddress((void**)&ctx,   g_ctx);
    cudaGetSymbolAddress((void**)&Qb,    g_Q);
    cudaGetSymbolAddress((void**)&KVb,   g_KV);
    cudaGetSymbolAddress((void**)&biasb, g_bias);
    cudaGetSymbolAddress((void**)&Ob,    g_O);

    // 1) pooled context
    pool_kernel<<<dim3(Tt + 1, Bk), 256>>>(x, W_logit, ctx);
    // 2) CPB bias table [H,N,K]
    cpb_kernel<<<(NKp + 255) / 256, 256>>>(feats, maskp, cw1, cb1, cw2, cb2, biasb);
    // 3) Q = x @ Wq^T   (tensor cores, tf32 3x)
    gemm_tf32<<<dim3(Dk/128, (MQ + 127)/128), 256>>>(x, Wq, nullptr, Qb, MQ, Dk, Dk);
    // 4) KV = ctx @ Wkv^T
    gemm_tf32<<<dim3((2*Dk)/128, (MKV + 127)/128), 256>>>(ctx, Wkv, nullptr, KVb, MKV, 2*Dk, Dk);
    // 5) attention
    const size_t ATTN_SMEM = (size_t)(2 * Kc * KPAD + 8 * 272) * sizeof(float);
    cudaFuncSetAttribute(attn_kernel, cudaFuncAttributeMaxDynamicSharedMemorySize,
                         (int)ATTN_SMEM);
    attn_kernel<<<dim3(9, Bk * Hh), 256, ATTN_SMEM>>>(Qb, KVb, biasb, Ob);
    // 6) out = O @ Wo^T + bo
    gemm_tf32<<<dim3(Dk/128, (MQ + 127)/128), 256>>>(Ob, Wo, bo, out, MQ, Dk, Dk);
}

// round 3
// speedup vs baseline: 2.1655x; 1.9589x over previous
#include <cuda_runtime.h>
#include <cuda_bf16.h>
#include <cstdint>

// Problem constants
#define Bk   32
#define Nk   1025
#define Dk   768
#define Hh   12
#define dh   64
#define Tt   256
#define Kc   257
#define NKp  (Nk*Kc)
#define MQ   (Bk*Nk)      // 32800
#define MKV  (Bk*Kc)      // 8224

// Scratch (device globals)
__device__ float    g_ctx [MKV*Dk];
__device__ float    g_Q   [MQ*Dk];
__device__ float    g_KV  [MKV*2*Dk];
__device__ float    g_bias[(size_t)Hh*NKp];
// packed bf16 hi/lo operands (uint32 = 2 consecutive-k bf16)
__device__ uint32_t g_xh [MQ*Dk/2],  g_xl [MQ*Dk/2];
__device__ uint32_t g_ch [MKV*Dk/2], g_cl [MKV*Dk/2];
__device__ uint32_t g_oh [MQ*Dk/2],  g_ol [MQ*Dk/2];
__device__ uint32_t g_wqh [Dk*Dk/2],   g_wql [Dk*Dk/2];
__device__ uint32_t g_wkvh[Dk*Dk],     g_wkvl[Dk*Dk];      // 1536*768/2
__device__ uint32_t g_woh [Dk*Dk/2],   g_wol [Dk*Dk/2];

// ---------------------------------------------------------------------------
// helpers: bf16 hi/lo splitting
// ---------------------------------------------------------------------------
__device__ __forceinline__ uint32_t bf2u(__nv_bfloat162 v) {
    return *reinterpret_cast<uint32_t*>(&v);
}
__device__ __forceinline__ void split2(float f0, float f1, uint32_t& hi, uint32_t& lo) {
    __nv_bfloat162 h = __floats2bfloat162_rn(f0, f1);
    float2 hf = __bfloat1622float2(h);
    __nv_bfloat162 l = __floats2bfloat162_rn(f0 - hf.x, f1 - hf.y);
    hi = bf2u(h); lo = bf2u(l);
}
__device__ __forceinline__ void split1(float f, __nv_bfloat16& h, __nv_bfloat16& l) {
    h = __float2bfloat16_rn(f);
    l = __float2bfloat16_rn(f - __bfloat162float(h));
}
__device__ __forceinline__ void mma16(float* d, const uint32_t* a, uint32_t b0, uint32_t b1) {
    asm volatile(
        "mma.sync.aligned.m16n8k16.row.col.f32.bf16.bf16.f32 "
        "{%0,%1,%2,%3}, {%4,%5,%6,%7}, {%8,%9}, {%0,%1,%2,%3};"
        : "+f"(d[0]), "+f"(d[1]), "+f"(d[2]), "+f"(d[3])
        : "r"(a[0]), "r"(a[1]), "r"(a[2]), "r"(a[3]), "r"(b0), "r"(b1));
}

// ---------------------------------------------------------------------------
// split fp32 -> packed bf16 hi/lo (8 elements per thread)
// ---------------------------------------------------------------------------
__global__ void split_kernel(const float4* __restrict__ in, uint4* __restrict__ hi,
                             uint4* __restrict__ lo, int n4) {
    int i = blockIdx.x * 256 + threadIdx.x;
    if (i >= n4) return;
    float4 a = in[2*i], b = in[2*i + 1];
    uint4 H, L;
    split2(a.x, a.y, H.x, L.x);
    split2(a.z, a.w, H.y, L.y);
    split2(b.x, b.y, H.z, L.z);
    split2(b.z, b.w, H.w, L.w);
    hi[i] = H; lo[i] = L;
}

// ---------------------------------------------------------------------------
// Pooling (unchanged)
// ---------------------------------------------------------------------------
__global__ void pool_kernel(const float* __restrict__ x,
                            const float* __restrict__ wl,
                            float* __restrict__ ctx) {
    int t = blockIdx.x;
    int b = blockIdx.y;
    int tid = threadIdx.x;
    const float* xb = x + (size_t)b * Nk * Dk;
    if (t == Tt) {
        float* dst = ctx + (size_t)b * Kc * Dk;
        for (int dd = tid; dd < Dk; dd += 256) dst[dd] = xb[dd];
        return;
    }
    int gy = t >> 4, gx = t & 15;
    int n0 = 1 + (gy * 2) * 32 + gx * 2;
    int rows[4] = { n0, n0 + 1, n0 + 32, n0 + 33 };

    float p[4] = {0.f, 0.f, 0.f, 0.f};
    for (int dd = tid; dd < Dk; dd += 256) {
        float wv = wl[dd];
        p[0] += xb[(size_t)rows[0]*Dk + dd] * wv;
        p[1] += xb[(size_t)rows[1]*Dk + dd] * wv;
        p[2] += xb[(size_t)rows[2]*Dk + dd] * wv;
        p[3] += xb[(size_t)rows[3]*Dk + dd] * wv;
    }
    __shared__ float wred[4][8];
    __shared__ float sw4[4];
    int lane = tid & 31, w = tid >> 5;
    #pragma unroll
    for (int i = 0; i < 4; i++) {
        float v = p[i];
        #pragma unroll
        for (int off = 16; off; off >>= 1) v += __shfl_xor_sync(0xffffffffu, v, off);
        if (lane == 0) wred[i][w] = v;
    }
    __syncthreads();
    if (tid == 0) {
        float s[4];
        #pragma unroll
        for (int i = 0; i < 4; i++) {
            float a = 0.f;
            for (int ww = 0; ww < 8; ww++) a += wred[i][ww];
            s[i] = a;
        }
        float m = fmaxf(fmaxf(s[0], s[1]), fmaxf(s[2], s[3]));
        float e[4], su = 0.f;
        #pragma unroll
        for (int i = 0; i < 4; i++) { e[i] = expf(s[i] - m); su += e[i]; }
        float inv = 1.f / su;
        #pragma unroll
        for (int i = 0; i < 4; i++) sw4[i] = e[i] * inv;
    }
    __syncthreads();
    float w0 = sw4[0], w1 = sw4[1], w2 = sw4[2], w3 = sw4[3];
    float* dst = ctx + ((size_t)b * Kc + 1 + t) * Dk;
    for (int dd = tid; dd < Dk; dd += 256)
        dst[dd] = w0 * xb[(size_t)rows[0]*Dk + dd] + w1 * xb[(size_t)rows[1]*Dk + dd]
                + w2 * xb[(size_t)rows[2]*Dk + dd] + w3 * xb[(size_t)rows[3]*Dk + dd];
}

// ---------------------------------------------------------------------------
// CPB bias (unchanged)
// ---------------------------------------------------------------------------
__global__ void cpb_kernel(const float* __restrict__ feats, const float* __restrict__ mask,
                           const float* __restrict__ w1, const float* __restrict__ b1,
                           const float* __restrict__ w2, const float* __restrict__ b2,
                           float* __restrict__ bias) {
    __shared__ float sw1[64], sb1[32], sw2[12*32], sb2[12];
    int tid = threadIdx.x;
    if (tid < 64) sw1[tid] = w1[tid];
    if (tid >= 64 && tid < 96) sb1[tid - 64] = b1[tid - 64];
    if (tid >= 96 && tid < 108) sb2[tid - 96] = b2[tid - 96];
    for (int i = tid; i < 384; i += 256) sw2[i] = w2[i];
    __syncthreads();
    int idx = blockIdx.x * 256 + tid;
    if (idx >= NKp) return;
    float f0 = feats[2*idx], f1 = feats[2*idx + 1];
    float m = mask[idx];
    float acc[12];
    #pragma unroll
    for (int h = 0; h < 12; h++) acc[h] = sb2[h];
    #pragma unroll
    for (int j = 0; j < 32; j++) {
        float tt = f0 * sw1[2*j] + f1 * sw1[2*j + 1] + sb1[j];
        float g = 0.5f * tt * (1.0f + erff(tt * 0.7071067811865475f));
        #pragma unroll
        for (int h = 0; h < 12; h++) acc[h] += sw2[h*32 + j] * g;
    }
    #pragma unroll
    for (int h = 0; h < 12; h++) bias[(size_t)h * NKp + idx] = acc[h] * m;
}

// ---------------------------------------------------------------------------
// bf16x2 tensor-core GEMM: C[M,Nn] = A @ W^T (+bias). Operands pre-split into
// packed bf16 hi/lo (uint32 = 2 consecutive k). 128x128 tile, k-chunk 32,
// 8 warps 4x2, warp tile 32x64, mma.m16n8k16 3-pass.
// ---------------------------------------------------------------------------
#define SP 136   // smem stride in uint32

__global__ void __launch_bounds__(256)
gemm_bf16(const uint32_t* __restrict__ Ah, const uint32_t* __restrict__ Al,
          const uint32_t* __restrict__ Wh, const uint32_t* __restrict__ Wl,
          const float* __restrict__ bias, float* __restrict__ C,
          int M, int Nn, int Kd) {
    __shared__ uint32_t Ash[16*SP], Asl[16*SP], Bsh[16*SP], Bsl[16*SP];
    int tid = threadIdx.x;
    int warp = tid >> 5, lane = tid & 31;
    int wm = warp & 3, wn = warp >> 2;
    int r = lane >> 2, c = lane & 3;
    int row0 = blockIdx.y * 128, col0 = blockIdx.x * 128;
    int KP = Kd >> 1;
    int lm = tid & 127, g = tid >> 7;   // g in {0,1}: kp groups g*4 and (g+2)*4
    int o0 = g * 4, o1 = (g + 2) * 4;

    const uint32_t* ApH = Ah + (size_t)(row0 + lm) * KP;
    const uint32_t* ApL = Al + (size_t)(row0 + lm) * KP;
    const uint32_t* WpH = Wh + (size_t)(col0 + lm) * KP;
    const uint32_t* WpL = Wl + (size_t)(col0 + lm) * KP;
    bool aval = (row0 + lm) < M;

    float acc[2][8][4];
    #pragma unroll
    for (int mt = 0; mt < 2; mt++)
        #pragma unroll
        for (int nt = 0; nt < 8; nt++)
            #pragma unroll
            for (int i = 0; i < 4; i++) acc[mt][nt][i] = 0.f;

    uint4 z4 = make_uint4(0,0,0,0);
    uint4 pah0 = aval ? *(const uint4*)(ApH + o0) : z4;
    uint4 pah1 = aval ? *(const uint4*)(ApH + o1) : z4;
    uint4 pal0 = aval ? *(const uint4*)(ApL + o0) : z4;
    uint4 pal1 = aval ? *(const uint4*)(ApL + o1) : z4;
    uint4 pwh0 = *(const uint4*)(WpH + o0);
    uint4 pwh1 = *(const uint4*)(WpH + o1);
    uint4 pwl0 = *(const uint4*)(WpL + o0);
    uint4 pwl1 = *(const uint4*)(WpL + o1);

    for (int kcp = 0; kcp < KP; kcp += 16) {
        Ash[(o0+0)*SP+lm]=pah0.x; Ash[(o0+1)*SP+lm]=pah0.y; Ash[(o0+2)*SP+lm]=pah0.z; Ash[(o0+3)*SP+lm]=pah0.w;
        Ash[(o1+0)*SP+lm]=pah1.x; Ash[(o1+1)*SP+lm]=pah1.y; Ash[(o1+2)*SP+lm]=pah1.z; Ash[(o1+3)*SP+lm]=pah1.w;
        Asl[(o0+0)*SP+lm]=pal0.x; Asl[(o0+1)*SP+lm]=pal0.y; Asl[(o0+2)*SP+lm]=pal0.z; Asl[(o0+3)*SP+lm]=pal0.w;
        Asl[(o1+0)*SP+lm]=pal1.x; Asl[(o1+1)*SP+lm]=pal1.y; Asl[(o1+2)*SP+lm]=pal1.z; Asl[(o1+3)*SP+lm]=pal1.w;
        Bsh[(o0+0)*SP+lm]=pwh0.x; Bsh[(o0+1)*SP+lm]=pwh0.y; Bsh[(o0+2)*SP+lm]=pwh0.z; Bsh[(o0+3)*SP+lm]=pwh0.w;
        Bsh[(o1+0)*SP+lm]=pwh1.x; Bsh[(o1+1)*SP+lm]=pwh1.y; Bsh[(o1+2)*SP+lm]=pwh1.z; Bsh[(o1+3)*SP+lm]=pwh1.w;
        Bsl[(o0+0)*SP+lm]=pwl0.x; Bsl[(o0+1)*SP+lm]=pwl0.y; Bsl[(o0+2)*SP+lm]=pwl0.z; Bsl[(o0+3)*SP+lm]=pwl0.w;
        Bsl[(o1+0)*SP+lm]=pwl1.x; Bsl[(o1+1)*SP+lm]=pwl1.y; Bsl[(o1+2)*SP+lm]=pwl1.z; Bsl[(o1+3)*SP+lm]=pwl1.w;
        __syncthreads();

        if (kcp + 16 < KP) {
            int nk = kcp + 16;
            pah0 = aval ? *(const uint4*)(ApH + nk + o0) : z4;
            pah1 = aval ? *(const uint4*)(ApH + nk + o1) : z4;
            pal0 = aval ? *(const uint4*)(ApL + nk + o0) : z4;
            pal1 = aval ? *(const uint4*)(ApL + nk + o1) : z4;
            pwh0 = *(const uint4*)(WpH + nk + o0);
            pwh1 = *(const uint4*)(WpH + nk + o1);
            pwl0 = *(const uint4*)(WpL + nk + o0);
            pwl1 = *(const uint4*)(WpL + nk + o1);
        }

        #pragma unroll
        for (int kk = 0; kk < 2; kk++) {
            int kps = kk * 8;
            uint32_t ah[2][4], al[2][4];
            #pragma unroll
            for (int mt = 0; mt < 2; mt++) {
                int m0 = wm * 32 + mt * 16;
                ah[mt][0] = Ash[(kps+c)*SP   + m0 + r];
                ah[mt][1] = Ash[(kps+c)*SP   + m0 + r + 8];
                ah[mt][2] = Ash[(kps+c+4)*SP + m0 + r];
                ah[mt][3] = Ash[(kps+c+4)*SP + m0 + r + 8];
                al[mt][0] = Asl[(kps+c)*SP   + m0 + r];
                al[mt][1] = Asl[(kps+c)*SP   + m0 + r + 8];
                al[mt][2] = Asl[(kps+c+4)*SP + m0 + r];
                al[mt][3] = Asl[(kps+c+4)*SP + m0 + r + 8];
            }
            uint32_t bh[8][2], bl[8][2];
            #pragma unroll
            for (int nt = 0; nt < 8; nt++) {
                int n0w = wn * 64 + nt * 8;
                bh[nt][0] = Bsh[(kps+c)*SP   + n0w + r];
                bh[nt][1] = Bsh[(kps+c+4)*SP + n0w + r];
                bl[nt][0] = Bsl[(kps+c)*SP   + n0w + r];
                bl[nt][1] = Bsl[(kps+c+4)*SP + n0w + r];
            }
            #pragma unroll
            for (int mt = 0; mt < 2; mt++)
                #pragma unroll
                for (int nt = 0; nt < 8; nt++) {
                    mma16(acc[mt][nt], ah[mt], bh[nt][0], bh[nt][1]);
                    mma16(acc[mt][nt], ah[mt], bl[nt][0], bl[nt][1]);
                    mma16(acc[mt][nt], al[mt], bh[nt][0], bh[nt][1]);
                }
        }
        __syncthreads();
    }

    #pragma unroll
    for (int mt = 0; mt < 2; mt++) {
        int rowa = row0 + wm * 32 + mt * 16 + r;
        #pragma unroll
        for (int nt = 0; nt < 8; nt++) {
            int colb = col0 + wn * 64 + nt * 8 + 2 * c;
            float bv0 = bias ? bias[colb]     : 0.f;
            float bv1 = bias ? bias[colb + 1] : 0.f;
            if (rowa < M) {
                float2 v = make_float2(acc[mt][nt][0] + bv0, acc[mt][nt][1] + bv1);
                *(float2*)&C[(size_t)rowa * Nn + colb] = v;
            }
            if (rowa + 8 < M) {
                float2 v = make_float2(acc[mt][nt][2] + bv0, acc[mt][nt][3] + bv1);
                *(float2*)&C[(size_t)(rowa + 8) * Nn + colb] = v;
            }
        }
    }
}

// ---------------------------------------------------------------------------
// Tensor-core attention. One block per (b,h); iterates 9 query tiles of 128.
// K/V/Q staged in smem as bf16 hi/lo (packed pairs). QK^T logits held entirely
// in register C-fragments; softmax in-register; P refolds into PV A-fragments
// with zero data movement. Output written directly as packed bf16 hi/lo.
// ---------------------------------------------------------------------------
#define SPQ 36    // uint32 stride for K and Q tiles (32 d-pairs + pad)
#define SPV 140   // uint32 stride for V^T tile (136 k-pairs + pad)

__global__ void __launch_bounds__(256)
attn_mma(const float* __restrict__ Q, const float* __restrict__ KV,
         const float* __restrict__ biasb,
         uint32_t* __restrict__ Oh, uint32_t* __restrict__ Ol) {
    extern __shared__ uint32_t sm4[];
    uint32_t* Kh = sm4;                  // [272][36]
    uint32_t* Kl = Kh + 272 * SPQ;
    uint32_t* Vh = Kl + 272 * SPQ;       // [64][140]
    uint32_t* Vl = Vh + 64 * SPV;
    uint32_t* Qh = Vl + 64 * SPV;        // [128][36]
    uint32_t* Ql = Qh + 128 * SPQ;
    __nv_bfloat16* Khb = (__nv_bfloat16*)Kh;
    __nv_bfloat16* Klb = (__nv_bfloat16*)Kl;
    __nv_bfloat16* Vhb = (__nv_bfloat16*)Vh;
    __nv_bfloat16* Vlb = (__nv_bfloat16*)Vl;
    __nv_bfloat16* Qhb = (__nv_bfloat16*)Qh;
    __nv_bfloat16* Qlb = (__nv_bfloat16*)Ql;

    int bh = blockIdx.x;
    int b = bh / Hh, h = bh - b * Hh;
    int tid = threadIdx.x, wr = tid >> 5, lane = tid & 31;
    int r = lane >> 2, c = lane & 3;

    // ---- fill K (kpos-major) and V^T (d-major), zero-padded to kpos=272 ----
    const float* kv = KV + (size_t)b * Kc * (2*Dk) + h * dh;
    for (int i = tid; i < 272 * 64; i += 256) {
        int kpos = i >> 6, d = i & 63;
        float fk = 0.f, fv = 0.f;
        if (kpos < Kc) {
            const float* p = kv + (size_t)kpos * (2*Dk) + d;
            fk = p[0]; fv = p[Dk];
        }
        __nv_bfloat16 hh, ll;
        split1(fk, hh, ll);
        Khb[kpos * 72 + d] = hh;  Klb[kpos * 72 + d] = ll;
        split1(fv, hh, ll);
        Vhb[d * 280 + kpos] = hh; Vlb[d * 280 + kpos] = ll;
    }

    #pragma unroll 1
    for (int bx = 0; bx < 9; bx++) {
        int n0 = bx * 128;
        __syncthreads();   // Q smem reuse barrier (also covers first-iter K/V fill)
        for (int i = tid; i < 128 * 64; i += 256) {
            int rl = i >> 6, d = i & 63;
            int n = n0 + rl; if (n > 1024) n = 1024;
            float f = Q[((size_t)b * Nk + n) * Dk + h * dh + d];
            __nv_bfloat16 hh, ll;
            split1(f, hh, ll);
            Qhb[rl * 72 + d] = hh; Qlb[rl * 72 + d] = ll;
        }
        __syncthreads();

        int m0 = wr * 16;
        // Q fragments (4 d-tiles of k16)
        uint32_t qfh[4][4], qfl[4][4];
        #pragma unroll
        for (int kt = 0; kt < 4; kt++) {
            qfh[kt][0] = Qh[(m0+r)*SPQ   + kt*8 + c];
            qfh[kt][1] = Qh[(m0+r+8)*SPQ + kt*8 + c];
            qfh[kt][2] = Qh[(m0+r)*SPQ   + kt*8 + c + 4];
            qfh[kt][3] = Qh[(m0+r+8)*SPQ + kt*8 + c + 4];
            qfl[kt][0] = Ql[(m0+r)*SPQ   + kt*8 + c];
            qfl[kt][1] = Ql[(m0+r+8)*SPQ + kt*8 + c];
            qfl[kt][2] = Ql[(m0+r)*SPQ   + kt*8 + c + 4];
            qfl[kt][3] = Ql[(m0+r+8)*SPQ + kt*8 + c + 4];
        }

        // QK^T -> 33 C-fragments in registers
        float lg[33][4];
        #pragma unroll
        for (int nt = 0; nt < 33; nt++)
            #pragma unroll
            for (int i = 0; i < 4; i++) lg[nt][i] = 0.f;

        #pragma unroll
        for (int nt = 0; nt < 33; nt++) {
            #pragma unroll
            for (int kt = 0; kt < 4; kt++) {
                int kr = (nt*8 + r) * SPQ + kt*8 + c;
                uint32_t bh0 = Kh[kr], bh1 = Kh[kr + 4];
                uint32_t bl0 = Kl[kr], bl1 = Kl[kr + 4];
                mma16(lg[nt], qfh[kt], bh0, bh1);
                mma16(lg[nt], qfh[kt], bl0, bl1);
                mma16(lg[nt], qfl[kt], bh0, bh1);
            }
        }

        // scale + bias + mask
        int nr  = n0 + m0 + r;
        int nr8 = nr + 8;
        const float* bp0 = biasb + ((size_t)h * Nk + (nr  > 1024 ? 1024 : nr )) * Kc;
        const float* bp1 = biasb + ((size_t)h * Nk + (nr8 > 1024 ? 1024 : nr8)) * Kc;
        #pragma unroll
        for (int nt = 0; nt < 33; nt++) {
            int k0 = nt*8 + 2*c, k1 = k0 + 1;
            lg[nt][0] = (k0 < Kc) ? lg[nt][0] * 0.125f + bp0[k0] : -1e30f;
            lg[nt][1] = (k1 < Kc) ? lg[nt][1] * 0.125f + bp0[k1] : -1e30f;
            lg[nt][2] = (k0 < Kc) ? lg[nt][2] * 0.125f + bp1[k0] : -1e30f;
            lg[nt][3] = (k1 < Kc) ? lg[nt][3] * 0.125f + bp1[k1] : -1e30f;
        }

        // softmax (rows r and r+8); 4 lanes per row -> xor 1,2 reductions
        float mx0 = -1e30f, mx1 = -1e30f;
        #pragma unroll
        for (int nt = 0; nt < 33; nt++) {
            mx0 = fmaxf(mx0, fmaxf(lg[nt][0], lg[nt][1]));
            mx1 = fmaxf(mx1, fmaxf(lg[nt][2], lg[nt][3]));
        }
        mx0 = fmaxf(mx0, __shfl_xor_sync(0xffffffffu, mx0, 1));
        mx0 = fmaxf(mx0, __shfl_xor_sync(0xffffffffu, mx0, 2));
        mx1 = fmaxf(mx1, __shfl_xor_sync(0xffffffffu, mx1, 1));
        mx1 = fmaxf(mx1, __shfl_xor_sync(0xffffffffu, mx1, 2));
        float s0 = 0.f, s1 = 0.f;
        #pragma unroll
        for (int nt = 0; nt < 33; nt++) {
            lg[nt][0] = __expf(lg[nt][0] - mx0); s0 += lg[nt][0];
            lg[nt][1] = __expf(lg[nt][1] - mx0); s0 += lg[nt][1];
            lg[nt][2] = __expf(lg[nt][2] - mx1); s1 += lg[nt][2];
            lg[nt][3] = __expf(lg[nt][3] - mx1); s1 += lg[nt][3];
        }
        s0 += __shfl_xor_sync(0xffffffffu, s0, 1);
        s0 += __shfl_xor_sync(0xffffffffu, s0, 2);
        s1 += __shfl_xor_sync(0xffffffffu, s1, 1);
        s1 += __shfl_xor_sync(0xffffffffu, s1, 2);
        float inv0 = 1.f / s0, inv1 = 1.f / s1;

        // PV: C-fragment pairs refold directly into A-fragments
        float oacc[8][4];
        #pragma unroll
        for (int nt = 0; nt < 8; nt++)
            #pragma unroll
            for (int i = 0; i < 4; i++) oacc[nt][i] = 0.f;

        #pragma unroll
        for (int kt2 = 0; kt2 < 17; kt2++) {
            uint32_t ph[4], pl[4];
            int e0 = 2*kt2, e1 = 2*kt2 + 1;
            split2(lg[e0][0], lg[e0][1], ph[0], pl[0]);
            split2(lg[e0][2], lg[e0][3], ph[1], pl[1]);
            if (e1 < 33) {
                split2(lg[e1][0], lg[e1][1], ph[2], pl[2]);
                split2(lg[e1][2], lg[e1][3], ph[3], pl[3]);
            } else {
                ph[2] = ph[3] = pl[2] = pl[3] = 0u;
            }
            #pragma unroll
            for (int nt = 0; nt < 8; nt++) {
                int vr = (nt*8 + r) * SPV + kt2*8 + c;
                uint32_t vh0 = Vh[vr], vh1 = Vh[vr + 4];
                uint32_t vl0 = Vl[vr], vl1 = Vl[vr + 4];
                mma16(oacc[nt], ph, vh0, vh1);
                mma16(oacc[nt], ph, vl0, vl1);
                mma16(oacc[nt], pl, vh0, vh1);
            }
        }

        // store packed bf16 hi/lo output
        bool v0 = (nr <= 1024), v1 = (nr8 <= 1024);
        size_t ro0 = ((size_t)b * Nk + nr ) * (Dk/2) + h * (dh/2);
        size_t ro1 = ((size_t)b * Nk + nr8) * (Dk/2) + h * (dh/2);
        #pragma unroll
        for (int nt = 0; nt < 8; nt++) {
            uint32_t H, L;
            if (v0) {
                split2(oacc[nt][0] * inv0, oacc[nt][1] * inv0, H, L);
                Oh[ro0 + nt*4 + c] = H; Ol[ro0 + nt*4 + c] = L;
            }
            if (v1) {
                split2(oacc[nt][2] * inv1, oacc[nt][3] * inv1, H, L);
                Oh[ro1 + nt*4 + c] = H; Ol[ro1 + nt*4 + c] = L;
            }
        }
    }
}

// ---------------------------------------------------------------------------
// Launch
// ---------------------------------------------------------------------------
extern "C" void kernel_launch(void* const* d_in, const int* in_sizes, int n_in,
                              void* d_out, int out_size) {
    const float* x       = (const float*)d_in[0];
    const float* W_logit = (const float*)d_in[1];
    const float* Wq      = (const float*)d_in[2];
    const float* Wkv     = (const float*)d_in[3];
    const float* Wo      = (const float*)d_in[4];
    const float* bo      = (const float*)d_in[5];
    const float* cw1     = (const float*)d_in[6];
    const float* cb1     = (const float*)d_in[7];
    const float* cw2     = (const float*)d_in[8];
    const float* cb2     = (const float*)d_in[9];
    const float* feats   = (const float*)d_in[10];
    const float* maskp   = (const float*)d_in[11];
    float* out = (float*)d_out;

    float *ctx, *Qb, *KVb, *biasb;
    uint32_t *xh, *xl, *ch, *cl, *oh, *ol, *wqh, *wql, *wkvh, *wkvl, *woh, *wol;
    cudaGetSymbolAddress((void**)&ctx,   g_ctx);
    cudaGetSymbolAddress((void**)&Qb,    g_Q);
    cudaGetSymbolAddress((void**)&KVb,   g_KV);
    cudaGetSymbolAddress((void**)&biasb, g_bias);
    cudaGetSymbolAddress((void**)&xh,  g_xh);  cudaGetSymbolAddress((void**)&xl,  g_xl);
    cudaGetSymbolAddress((void**)&ch,  g_ch);  cudaGetSymbolAddress((void**)&cl,  g_cl);
    cudaGetSymbolAddress((void**)&oh,  g_oh);  cudaGetSymbolAddress((void**)&ol,  g_ol);
    cudaGetSymbolAddress((void**)&wqh, g_wqh); cudaGetSymbolAddress((void**)&wql, g_wql);
    cudaGetSymbolAddress((void**)&wkvh,g_wkvh);cudaGetSymbolAddress((void**)&wkvl,g_wkvl);
    cudaGetSymbolAddress((void**)&woh, g_woh); cudaGetSymbolAddress((void**)&wol, g_wol);

    // 1) pooled context
    pool_kernel<<<dim3(Tt + 1, Bk), 256>>>(x, W_logit, ctx);
    // 2) operand splits
    int n4x = MQ * Dk / 8;
    split_kernel<<<(n4x + 255)/256, 256>>>((const float4*)x, (uint4*)xh, (uint4*)xl, n4x);
    int n4q = Dk * Dk / 8;
    split_kernel<<<(n4q + 255)/256, 256>>>((const float4*)Wq, (uint4*)wqh, (uint4*)wql, n4q);
    int n4kv = 2 * Dk * Dk / 8;
    split_kernel<<<(n4kv + 255)/256, 256>>>((const float4*)Wkv, (uint4*)wkvh, (uint4*)wkvl, n4kv);
    split_kernel<<<(n4q + 255)/256, 256>>>((const float4*)Wo, (uint4*)woh, (uint4*)wol, n4q);
    int n4c = MKV * Dk / 8;
    split_kernel<<<(n4c + 255)/256, 256>>>((const float4*)ctx, (uint4*)ch, (uint4*)cl, n4c);
    // 3) CPB bias table
    cpb_kernel<<<(NKp + 255) / 256, 256>>>(feats, maskp, cw1, cb1, cw2, cb2, biasb);
    // 4) Q = x @ Wq^T
    gemm_bf16<<<dim3(Dk/128, (MQ + 127)/128), 256>>>(xh, xl, wqh, wql, nullptr, Qb, MQ, Dk, Dk);
    // 5) KV = ctx @ Wkv^T
    gemm_bf16<<<dim3((2*Dk)/128, (MKV + 127)/128), 256>>>(ch, cl, wkvh, wkvl, nullptr, KVb, MKV, 2*Dk, Dk);
    // 6) attention (tensor cores), emits packed bf16 hi/lo output
    const size_t ATTN_SMEM = (size_t)(2*272*SPQ + 2*64*SPV + 2*128*SPQ) * sizeof(uint32_t);
    cudaFuncSetAttribute(attn_mma, cudaFuncAttributeMaxDynamicSharedMemorySize, (int)ATTN_SMEM);
    attn_mma<<<Bk * Hh, 256, ATTN_SMEM>>>(Qb, KVb, biasb, oh, ol);
    // 7) out = O @ Wo^T + bo
    gemm_bf16<<<dim3(Dk/128, (MQ + 127)/128), 256>>>(oh, ol, woh, wol, bo, out, MQ, Dk, Dk);
}

// round 5
// speedup vs baseline: 2.1743x; 1.0041x over previous
#include <cuda_runtime.h>
#include <cuda_bf16.h>
#include <cstdint>

// Problem constants
#define Bk   32
#define Nk   1025
#define Dk   768
#define Hh   12
#define dh   64
#define Tt   256
#define Kc   257
#define NKp  (Nk*Kc)
#define MQ   (Bk*Nk)      // 32800
#define MKV  (Bk*Kc)      // 8224

// Scratch (device globals)
__device__ float    g_ctx [MKV*Dk];
__device__ float    g_Q   [MQ*Dk];
__device__ float    g_KV  [MKV*2*Dk];
__device__ float    g_bias[(size_t)Hh*NKp];
// packed bf16 hi/lo operands (uint32 = 2 consecutive-k bf16)
__device__ uint32_t g_xh [MQ*Dk/2],  g_xl [MQ*Dk/2];
__device__ uint32_t g_ch [MKV*Dk/2], g_cl [MKV*Dk/2];
__device__ uint32_t g_oh [MQ*Dk/2],  g_ol [MQ*Dk/2];
__device__ uint32_t g_wqh [Dk*Dk/2],   g_wql [Dk*Dk/2];
__device__ uint32_t g_wkvh[Dk*Dk],     g_wkvl[Dk*Dk];
__device__ uint32_t g_woh [Dk*Dk/2],   g_wol [Dk*Dk/2];

// ---------------------------------------------------------------------------
// helpers: bf16 hi/lo splitting
// ---------------------------------------------------------------------------
__device__ __forceinline__ uint32_t bf2u(__nv_bfloat162 v) {
    return *reinterpret_cast<uint32_t*>(&v);
}
__device__ __forceinline__ void split2(float f0, float f1, uint32_t& hi, uint32_t& lo) {
    __nv_bfloat162 h = __floats2bfloat162_rn(f0, f1);
    float2 hf = __bfloat1622float2(h);
    __nv_bfloat162 l = __floats2bfloat162_rn(f0 - hf.x, f1 - hf.y);
    hi = bf2u(h); lo = bf2u(l);
}
__device__ __forceinline__ void split1(float f, __nv_bfloat16& h, __nv_bfloat16& l) {
    h = __float2bfloat16_rn(f);
    l = __float2bfloat16_rn(f - __bfloat162float(h));
}
__device__ __forceinline__ void mma16(float* d, const uint32_t* a, uint32_t b0, uint32_t b1) {
    asm volatile(
        "mma.sync.aligned.m16n8k16.row.col.f32.bf16.bf16.f32 "
        "{%0,%1,%2,%3}, {%4,%5,%6,%7}, {%8,%9}, {%0,%1,%2,%3};"
        : "+f"(d[0]), "+f"(d[1]), "+f"(d[2]), "+f"(d[3])
        : "r"(a[0]), "r"(a[1]), "r"(a[2]), "r"(a[3]), "r"(b0), "r"(b1));
}

// ---------------------------------------------------------------------------
// split fp32 -> packed bf16 hi/lo (8 elements per thread)
// ---------------------------------------------------------------------------
__global__ void split_kernel(const float4* __restrict__ in, uint4* __restrict__ hi,
                             uint4* __restrict__ lo, int n4) {
    int i = blockIdx.x * 256 + threadIdx.x;
    if (i >= n4) return;
    float4 a = in[2*i], b = in[2*i + 1];
    uint4 H, L;
    split2(a.x, a.y, H.x, L.x);
    split2(a.z, a.w, H.y, L.y);
    split2(b.x, b.y, H.z, L.z);
    split2(b.z, b.w, H.w, L.w);
    hi[i] = H; lo[i] = L;
}

// ---------------------------------------------------------------------------
// Pooling (unchanged)
// ---------------------------------------------------------------------------
__global__ void pool_kernel(const float* __restrict__ x,
                            const float* __restrict__ wl,
                            float* __restrict__ ctx) {
    int t = blockIdx.x;
    int b = blockIdx.y;
    int tid = threadIdx.x;
    const float* xb = x + (size_t)b * Nk * Dk;
    if (t == Tt) {
        float* dst = ctx + (size_t)b * Kc * Dk;
        for (int dd = tid; dd < Dk; dd += 256) dst[dd] = xb[dd];
        return;
    }
    int gy = t >> 4, gx = t & 15;
    int n0 = 1 + (gy * 2) * 32 + gx * 2;
    int rows[4] = { n0, n0 + 1, n0 + 32, n0 + 33 };

    float p[4] = {0.f, 0.f, 0.f, 0.f};
    for (int dd = tid; dd < Dk; dd += 256) {
        float wv = wl[dd];
        p[0] += xb[(size_t)rows[0]*Dk + dd] * wv;
        p[1] += xb[(size_t)rows[1]*Dk + dd] * wv;
        p[2] += xb[(size_t)rows[2]*Dk + dd] * wv;
        p[3] += xb[(size_t)rows[3]*Dk + dd] * wv;
    }
    __shared__ float wred[4][8];
    __shared__ float sw4[4];
    int lane = tid & 31, w = tid >> 5;
    #pragma unroll
    for (int i = 0; i < 4; i++) {
        float v = p[i];
        #pragma unroll
        for (int off = 16; off; off >>= 1) v += __shfl_xor_sync(0xffffffffu, v, off);
        if (lane == 0) wred[i][w] = v;
    }
    __syncthreads();
    if (tid == 0) {
        float s[4];
        #pragma unroll
        for (int i = 0; i < 4; i++) {
            float a = 0.f;
            for (int ww = 0; ww < 8; ww++) a += wred[i][ww];
            s[i] = a;
        }
        float m = fmaxf(fmaxf(s[0], s[1]), fmaxf(s[2], s[3]));
        float e[4], su = 0.f;
        #pragma unroll
        for (int i = 0; i < 4; i++) { e[i] = expf(s[i] - m); su += e[i]; }
        float inv = 1.f / su;
        #pragma unroll
        for (int i = 0; i < 4; i++) sw4[i] = e[i] * inv;
    }
    __syncthreads();
    float w0 = sw4[0], w1 = sw4[1], w2 = sw4[2], w3 = sw4[3];
    float* dst = ctx + ((size_t)b * Kc + 1 + t) * Dk;
    for (int dd = tid; dd < Dk; dd += 256)
        dst[dd] = w0 * xb[(size_t)rows[0]*Dk + dd] + w1 * xb[(size_t)rows[1]*Dk + dd]
                + w2 * xb[(size_t)rows[2]*Dk + dd] + w3 * xb[(size_t)rows[3]*Dk + dd];
}

// ---------------------------------------------------------------------------
// CPB bias (unchanged)
// ---------------------------------------------------------------------------
__global__ void cpb_kernel(const float* __restrict__ feats, const float* __restrict__ mask,
                           const float* __restrict__ w1, const float* __restrict__ b1,
                           const float* __restrict__ w2, const float* __restrict__ b2,
                           float* __restrict__ bias) {
    __shared__ float sw1[64], sb1[32], sw2[12*32], sb2[12];
    int tid = threadIdx.x;
    if (tid < 64) sw1[tid] = w1[tid];
    if (tid >= 64 && tid < 96) sb1[tid - 64] = b1[tid - 64];
    if (tid >= 96 && tid < 108) sb2[tid - 96] = b2[tid - 96];
    for (int i = tid; i < 384; i += 256) sw2[i] = w2[i];
    __syncthreads();
    int idx = blockIdx.x * 256 + tid;
    if (idx >= NKp) return;
    float f0 = feats[2*idx], f1 = feats[2*idx + 1];
    float m = mask[idx];
    float acc[12];
    #pragma unroll
    for (int h = 0; h < 12; h++) acc[h] = sb2[h];
    #pragma unroll
    for (int j = 0; j < 32; j++) {
        float tt = f0 * sw1[2*j] + f1 * sw1[2*j + 1] + sb1[j];
        float g = 0.5f * tt * (1.0f + erff(tt * 0.7071067811865475f));
        #pragma unroll
        for (int h = 0; h < 12; h++) acc[h] += sw2[h*32 + j] * g;
    }
    #pragma unroll
    for (int h = 0; h < 12; h++) bias[(size_t)h * NKp + idx] = acc[h] * m;
}

// ---------------------------------------------------------------------------
// bf16x2 tensor-core GEMM, pass-outer MMA ordering (dependency distance 16).
// ---------------------------------------------------------------------------
#define SP 136   // smem stride in uint32

__global__ void __launch_bounds__(256)
gemm_bf16(const uint32_t* __restrict__ Ah, const uint32_t* __restrict__ Al,
          const uint32_t* __restrict__ Wh, const uint32_t* __restrict__ Wl,
          const float* __restrict__ bias, float* __restrict__ C,
          int M, int Nn, int Kd) {
    __shared__ uint32_t Ash[16*SP], Asl[16*SP], Bsh[16*SP], Bsl[16*SP];
    int tid = threadIdx.x;
    int warp = tid >> 5, lane = tid & 31;
    int wm = warp & 3, wn = warp >> 2;
    int r = lane >> 2, c = lane & 3;
    int row0 = blockIdx.y * 128, col0 = blockIdx.x * 128;
    int KP = Kd >> 1;
    int lm = tid & 127, g = tid >> 7;
    int o0 = g * 4, o1 = (g + 2) * 4;

    const uint32_t* ApH = Ah + (size_t)(row0 + lm) * KP;
    const uint32_t* ApL = Al + (size_t)(row0 + lm) * KP;
    const uint32_t* WpH = Wh + (size_t)(col0 + lm) * KP;
    const uint32_t* WpL = Wl + (size_t)(col0 + lm) * KP;
    bool aval = (row0 + lm) < M;

    float acc[2][8][4];
    #pragma unroll
    for (int mt = 0; mt < 2; mt++)
        #pragma unroll
        for (int nt = 0; nt < 8; nt++)
            #pragma unroll
            for (int i = 0; i < 4; i++) acc[mt][nt][i] = 0.f;

    uint4 z4 = make_uint4(0,0,0,0);
    uint4 pah0 = aval ? *(const uint4*)(ApH + o0) : z4;
    uint4 pah1 = aval ? *(const uint4*)(ApH + o1) : z4;
    uint4 pal0 = aval ? *(const uint4*)(ApL + o0) : z4;
    uint4 pal1 = aval ? *(const uint4*)(ApL + o1) : z4;
    uint4 pwh0 = *(const uint4*)(WpH + o0);
    uint4 pwh1 = *(const uint4*)(WpH + o1);
    uint4 pwl0 = *(const uint4*)(WpL + o0);
    uint4 pwl1 = *(const uint4*)(WpL + o1);

    for (int kcp = 0; kcp < KP; kcp += 16) {
        Ash[(o0+0)*SP+lm]=pah0.x; Ash[(o0+1)*SP+lm]=pah0.y; Ash[(o0+2)*SP+lm]=pah0.z; Ash[(o0+3)*SP+lm]=pah0.w;
        Ash[(o1+0)*SP+lm]=pah1.x; Ash[(o1+1)*SP+lm]=pah1.y; Ash[(o1+2)*SP+lm]=pah1.z; Ash[(o1+3)*SP+lm]=pah1.w;
        Asl[(o0+0)*SP+lm]=pal0.x; Asl[(o0+1)*SP+lm]=pal0.y; Asl[(o0+2)*SP+lm]=pal0.z; Asl[(o0+3)*SP+lm]=pal0.w;
        Asl[(o1+0)*SP+lm]=pal1.x; Asl[(o1+1)*SP+lm]=pal1.y; Asl[(o1+2)*SP+lm]=pal1.z; Asl[(o1+3)*SP+lm]=pal1.w;
        Bsh[(o0+0)*SP+lm]=pwh0.x; Bsh[(o0+1)*SP+lm]=pwh0.y; Bsh[(o0+2)*SP+lm]=pwh0.z; Bsh[(o0+3)*SP+lm]=pwh0.w;
        Bsh[(o1+0)*SP+lm]=pwh1.x; Bsh[(o1+1)*SP+lm]=pwh1.y; Bsh[(o1+2)*SP+lm]=pwh1.z; Bsh[(o1+3)*SP+lm]=pwh1.w;
        Bsl[(o0+0)*SP+lm]=pwl0.x; Bsl[(o0+1)*SP+lm]=pwl0.y; Bsl[(o0+2)*SP+lm]=pwl0.z; Bsl[(o0+3)*SP+lm]=pwl0.w;
        Bsl[(o1+0)*SP+lm]=pwl1.x; Bsl[(o1+1)*SP+lm]=pwl1.y; Bsl[(o1+2)*SP+lm]=pwl1.z; Bsl[(o1+3)*SP+lm]=pwl1.w;
        __syncthreads();

        if (kcp + 16 < KP) {
            int nk = kcp + 16;
            pah0 = aval ? *(const uint4*)(ApH + nk + o0) : z4;
            pah1 = aval ? *(const uint4*)(ApH + nk + o1) : z4;
            pal0 = aval ? *(const uint4*)(ApL + nk + o0) : z4;
            pal1 = aval ? *(const uint4*)(ApL + nk + o1) : z4;
            pwh0 = *(const uint4*)(WpH + nk + o0);
            pwh1 = *(const uint4*)(WpH + nk + o1);
            pwl0 = *(const uint4*)(WpL + nk + o0);
            pwl1 = *(const uint4*)(WpL + nk + o1);
        }

        #pragma unroll
        for (int kk = 0; kk < 2; kk++) {
            int kps = kk * 8;
            uint32_t ah[2][4], al[2][4];
            #pragma unroll
            for (int mt = 0; mt < 2; mt++) {
                int m0 = wm * 32 + mt * 16;
                ah[mt][0] = Ash[(kps+c)*SP   + m0 + r];
                ah[mt][1] = Ash[(kps+c)*SP   + m0 + r + 8];
                ah[mt][2] = Ash[(kps+c+4)*SP + m0 + r];
                ah[mt][3] = Ash[(kps+c+4)*SP + m0 + r + 8];
                al[mt][0] = Asl[(kps+c)*SP   + m0 + r];
                al[mt][1] = Asl[(kps+c)*SP   + m0 + r + 8];
                al[mt][2] = Asl[(kps+c+4)*SP + m0 + r];
                al[mt][3] = Asl[(kps+c+4)*SP + m0 + r + 8];
            }
            uint32_t bh[8][2], bl[8][2];
            #pragma unroll
            for (int nt = 0; nt < 8; nt++) {
                int n0w = wn * 64 + nt * 8;
                bh[nt][0] = Bsh[(kps+c)*SP   + n0w + r];
                bh[nt][1] = Bsh[(kps+c+4)*SP + n0w + r];
                bl[nt][0] = Bsl[(kps+c)*SP   + n0w + r];
                bl[nt][1] = Bsl[(kps+c+4)*SP + n0w + r];
            }
            // pass-outer: same-accumulator MMAs are 16 issues apart
            #pragma unroll
            for (int mt = 0; mt < 2; mt++)
                #pragma unroll
                for (int nt = 0; nt < 8; nt++)
                    mma16(acc[mt][nt], ah[mt], bh[nt][0], bh[nt][1]);
            #pragma unroll
            for (int mt = 0; mt < 2; mt++)
                #pragma unroll
                for (int nt = 0; nt < 8; nt++)
                    mma16(acc[mt][nt], ah[mt], bl[nt][0], bl[nt][1]);
            #pragma unroll
            for (int mt = 0; mt < 2; mt++)
                #pragma unroll
                for (int nt = 0; nt < 8; nt++)
                    mma16(acc[mt][nt], al[mt], bh[nt][0], bh[nt][1]);
        }
        __syncthreads();
    }

    #pragma unroll
    for (int mt = 0; mt < 2; mt++) {
        int rowa = row0 + wm * 32 + mt * 16 + r;
        #pragma unroll
        for (int nt = 0; nt < 8; nt++) {
            int colb = col0 + wn * 64 + nt * 8 + 2 * c;
            float bv0 = bias ? bias[colb]     : 0.f;
            float bv1 = bias ? bias[colb + 1] : 0.f;
            if (rowa < M) {
                float2 v = make_float2(acc[mt][nt][0] + bv0, acc[mt][nt][1] + bv1);
                *(float2*)&C[(size_t)rowa * Nn + colb] = v;
            }
            if (rowa + 8 < M) {
                float2 v = make_float2(acc[mt][nt][2] + bv0, acc[mt][nt][3] + bv1);
                *(float2*)&C[(size_t)(rowa + 8) * Nn + colb] = v;
            }
        }
    }
}

// ---------------------------------------------------------------------------
// Tensor-core attention, interleaved MMA ordering.
// ---------------------------------------------------------------------------
#define SPQ 36
#define SPV 140

__global__ void __launch_bounds__(256)
attn_mma(const float* __restrict__ Q, const float* __restrict__ KV,
         const float* __restrict__ biasb,
         uint32_t* __restrict__ Oh, uint32_t* __restrict__ Ol) {
    extern __shared__ uint32_t sm4[];
    uint32_t* Kh = sm4;
    uint32_t* Kl = Kh + 272 * SPQ;
    uint32_t* Vh = Kl + 272 * SPQ;
    uint32_t* Vl = Vh + 64 * SPV;
    uint32_t* Qh = Vl + 64 * SPV;
    uint32_t* Ql = Qh + 128 * SPQ;
    __nv_bfloat16* Khb = (__nv_bfloat16*)Kh;
    __nv_bfloat16* Klb = (__nv_bfloat16*)Kl;
    __nv_bfloat16* Vhb = (__nv_bfloat16*)Vh;
    __nv_bfloat16* Vlb = (__nv_bfloat16*)Vl;
    __nv_bfloat16* Qhb = (__nv_bfloat16*)Qh;
    __nv_bfloat16* Qlb = (__nv_bfloat16*)Ql;

    int bh = blockIdx.x;
    int b = bh / Hh, h = bh - b * Hh;
    int tid = threadIdx.x, wr = tid >> 5, lane = tid & 31;
    int r = lane >> 2, c = lane & 3;

    const float* kv = KV + (size_t)b * Kc * (2*Dk) + h * dh;
    for (int i = tid; i < 272 * 64; i += 256) {
        int kpos = i >> 6, d = i & 63;
        float fk = 0.f, fv = 0.f;
        if (kpos < Kc) {
            const float* p = kv + (size_t)kpos * (2*Dk) + d;
            fk = p[0]; fv = p[Dk];
        }
        __nv_bfloat16 hh, ll;
        split1(fk, hh, ll);
        Khb[kpos * 72 + d] = hh;  Klb[kpos * 72 + d] = ll;
        split1(fv, hh, ll);
        Vhb[d * 280 + kpos] = hh; Vlb[d * 280 + kpos] = ll;
    }

    #pragma unroll 1
    for (int bx = 0; bx < 9; bx++) {
        int n0 = bx * 128;
        __syncthreads();
        for (int i = tid; i < 128 * 64; i += 256) {
            int rl = i >> 6, d = i & 63;
            int n = n0 + rl; if (n > 1024) n = 1024;
            float f = Q[((size_t)b * Nk + n) * Dk + h * dh + d];
            __nv_bfloat16 hh, ll;
            split1(f, hh, ll);
            Qhb[rl * 72 + d] = hh; Qlb[rl * 72 + d] = ll;
        }
        __syncthreads();

        int m0 = wr * 16;
        uint32_t qfh[4][4], qfl[4][4];
        #pragma unroll
        for (int kt = 0; kt < 4; kt++) {
            qfh[kt][0] = Qh[(m0+r)*SPQ   + kt*8 + c];
            qfh[kt][1] = Qh[(m0+r+8)*SPQ + kt*8 + c];
            qfh[kt][2] = Qh[(m0+r)*SPQ   + kt*8 + c + 4];
            qfh[kt][3] = Qh[(m0+r+8)*SPQ + kt*8 + c + 4];
            qfl[kt][0] = Ql[(m0+r)*SPQ   + kt*8 + c];
            qfl[kt][1] = Ql[(m0+r+8)*SPQ + kt*8 + c];
            qfl[kt][2] = Ql[(m0+r)*SPQ   + kt*8 + c + 4];
            qfl[kt][3] = Ql[(m0+r+8)*SPQ + kt*8 + c + 4];
        }

        float lg[33][4];
        #pragma unroll
        for (int nt = 0; nt < 33; nt++)
            #pragma unroll
            for (int i = 0; i < 4; i++) lg[nt][i] = 0.f;

        // QK^T: groups of 4 nt, pass-interleaved (dependency distance 4)
        #pragma unroll
        for (int gq = 0; gq < 8; gq++) {
            #pragma unroll
            for (int kt = 0; kt < 4; kt++) {
                uint32_t kfh[4][2], kfl[4][2];
                #pragma unroll
                for (int x = 0; x < 4; x++) {
                    int kr = ((gq*4 + x)*8 + r) * SPQ + kt*8 + c;
                    kfh[x][0] = Kh[kr]; kfh[x][1] = Kh[kr + 4];
                    kfl[x][0] = Kl[kr]; kfl[x][1] = Kl[kr + 4];
                }
                #pragma unroll
                for (int x = 0; x < 4; x++)
                    mma16(lg[gq*4 + x], qfh[kt], kfh[x][0], kfh[x][1]);
                #pragma unroll
                for (int x = 0; x < 4; x++)
                    mma16(lg[gq*4 + x], qfh[kt], kfl[x][0], kfl[x][1]);
                #pragma unroll
                for (int x = 0; x < 4; x++)
                    mma16(lg[gq*4 + x], qfl[kt], kfh[x][0], kfh[x][1]);
            }
        }
        // tail nt = 32
        #pragma unroll
        for (int kt = 0; kt < 4; kt++) {
            int kr = (32*8 + r) * SPQ + kt*8 + c;
            uint32_t bh0 = Kh[kr], bh1 = Kh[kr + 4];
            uint32_t bl0 = Kl[kr], bl1 = Kl[kr + 4];
            mma16(lg[32], qfh[kt], bh0, bh1);
            mma16(lg[32], qfh[kt], bl0, bl1);
            mma16(lg[32], qfl[kt], bh0, bh1);
        }

        int nr  = n0 + m0 + r;
        int nr8 = nr + 8;
        const float* bp0 = biasb + ((size_t)h * Nk + (nr  > 1024 ? 1024 : nr )) * Kc;
        const float* bp1 = biasb + ((size_t)h * Nk + (nr8 > 1024 ? 1024 : nr8)) * Kc;
        #pragma unroll
        for (int nt = 0; nt < 33; nt++) {
            int k0 = nt*8 + 2*c, k1 = k0 + 1;
            lg[nt][0] = (k0 < Kc) ? lg[nt][0] * 0.125f + bp0[k0] : -1e30f;
            lg[nt][1] = (k1 < Kc) ? lg[nt][1] * 0.125f + bp0[k1] : -1e30f;
            lg[nt][2] = (k0 < Kc) ? lg[nt][2] * 0.125f + bp1[k0] : -1e30f;
            lg[nt][3] = (k1 < Kc) ? lg[nt][3] * 0.125f + bp1[k1] : -1e30f;
        }

        float mx0 = -1e30f, mx1 = -1e30f;
        #pragma unroll
        for (int nt = 0; nt < 33; nt++) {
            mx0 = fmaxf(mx0, fmaxf(lg[nt][0], lg[nt][1]));
            mx1 = fmaxf(mx1, fmaxf(lg[nt][2], lg[nt][3]));
        }
        mx0 = fmaxf(mx0, __shfl_xor_sync(0xffffffffu, mx0, 1));
        mx0 = fmaxf(mx0, __shfl_xor_sync(0xffffffffu, mx0, 2));
        mx1 = fmaxf(mx1, __shfl_xor_sync(0xffffffffu, mx1, 1));
        mx1 = fmaxf(mx1, __shfl_xor_sync(0xffffffffu, mx1, 2));
        float s0 = 0.f, s1 = 0.f;
        #pragma unroll
        for (int nt = 0; nt < 33; nt++) {
            lg[nt][0] = __expf(lg[nt][0] - mx0); s0 += lg[nt][0];
            lg[nt][1] = __expf(lg[nt][1] - mx0); s0 += lg[nt][1];
            lg[nt][2] = __expf(lg[nt][2] - mx1); s1 += lg[nt][2];
            lg[nt][3] = __expf(lg[nt][3] - mx1); s1 += lg[nt][3];
        }
        s0 += __shfl_xor_sync(0xffffffffu, s0, 1);
        s0 += __shfl_xor_sync(0xffffffffu, s0, 2);
        s1 += __shfl_xor_sync(0xffffffffu, s1, 1);
        s1 += __shfl_xor_sync(0xffffffffu, s1, 2);
        float inv0 = 1.f / s0, inv1 = 1.f / s1;

        float oacc[8][4];
        #pragma unroll
        for (int nt = 0; nt < 8; nt++)
            #pragma unroll
            for (int i = 0; i < 4; i++) oacc[nt][i] = 0.f;

        // PV: preload V frags for all 8 nt, pass-outer (distance 8)
        #pragma unroll
        for (int kt2 = 0; kt2 < 17; kt2++) {
            uint32_t ph[4], pl[4];
            int e0 = 2*kt2, e1 = 2*kt2 + 1;
            split2(lg[e0][0], lg[e0][1], ph[0], pl[0]);
            split2(lg[e0][2], lg[e0][3], ph[1], pl[1]);
            if (e1 < 33) {
                split2(lg[e1][0], lg[e1][1], ph[2], pl[2]);
                split2(lg[e1][2], lg[e1][3], ph[3], pl[3]);
            } else {
                ph[2] = ph[3] = pl[2] = pl[3] = 0u;
            }
            uint32_t vfh[8][2], vfl[8][2];
            #pragma unroll
            for (int nt = 0; nt < 8; nt++) {
                int vr = (nt*8 + r) * SPV + kt2*8 + c;
                vfh[nt][0] = Vh[vr]; vfh[nt][1] = Vh[vr + 4];
                vfl[nt][0] = Vl[vr]; vfl[nt][1] = Vl[vr + 4];
            }
            #pragma unroll
            for (int nt = 0; nt < 8; nt++)
                mma16(oacc[nt], ph, vfh[nt][0], vfh[nt][1]);
            #pragma unroll
            for (int nt = 0; nt < 8; nt++)
                mma16(oacc[nt], ph, vfl[nt][0], vfl[nt][1]);
            #pragma unroll
            for (int nt = 0; nt < 8; nt++)
                mma16(oacc[nt], pl, vfh[nt][0], vfh[nt][1]);
        }

        bool v0 = (nr <= 1024), v1 = (nr8 <= 1024);
        size_t ro0 = ((size_t)b * Nk + nr ) * (Dk/2) + h * (dh/2);
        size_t ro1 = ((size_t)b * Nk + nr8) * (Dk/2) + h * (dh/2);
        #pragma unroll
        for (int nt = 0; nt < 8; nt++) {
            uint32_t H, L;
            if (v0) {
                split2(oacc[nt][0] * inv0, oacc[nt][1] * inv0, H, L);
                Oh[ro0 + nt*4 + c] = H; Ol[ro0 + nt*4 + c] = L;
            }
            if (v1) {
                split2(oacc[nt][2] * inv1, oacc[nt][3] * inv1, H, L);
                Oh[ro1 + nt*4 + c] = H; Ol[ro1 + nt*4 + c] = L;
            }
        }
    }
}

// ---------------------------------------------------------------------------
// Launch
// ---------------------------------------------------------------------------
extern "C" void kernel_launch(void* const* d_in, const int* in_sizes, int n_in,
                              void* d_out, int out_size) {
    const float* x       = (const float*)d_in[0];
    const float* W_logit = (const float*)d_in[1];
    const float* Wq      = (const float*)d_in[2];
    const float* Wkv     = (const float*)d_in[3];
    const float* Wo      = (const float*)d_in[4];
    const float* bo      = (const float*)d_in[5];
    const float* cw1     = (const float*)d_in[6];
    const float* cb1     = (const float*)d_in[7];
    const float* cw2     = (const float*)d_in[8];
    const float* cb2     = (const float*)d_in[9];
    const float* feats   = (const float*)d_in[10];
    const float* maskp   = (const float*)d_in[11];
    float* out = (float*)d_out;

    float *ctx, *Qb, *KVb, *biasb;
    uint32_t *xh, *xl, *ch, *cl, *oh, *ol, *wqh, *wql, *wkvh, *wkvl, *woh, *wol;
    cudaGetSymbolAddress((void**)&ctx,   g_ctx);
    cudaGetSymbolAddress((void**)&Qb,    g_Q);
    cudaGetSymbolAddress((void**)&KVb,   g_KV);
    cudaGetSymbolAddress((void**)&biasb, g_bias);
    cudaGetSymbolAddress((void**)&xh,  g_xh);  cudaGetSymbolAddress((void**)&xl,  g_xl);
    cudaGetSymbolAddress((void**)&ch,  g_ch);  cudaGetSymbolAddress((void**)&cl,  g_cl);
    cudaGetSymbolAddress((void**)&oh,  g_oh);  cudaGetSymbolAddress((void**)&ol,  g_ol);
    cudaGetSymbolAddress((void**)&wqh, g_wqh); cudaGetSymbolAddress((void**)&wql, g_wql);
    cudaGetSymbolAddress((void**)&wkvh,g_wkvh);cudaGetSymbolAddress((void**)&wkvl,g_wkvl);
    cudaGetSymbolAddress((void**)&woh, g_woh); cudaGetSymbolAddress((void**)&wol, g_wol);

    // 1) pooled context
    pool_kernel<<<dim3(Tt + 1, Bk), 256>>>(x, W_logit, ctx);
    // 2) operand splits
    int n4x = MQ * Dk / 8;
    split_kernel<<<(n4x + 255)/256, 256>>>((const float4*)x, (uint4*)xh, (uint4*)xl, n4x);
    int n4q = Dk * Dk / 8;
    split_kernel<<<(n4q + 255)/256, 256>>>((const float4*)Wq, (uint4*)wqh, (uint4*)wql, n4q);
    int n4kv = 2 * Dk * Dk / 8;
    split_kernel<<<(n4kv + 255)/256, 256>>>((const float4*)Wkv, (uint4*)wkvh, (uint4*)wkvl, n4kv);
    split_kernel<<<(n4q + 255)/256, 256>>>((const float4*)Wo, (uint4*)woh, (uint4*)wol, n4q);
    int n4c = MKV * Dk / 8;
    split_kernel<<<(n4c + 255)/256, 256>>>((const float4*)ctx, (uint4*)ch, (uint4*)cl, n4c);
    // 3) CPB bias table
    cpb_kernel<<<(NKp + 255) / 256, 256>>>(feats, maskp, cw1, cb1, cw2, cb2, biasb);
    // 4) Q = x @ Wq^T
    gemm_bf16<<<dim3(Dk/128, (MQ + 127)/128), 256>>>(xh, xl, wqh, wql, nullptr, Qb, MQ, Dk, Dk);
    // 5) KV = ctx @ Wkv^T
    gemm_bf16<<<dim3((2*Dk)/128, (MKV + 127)/128), 256>>>(ch, cl, wkvh, wkvl, nullptr, KVb, MKV, 2*Dk, Dk);
    // 6) attention
    const size_t ATTN_SMEM = (size_t)(2*272*SPQ + 2*64*SPV + 2*128*SPQ) * sizeof(uint32_t);
    cudaFuncSetAttribute(attn_mma, cudaFuncAttributeMaxDynamicSharedMemorySize, (int)ATTN_SMEM);
    attn_mma<<<Bk * Hh, 256, ATTN_SMEM>>>(Qb, KVb, biasb, oh, ol);
    // 7) out = O @ Wo^T + bo
    gemm_bf16<<<dim3(Dk/128, (MQ + 127)/128), 256>>>(oh, ol, woh, wol, bo, out, MQ, Dk, Dk);
}

// round 6
// speedup vs baseline: 3.0412x; 1.3987x over previous
#include <cuda_runtime.h>
#include <cuda_bf16.h>
#include <cstdint>

// Problem constants
#define Bk   32
#define Nk   1025
#define Dk   768
#define Hh   12
#define dh   64
#define Tt   256
#define Kc   257
#define NKp  (Nk*Kc)
#define MQ   (Bk*Nk)      // 32800
#define MKV  (Bk*Kc)      // 8224

// Scratch (device globals)
__device__ float    g_ctx [MKV*Dk];
__device__ float    g_Q   [MQ*Dk];
__device__ float    g_KV  [MKV*2*Dk];
__device__ float    g_bias[(size_t)Hh*NKp];
__device__ uint32_t g_xh [MQ*Dk/2],  g_xl [MQ*Dk/2];
__device__ uint32_t g_ch [MKV*Dk/2], g_cl [MKV*Dk/2];
__device__ uint32_t g_oh [MQ*Dk/2],  g_ol [MQ*Dk/2];
__device__ uint32_t g_wqh [Dk*Dk/2],   g_wql [Dk*Dk/2];
__device__ uint32_t g_wkvh[Dk*Dk],     g_wkvl[Dk*Dk];
__device__ uint32_t g_woh [Dk*Dk/2],   g_wol [Dk*Dk/2];

// ---------------------------------------------------------------------------
// helpers
// ---------------------------------------------------------------------------
__device__ __forceinline__ uint32_t bf2u(__nv_bfloat162 v) {
    return *reinterpret_cast<uint32_t*>(&v);
}
__device__ __forceinline__ void split2(float f0, float f1, uint32_t& hi, uint32_t& lo) {
    __nv_bfloat162 h = __floats2bfloat162_rn(f0, f1);
    float2 hf = __bfloat1622float2(h);
    __nv_bfloat162 l = __floats2bfloat162_rn(f0 - hf.x, f1 - hf.y);
    hi = bf2u(h); lo = bf2u(l);
}
__device__ __forceinline__ void split1(float f, __nv_bfloat16& h, __nv_bfloat16& l) {
    h = __float2bfloat16_rn(f);
    l = __float2bfloat16_rn(f - __bfloat162float(h));
}
__device__ __forceinline__ void mma16(float* d, const uint32_t* a, uint32_t b0, uint32_t b1) {
    asm volatile(
        "mma.sync.aligned.m16n8k16.row.col.f32.bf16.bf16.f32 "
        "{%0,%1,%2,%3}, {%4,%5,%6,%7}, {%8,%9}, {%0,%1,%2,%3};"
        : "+f"(d[0]), "+f"(d[1]), "+f"(d[2]), "+f"(d[3])
        : "r"(a[0]), "r"(a[1]), "r"(a[2]), "r"(a[3]), "r"(b0), "r"(b1));
}
__device__ __forceinline__ uint32_t s2u(const void* p) {
    uint32_t a;
    asm("{ .reg .u64 t; cvta.to.shared.u64 t, %1; cvt.u32.u64 %0, t; }" : "=r"(a) : "l"(p));
    return a;
}
#define CP16(dst, src, sz) \
    asm volatile("cp.async.cg.shared.global [%0], [%1], 16, %2;" \
                 :: "r"(dst), "l"(src), "r"(sz) : "memory")
#define CP_COMMIT() asm volatile("cp.async.commit_group;" ::: "memory")
#define CP_WAIT1()  asm volatile("cp.async.wait_group 1;" ::: "memory")
#define CP_WAIT0()  asm volatile("cp.async.wait_group 0;" ::: "memory")

// ---------------------------------------------------------------------------
// split fp32 -> packed bf16 hi/lo
// ---------------------------------------------------------------------------
__global__ void split_kernel(const float4* __restrict__ in, uint4* __restrict__ hi,
                             uint4* __restrict__ lo, int n4) {
    int i = blockIdx.x * 256 + threadIdx.x;
    if (i >= n4) return;
    float4 a = in[2*i], b = in[2*i + 1];
    uint4 H, L;
    split2(a.x, a.y, H.x, L.x);
    split2(a.z, a.w, H.y, L.y);
    split2(b.x, b.y, H.z, L.z);
    split2(b.z, b.w, H.w, L.w);
    hi[i] = H; lo[i] = L;
}

// ---------------------------------------------------------------------------
// Pooling (unchanged)
// ---------------------------------------------------------------------------
__global__ void pool_kernel(const float* __restrict__ x,
                            const float* __restrict__ wl,
                            float* __restrict__ ctx) {
    int t = blockIdx.x;
    int b = blockIdx.y;
    int tid = threadIdx.x;
    const float* xb = x + (size_t)b * Nk * Dk;
    if (t == Tt) {
        float* dst = ctx + (size_t)b * Kc * Dk;
        for (int dd = tid; dd < Dk; dd += 256) dst[dd] = xb[dd];
        return;
    }
    int gy = t >> 4, gx = t & 15;
    int n0 = 1 + (gy * 2) * 32 + gx * 2;
    int rows[4] = { n0, n0 + 1, n0 + 32, n0 + 33 };

    float p[4] = {0.f, 0.f, 0.f, 0.f};
    for (int dd = tid; dd < Dk; dd += 256) {
        float wv = wl[dd];
        p[0] += xb[(size_t)rows[0]*Dk + dd] * wv;
        p[1] += xb[(size_t)rows[1]*Dk + dd] * wv;
        p[2] += xb[(size_t)rows[2]*Dk + dd] * wv;
        p[3] += xb[(size_t)rows[3]*Dk + dd] * wv;
    }
    __shared__ float wred[4][8];
    __shared__ float sw4[4];
    int lane = tid & 31, w = tid >> 5;
    #pragma unroll
    for (int i = 0; i < 4; i++) {
        float v = p[i];
        #pragma unroll
        for (int off = 16; off; off >>= 1) v += __shfl_xor_sync(0xffffffffu, v, off);
        if (lane == 0) wred[i][w] = v;
    }
    __syncthreads();
    if (tid == 0) {
        float s[4];
        #pragma unroll
        for (int i = 0; i < 4; i++) {
            float a = 0.f;
            for (int ww = 0; ww < 8; ww++) a += wred[i][ww];
            s[i] = a;
        }
        float m = fmaxf(fmaxf(s[0], s[1]), fmaxf(s[2], s[3]));
        float e[4], su = 0.f;
        #pragma unroll
        for (int i = 0; i < 4; i++) { e[i] = expf(s[i] - m); su += e[i]; }
        float inv = 1.f / su;
        #pragma unroll
        for (int i = 0; i < 4; i++) sw4[i] = e[i] * inv;
    }
    __syncthreads();
    float w0 = sw4[0], w1 = sw4[1], w2 = sw4[2], w3 = sw4[3];
    float* dst = ctx + ((size_t)b * Kc + 1 + t) * Dk;
    for (int dd = tid; dd < Dk; dd += 256)
        dst[dd] = w0 * xb[(size_t)rows[0]*Dk + dd] + w1 * xb[(size_t)rows[1]*Dk + dd]
                + w2 * xb[(size_t)rows[2]*Dk + dd] + w3 * xb[(size_t)rows[3]*Dk + dd];
}

// ---------------------------------------------------------------------------
// CPB bias (unchanged)
// ---------------------------------------------------------------------------
__global__ void cpb_kernel(const float* __restrict__ feats, const float* __restrict__ mask,
                           const float* __restrict__ w1, const float* __restrict__ b1,
                           const float* __restrict__ w2, const float* __restrict__ b2,
                           float* __restrict__ bias) {
    __shared__ float sw1[64], sb1[32], sw2[12*32], sb2[12];
    int tid = threadIdx.x;
    if (tid < 64) sw1[tid] = w1[tid];
    if (tid >= 64 && tid < 96) sb1[tid - 64] = b1[tid - 64];
    if (tid >= 96 && tid < 108) sb2[tid - 96] = b2[tid - 96];
    for (int i = tid; i < 384; i += 256) sw2[i] = w2[i];
    __syncthreads();
    int idx = blockIdx.x * 256 + tid;
    if (idx >= NKp) return;
    float f0 = feats[2*idx], f1 = feats[2*idx + 1];
    float m = mask[idx];
    float acc[12];
    #pragma unroll
    for (int h = 0; h < 12; h++) acc[h] = sb2[h];
    #pragma unroll
    for (int j = 0; j < 32; j++) {
        float tt = f0 * sw1[2*j] + f1 * sw1[2*j + 1] + sb1[j];
        float g = 0.5f * tt * (1.0f + erff(tt * 0.7071067811865475f));
        #pragma unroll
        for (int h = 0; h < 12; h++) acc[h] += sw2[h*32 + j] * g;
    }
    #pragma unroll
    for (int h = 0; h < 12; h++) bias[(size_t)h * NKp + idx] = acc[h] * m;
}

// ---------------------------------------------------------------------------
// cp.async double-buffered bf16x2 GEMM. Block tile 128(M) x 256(N), K-chunk 32.
// 8 warps in 2(M) x 4(N) grid, warp tile 64x64. 3-pass hi/lo accumulate.
// smem stage: Ah[128][20] Al[128][20] Bh[256][20] Bl[256][20] (uint32, pad 4)
// ---------------------------------------------------------------------------
#define GST   20
#define AB_U32 (128*GST)               // 2560
#define BB_U32 (256*GST)               // 5120
#define STG_U32 (2*AB_U32 + 2*BB_U32)  // 15360
#define STG_B  (STG_U32*4)             // 61440

__global__ void __launch_bounds__(256)
gemm_cp(const uint32_t* __restrict__ Ah, const uint32_t* __restrict__ Al,
        const uint32_t* __restrict__ Wh, const uint32_t* __restrict__ Wl,
        const float* __restrict__ bias, float* __restrict__ C,
        int M, int Nn, int Kd) {
    extern __shared__ uint32_t smu[];
    uint32_t sb = s2u(smu);
    int tid = threadIdx.x, warp = tid >> 5, lane = tid & 31;
    int wm = warp & 1, wn = warp >> 1;     // 2 x 4 warp grid
    int r = lane >> 2, c = lane & 3;
    int row0 = blockIdx.y * 128, col0 = blockIdx.x * 256;
    int KPu = Kd >> 1;
    int nchk = Kd / 32;

    float acc[4][8][4];
    #pragma unroll
    for (int mt = 0; mt < 4; mt++)
        #pragma unroll
        for (int nt = 0; nt < 8; nt++)
            #pragma unroll
            for (int i = 0; i < 4; i++) acc[mt][nt][i] = 0.f;

    auto stage_load = [&](int s, int kc) {
        uint32_t stb = sb + s * STG_B;
        #pragma unroll
        for (int i = 0; i < 2; i++) {          // A: 128 rows x 4 chunks, hi+lo
            int cid = i * 256 + tid;
            int row = cid >> 2, kj = cid & 3;
            const uint32_t* sh = Ah + (size_t)(row0 + row) * KPu + kc + kj * 4;
            const uint32_t* sl = Al + (size_t)(row0 + row) * KPu + kc + kj * 4;
            uint32_t dst = stb + (row * GST + kj * 4) * 4;
            int sz = (row0 + row < M) ? 16 : 0;
            CP16(dst,              sh, sz);
            CP16(dst + AB_U32 * 4, sl, sz);
        }
        #pragma unroll
        for (int i = 0; i < 4; i++) {          // B: 256 rows x 4 chunks, hi+lo
            int cid = i * 256 + tid;
            int row = cid >> 2, kj = cid & 3;
            const uint32_t* sh = Wh + (size_t)(col0 + row) * KPu + kc + kj * 4;
            const uint32_t* sl = Wl + (size_t)(col0 + row) * KPu + kc + kj * 4;
            uint32_t dst = stb + (2 * AB_U32 + row * GST + kj * 4) * 4;
            CP16(dst,              sh, 16);
            CP16(dst + BB_U32 * 4, sl, 16);
        }
        CP_COMMIT();
    };

    stage_load(0, 0);

    for (int ch = 0; ch < nchk; ch++) {
        if (ch + 1 < nchk) { stage_load((ch + 1) & 1, (ch + 1) * 16); CP_WAIT1(); }
        else               { CP_WAIT0(); }
        __syncthreads();

        const uint32_t* ap_h = smu + (ch & 1) * STG_U32;
        const uint32_t* ap_l = ap_h + AB_U32;
        const uint32_t* bp_h = ap_h + 2 * AB_U32;
        const uint32_t* bp_l = bp_h + BB_U32;

        #pragma unroll
        for (int kk = 0; kk < 2; kk++) {
            int kb = kk * 8;
            uint32_t fah[4][4], fal[4][4];
            #pragma unroll
            for (int mt = 0; mt < 4; mt++) {
                int mrow = wm * 64 + mt * 16;
                fah[mt][0] = ap_h[(mrow + r)     * GST + kb + c];
                fah[mt][1] = ap_h[(mrow + r + 8) * GST + kb + c];
                fah[mt][2] = ap_h[(mrow + r)     * GST + kb + c + 4];
                fah[mt][3] = ap_h[(mrow + r + 8) * GST + kb + c + 4];
                fal[mt][0] = ap_l[(mrow + r)     * GST + kb + c];
                fal[mt][1] = ap_l[(mrow + r + 8) * GST + kb + c];
                fal[mt][2] = ap_l[(mrow + r)     * GST + kb + c + 4];
                fal[mt][3] = ap_l[(mrow + r + 8) * GST + kb + c + 4];
            }
            #pragma unroll
            for (int nt = 0; nt < 8; nt++) {
                int nrow = wn * 64 + nt * 8;
                uint32_t b0 = bp_h[(nrow + r) * GST + kb + c];
                uint32_t b1 = bp_h[(nrow + r) * GST + kb + c + 4];
                uint32_t l0 = bp_l[(nrow + r) * GST + kb + c];
                uint32_t l1 = bp_l[(nrow + r) * GST + kb + c + 4];
                #pragma unroll
                for (int mt = 0; mt < 4; mt++) mma16(acc[mt][nt], fah[mt], b0, b1);
                #pragma unroll
                for (int mt = 0; mt < 4; mt++) mma16(acc[mt][nt], fah[mt], l0, l1);
                #pragma unroll
                for (int mt = 0; mt < 4; mt++) mma16(acc[mt][nt], fal[mt], b0, b1);
            }
        }
        __syncthreads();
    }

    #pragma unroll
    for (int mt = 0; mt < 4; mt++) {
        int rowa = row0 + wm * 64 + mt * 16 + r;
        #pragma unroll
        for (int nt = 0; nt < 8; nt++) {
            int colb = col0 + wn * 64 + nt * 8 + 2 * c;
            float bv0 = bias ? bias[colb]     : 0.f;
            float bv1 = bias ? bias[colb + 1] : 0.f;
            if (rowa < M) {
                float2 v = make_float2(acc[mt][nt][0] + bv0, acc[mt][nt][1] + bv1);
                *(float2*)&C[(size_t)rowa * Nn + colb] = v;
            }
            if (rowa + 8 < M) {
                float2 v = make_float2(acc[mt][nt][2] + bv0, acc[mt][nt][3] + bv1);
                *(float2*)&C[(size_t)(rowa + 8) * Nn + colb] = v;
            }
        }
    }
}

// ---------------------------------------------------------------------------
// Tensor-core attention (unchanged from R5)
// ---------------------------------------------------------------------------
#define SPQ 36
#define SPV 140

__global__ void __launch_bounds__(256)
attn_mma(const float* __restrict__ Q, const float* __restrict__ KV,
         const float* __restrict__ biasb,
         uint32_t* __restrict__ Oh, uint32_t* __restrict__ Ol) {
    extern __shared__ uint32_t sm4[];
    uint32_t* Kh = sm4;
    uint32_t* Kl = Kh + 272 * SPQ;
    uint32_t* Vh = Kl + 272 * SPQ;
    uint32_t* Vl = Vh + 64 * SPV;
    uint32_t* Qh = Vl + 64 * SPV;
    uint32_t* Ql = Qh + 128 * SPQ;
    __nv_bfloat16* Khb = (__nv_bfloat16*)Kh;
    __nv_bfloat16* Klb = (__nv_bfloat16*)Kl;
    __nv_bfloat16* Vhb = (__nv_bfloat16*)Vh;
    __nv_bfloat16* Vlb = (__nv_bfloat16*)Vl;
    __nv_bfloat16* Qhb = (__nv_bfloat16*)Qh;
    __nv_bfloat16* Qlb = (__nv_bfloat16*)Ql;

    int bh = blockIdx.x;
    int b = bh / Hh, h = bh - b * Hh;
    int tid = threadIdx.x, wr = tid >> 5, lane = tid & 31;
    int r = lane >> 2, c = lane & 3;

    const float* kv = KV + (size_t)b * Kc * (2*Dk) + h * dh;
    for (int i = tid; i < 272 * 64; i += 256) {
        int kpos = i >> 6, d = i & 63;
        float fk = 0.f, fv = 0.f;
        if (kpos < Kc) {
            const float* p = kv + (size_t)kpos * (2*Dk) + d;
            fk = p[0]; fv = p[Dk];
        }
        __nv_bfloat16 hh, ll;
        split1(fk, hh, ll);
        Khb[kpos * 72 + d] = hh;  Klb[kpos * 72 + d] = ll;
        split1(fv, hh, ll);
        Vhb[d * 280 + kpos] = hh; Vlb[d * 280 + kpos] = ll;
    }

    #pragma unroll 1
    for (int bx = 0; bx < 9; bx++) {
        int n0 = bx * 128;
        __syncthreads();
        for (int i = tid; i < 128 * 64; i += 256) {
            int rl = i >> 6, d = i & 63;
            int n = n0 + rl; if (n > 1024) n = 1024;
            float f = Q[((size_t)b * Nk + n) * Dk + h * dh + d];
            __nv_bfloat16 hh, ll;
            split1(f, hh, ll);
            Qhb[rl * 72 + d] = hh; Qlb[rl * 72 + d] = ll;
        }
        __syncthreads();

        int m0 = wr * 16;
        uint32_t qfh[4][4], qfl[4][4];
        #pragma unroll
        for (int kt = 0; kt < 4; kt++) {
            qfh[kt][0] = Qh[(m0+r)*SPQ   + kt*8 + c];
            qfh[kt][1] = Qh[(m0+r+8)*SPQ + kt*8 + c];
            qfh[kt][2] = Qh[(m0+r)*SPQ   + kt*8 + c + 4];
            qfh[kt][3] = Qh[(m0+r+8)*SPQ + kt*8 + c + 4];
            qfl[kt][0] = Ql[(m0+r)*SPQ   + kt*8 + c];
            qfl[kt][1] = Ql[(m0+r+8)*SPQ + kt*8 + c];
            qfl[kt][2] = Ql[(m0+r)*SPQ   + kt*8 + c + 4];
            qfl[kt][3] = Ql[(m0+r+8)*SPQ + kt*8 + c + 4];
        }

        float lg[33][4];
        #pragma unroll
        for (int nt = 0; nt < 33; nt++)
            #pragma unroll
            for (int i = 0; i < 4; i++) lg[nt][i] = 0.f;

        #pragma unroll
        for (int gq = 0; gq < 8; gq++) {
            #pragma unroll
            for (int kt = 0; kt < 4; kt++) {
                uint32_t kfh[4][2], kfl[4][2];
                #pragma unroll
                for (int x = 0; x < 4; x++) {
                    int kr = ((gq*4 + x)*8 + r) * SPQ + kt*8 + c;
                    kfh[x][0] = Kh[kr]; kfh[x][1] = Kh[kr + 4];
                    kfl[x][0] = Kl[kr]; kfl[x][1] = Kl[kr + 4];
                }
                #pragma unroll
                for (int x = 0; x < 4; x++)
                    mma16(lg[gq*4 + x], qfh[kt], kfh[x][0], kfh[x][1]);
                #pragma unroll
                for (int x = 0; x < 4; x++)
                    mma16(lg[gq*4 + x], qfh[kt], kfl[x][0], kfl[x][1]);
                #pragma unroll
                for (int x = 0; x < 4; x++)
                    mma16(lg[gq*4 + x], qfl[kt], kfh[x][0], kfh[x][1]);
            }
        }
        #pragma unroll
        for (int kt = 0; kt < 4; kt++) {
            int kr = (32*8 + r) * SPQ + kt*8 + c;
            uint32_t bh0 = Kh[kr], bh1 = Kh[kr + 4];
            uint32_t bl0 = Kl[kr], bl1 = Kl[kr + 4];
            mma16(lg[32], qfh[kt], bh0, bh1);
            mma16(lg[32], qfh[kt], bl0, bl1);
            mma16(lg[32], qfl[kt], bh0, bh1);
        }

        int nr  = n0 + m0 + r;
        int nr8 = nr + 8;
        const float* bp0 = biasb + ((size_t)h * Nk + (nr  > 1024 ? 1024 : nr )) * Kc;
        const float* bp1 = biasb + ((size_t)h * Nk + (nr8 > 1024 ? 1024 : nr8)) * Kc;
        #pragma unroll
        for (int nt = 0; nt < 33; nt++) {
            int k0 = nt*8 + 2*c, k1 = k0 + 1;
            lg[nt][0] = (k0 < Kc) ? lg[nt][0] * 0.125f + bp0[k0] : -1e30f;
            lg[nt][1] = (k1 < Kc) ? lg[nt][1] * 0.125f + bp0[k1] : -1e30f;
            lg[nt][2] = (k0 < Kc) ? lg[nt][2] * 0.125f + bp1[k0] : -1e30f;
            lg[nt][3] = (k1 < Kc) ? lg[nt][3] * 0.125f + bp1[k1] : -1e30f;
        }

        float mx0 = -1e30f, mx1 = -1e30f;
        #pragma unroll
        for (int nt = 0; nt < 33; nt++) {
            mx0 = fmaxf(mx0, fmaxf(lg[nt][0], lg[nt][1]));
            mx1 = fmaxf(mx1, fmaxf(lg[nt][2], lg[nt][3]));
        }
        mx0 = fmaxf(mx0, __shfl_xor_sync(0xffffffffu, mx0, 1));
        mx0 = fmaxf(mx0, __shfl_xor_sync(0xffffffffu, mx0, 2));
        mx1 = fmaxf(mx1, __shfl_xor_sync(0xffffffffu, mx1, 1));
        mx1 = fmaxf(mx1, __shfl_xor_sync(0xffffffffu, mx1, 2));
        float s0 = 0.f, s1 = 0.f;
        #pragma unroll
        for (int nt = 0; nt < 33; nt++) {
            lg[nt][0] = __expf(lg[nt][0] - mx0); s0 += lg[nt][0];
            lg[nt][1] = __expf(lg[nt][1] - mx0); s0 += lg[nt][1];
            lg[nt][2] = __expf(lg[nt][2] - mx1); s1 += lg[nt][2];
            lg[nt][3] = __expf(lg[nt][3] - mx1); s1 += lg[nt][3];
        }
        s0 += __shfl_xor_sync(0xffffffffu, s0, 1);
        s0 += __shfl_xor_sync(0xffffffffu, s0, 2);
        s1 += __shfl_xor_sync(0xffffffffu, s1, 1);
        s1 += __shfl_xor_sync(0xffffffffu, s1, 2);
        float inv0 = 1.f / s0, inv1 = 1.f / s1;

        float oacc[8][4];
        #pragma unroll
        for (int nt = 0; nt < 8; nt++)
            #pragma unroll
            for (int i = 0; i < 4; i++) oacc[nt][i] = 0.f;

        #pragma unroll
        for (int kt2 = 0; kt2 < 17; kt2++) {
            uint32_t ph[4], pl[4];
            int e0 = 2*kt2, e1 = 2*kt2 + 1;
            split2(lg[e0][0], lg[e0][1], ph[0], pl[0]);
            split2(lg[e0][2], lg[e0][3], ph[1], pl[1]);
            if (e1 < 33) {
                split2(lg[e1][0], lg[e1][1], ph[2], pl[2]);
                split2(lg[e1][2], lg[e1][3], ph[3], pl[3]);
            } else {
                ph[2] = ph[3] = pl[2] = pl[3] = 0u;
            }
            uint32_t vfh[8][2], vfl[8][2];
            #pragma unroll
            for (int nt = 0; nt < 8; nt++) {
                int vr = (nt*8 + r) * SPV + kt2*8 + c;
                vfh[nt][0] = Vh[vr]; vfh[nt][1] = Vh[vr + 4];
                vfl[nt][0] = Vl[vr]; vfl[nt][1] = Vl[vr + 4];
            }
            #pragma unroll
            for (int nt = 0; nt < 8; nt++)
                mma16(oacc[nt], ph, vfh[nt][0], vfh[nt][1]);
            #pragma unroll
            for (int nt = 0; nt < 8; nt++)
                mma16(oacc[nt], ph, vfl[nt][0], vfl[nt][1]);
            #pragma unroll
            for (int nt = 0; nt < 8; nt++)
                mma16(oacc[nt], pl, vfh[nt][0], vfh[nt][1]);
        }

        bool v0 = (nr <= 1024), v1 = (nr8 <= 1024);
        size_t ro0 = ((size_t)b * Nk + nr ) * (Dk/2) + h * (dh/2);
        size_t ro1 = ((size_t)b * Nk + nr8) * (Dk/2) + h * (dh/2);
        #pragma unroll
        for (int nt = 0; nt < 8; nt++) {
            uint32_t H, L;
            if (v0) {
                split2(oacc[nt][0] * inv0, oacc[nt][1] * inv0, H, L);
                Oh[ro0 + nt*4 + c] = H; Ol[ro0 + nt*4 + c] = L;
            }
            if (v1) {
                split2(oacc[nt][2] * inv1, oacc[nt][3] * inv1, H, L);
                Oh[ro1 + nt*4 + c] = H; Ol[ro1 + nt*4 + c] = L;
            }
        }
    }
}

// ---------------------------------------------------------------------------
// Launch  (ordered so ncu's "-s 5 -c 1" captures the Q GEMM as launch #6)
// ---------------------------------------------------------------------------
extern "C" void kernel_launch(void* const* d_in, const int* in_sizes, int n_in,
                              void* d_out, int out_size) {
    const float* x       = (const float*)d_in[0];
    const float* W_logit = (const float*)d_in[1];
    const float* Wq      = (const float*)d_in[2];
    const float* Wkv     = (const float*)d_in[3];
    const float* Wo      = (const float*)d_in[4];
    const float* bo      = (const float*)d_in[5];
    const float* cw1     = (const float*)d_in[6];
    const float* cb1     = (const float*)d_in[7];
    const float* cw2     = (const float*)d_in[8];
    const float* cb2     = (const float*)d_in[9];
    const float* feats   = (const float*)d_in[10];
    const float* maskp   = (const float*)d_in[11];
    float* out = (float*)d_out;

    float *ctx, *Qb, *KVb, *biasb;
    uint32_t *xh, *xl, *ch, *cl, *oh, *ol, *wqh, *wql, *wkvh, *wkvl, *woh, *wol;
    cudaGetSymbolAddress((void**)&ctx,   g_ctx);
    cudaGetSymbolAddress((void**)&Qb,    g_Q);
    cudaGetSymbolAddress((void**)&KVb,   g_KV);
    cudaGetSymbolAddress((void**)&biasb, g_bias);
    cudaGetSymbolAddress((void**)&xh,  g_xh);  cudaGetSymbolAddress((void**)&xl,  g_xl);
    cudaGetSymbolAddress((void**)&ch,  g_ch);  cudaGetSymbolAddress((void**)&cl,  g_cl);
    cudaGetSymbolAddress((void**)&oh,  g_oh);  cudaGetSymbolAddress((void**)&ol,  g_ol);
    cudaGetSymbolAddress((void**)&wqh, g_wqh); cudaGetSymbolAddress((void**)&wql, g_wql);
    cudaGetSymbolAddress((void**)&wkvh,g_wkvh);cudaGetSymbolAddress((void**)&wkvl,g_wkvl);
    cudaGetSymbolAddress((void**)&woh, g_woh); cudaGetSymbolAddress((void**)&wol, g_wol);

    const int GEMM_SMEM = 2 * STG_B;   // 122880
    cudaFuncSetAttribute(gemm_cp, cudaFuncAttributeMaxDynamicSharedMemorySize, GEMM_SMEM);

    int n4q  = Dk * Dk / 8;
    int n4kv = 2 * Dk * Dk / 8;
    int n4x  = MQ * Dk / 8;
    int n4c  = MKV * Dk / 8;

    // 1-4: weight + x splits
    split_kernel<<<(n4q + 255)/256, 256>>>((const float4*)Wq, (uint4*)wqh, (uint4*)wql, n4q);
    split_kernel<<<(n4kv + 255)/256, 256>>>((const float4*)Wkv, (uint4*)wkvh, (uint4*)wkvl, n4kv);
    split_kernel<<<(n4q + 255)/256, 256>>>((const float4*)Wo, (uint4*)woh, (uint4*)wol, n4q);
    split_kernel<<<(n4x + 255)/256, 256>>>((const float4*)x, (uint4*)xh, (uint4*)xl, n4x);
    // 5: pooled context
    pool_kernel<<<dim3(Tt + 1, Bk), 256>>>(x, W_logit, ctx);
    // 6: Q = x @ Wq^T   (PROFILED LAUNCH)
    gemm_cp<<<dim3(Dk/256, (MQ + 127)/128), 256, GEMM_SMEM>>>(xh, xl, wqh, wql, nullptr, Qb, MQ, Dk, Dk);
    // 7: CPB bias table
    cpb_kernel<<<(NKp + 255) / 256, 256>>>(feats, maskp, cw1, cb1, cw2, cb2, biasb);
    // 8: ctx split
    split_kernel<<<(n4c + 255)/256, 256>>>((const float4*)ctx, (uint4*)ch, (uint4*)cl, n4c);
    // 9: KV = ctx @ Wkv^T
    gemm_cp<<<dim3((2*Dk)/256, (MKV + 127)/128), 256, GEMM_SMEM>>>(ch, cl, wkvh, wkvl, nullptr, KVb, MKV, 2*Dk, Dk);
    // 10: attention
    const size_t ATTN_SMEM = (size_t)(2*272*SPQ + 2*64*SPV + 2*128*SPQ) * sizeof(uint32_t);
    cudaFuncSetAttribute(attn_mma, cudaFuncAttributeMaxDynamicSharedMemorySize, (int)ATTN_SMEM);
    attn_mma<<<Bk * Hh, 256, ATTN_SMEM>>>(Qb, KVb, biasb, oh, ol);
    // 11: out = O @ Wo^T + bo
    gemm_cp<<<dim3(Dk/256, (MQ + 127)/128), 256, GEMM_SMEM>>>(oh, ol, woh, wol, bo, out, MQ, Dk, Dk);
}

// round 8
// speedup vs baseline: 5.2720x; 1.7335x over previous
#include <cuda_runtime.h>
#include <cuda_fp16.h>
#include <cstdint>

// Problem constants
#define Bk   32
#define Nk   1025
#define Dk   768
#define Hh   12
#define dh   64
#define Tt   256
#define Kc   257
#define NKp  (Nk*Kc)
#define MQ   (Bk*Nk)      // 32800
#define MKV  (Bk*Kc)      // 8224

// Scratch (device globals) — fp16 packed operands (uint32 = 2 consecutive k)
__device__ float    g_ctx [MKV*Dk];
__device__ float    g_Q   [MQ*Dk];
__device__ float    g_KV  [MKV*2*Dk];
__device__ float    g_bias[(size_t)Hh*NKp];
__device__ uint32_t g_xh [MQ*Dk/2];
__device__ uint32_t g_ch [MKV*Dk/2];
__device__ uint32_t g_oh [MQ*Dk/2];
__device__ uint32_t g_wqh [Dk*Dk/2];
__device__ uint32_t g_wkvh[Dk*Dk];
__device__ uint32_t g_woh [Dk*Dk/2];

// ---------------------------------------------------------------------------
// helpers
// ---------------------------------------------------------------------------
__device__ __forceinline__ uint32_t h2u(float f0, float f1) {
    __half2 h = __floats2half2_rn(f0, f1);
    return *reinterpret_cast<uint32_t*>(&h);
}
__device__ __forceinline__ void mma16h(float* d, const uint32_t* a, uint32_t b0, uint32_t b1) {
    asm volatile(
        "mma.sync.aligned.m16n8k16.row.col.f32.f16.f16.f32 "
        "{%0,%1,%2,%3}, {%4,%5,%6,%7}, {%8,%9}, {%0,%1,%2,%3};"
        : "+f"(d[0]), "+f"(d[1]), "+f"(d[2]), "+f"(d[3])
        : "r"(a[0]), "r"(a[1]), "r"(a[2]), "r"(a[3]), "r"(b0), "r"(b1));
}
__device__ __forceinline__ uint32_t s2u(const void* p) {
    uint32_t a;
    asm("{ .reg .u64 t; cvta.to.shared.u64 t, %1; cvt.u32.u64 %0, t; }" : "=r"(a) : "l"(p));
    return a;
}
#define CP16(dst, src, sz) \
    asm volatile("cp.async.cg.shared.global [%0], [%1], 16, %2;" \
                 :: "r"(dst), "l"(src), "r"(sz) : "memory")
#define CP_COMMIT() asm volatile("cp.async.commit_group;" ::: "memory")
#define CP_WAIT1()  asm volatile("cp.async.wait_group 1;" ::: "memory")
#define CP_WAIT0()  asm volatile("cp.async.wait_group 0;" ::: "memory")

// ---------------------------------------------------------------------------
// convert fp32 -> packed fp16 (8 elements per thread)
// ---------------------------------------------------------------------------
__global__ void cvt_kernel(const float4* __restrict__ in, uint4* __restrict__ out, int n4) {
    int i = blockIdx.x * 256 + threadIdx.x;
    if (i >= n4) return;
    float4 a = in[2*i], b = in[2*i + 1];
    uint4 H;
    H.x = h2u(a.x, a.y);
    H.y = h2u(a.z, a.w);
    H.z = h2u(b.x, b.y);
    H.w = h2u(b.z, b.w);
    out[i] = H;
}

// ---------------------------------------------------------------------------
// Pooling (unchanged)
// ---------------------------------------------------------------------------
__global__ void pool_kernel(const float* __restrict__ x,
                            const float* __restrict__ wl,
                            float* __restrict__ ctx) {
    int t = blockIdx.x;
    int b = blockIdx.y;
    int tid = threadIdx.x;
    const float* xb = x + (size_t)b * Nk * Dk;
    if (t == Tt) {
        float* dst = ctx + (size_t)b * Kc * Dk;
        for (int dd = tid; dd < Dk; dd += 256) dst[dd] = xb[dd];
        return;
    }
    int gy = t >> 4, gx = t & 15;
    int n0 = 1 + (gy * 2) * 32 + gx * 2;
    int rows[4] = { n0, n0 + 1, n0 + 32, n0 + 33 };

    float p[4] = {0.f, 0.f, 0.f, 0.f};
    for (int dd = tid; dd < Dk; dd += 256) {
        float wv = wl[dd];
        p[0] += xb[(size_t)rows[0]*Dk + dd] * wv;
        p[1] += xb[(size_t)rows[1]*Dk + dd] * wv;
        p[2] += xb[(size_t)rows[2]*Dk + dd] * wv;
        p[3] += xb[(size_t)rows[3]*Dk + dd] * wv;
    }
    __shared__ float wred[4][8];
    __shared__ float sw4[4];
    int lane = tid & 31, w = tid >> 5;
    #pragma unroll
    for (int i = 0; i < 4; i++) {
        float v = p[i];
        #pragma unroll
        for (int off = 16; off; off >>= 1) v += __shfl_xor_sync(0xffffffffu, v, off);
        if (lane == 0) wred[i][w] = v;
    }
    __syncthreads();
    if (tid == 0) {
        float s[4];
        #pragma unroll
        for (int i = 0; i < 4; i++) {
            float a = 0.f;
            for (int ww = 0; ww < 8; ww++) a += wred[i][ww];
            s[i] = a;
        }
        float m = fmaxf(fmaxf(s[0], s[1]), fmaxf(s[2], s[3]));
        float e[4], su = 0.f;
        #pragma unroll
        for (int i = 0; i < 4; i++) { e[i] = expf(s[i] - m); su += e[i]; }
        float inv = 1.f / su;
        #pragma unroll
        for (int i = 0; i < 4; i++) sw4[i] = e[i] * inv;
    }
    __syncthreads();
    float w0 = sw4[0], w1 = sw4[1], w2 = sw4[2], w3 = sw4[3];
    float* dst = ctx + ((size_t)b * Kc + 1 + t) * Dk;
    for (int dd = tid; dd < Dk; dd += 256)
        dst[dd] = w0 * xb[(size_t)rows[0]*Dk + dd] + w1 * xb[(size_t)rows[1]*Dk + dd]
                + w2 * xb[(size_t)rows[2]*Dk + dd] + w3 * xb[(size_t)rows[3]*Dk + dd];
}

// ---------------------------------------------------------------------------
// CPB bias (unchanged)
// ---------------------------------------------------------------------------
__global__ void cpb_kernel(const float* __restrict__ feats, const float* __restrict__ mask,
                           const float* __restrict__ w1, const float* __restrict__ b1,
                           const float* __restrict__ w2, const float* __restrict__ b2,
                           float* __restrict__ bias) {
    __shared__ float sw1[64], sb1[32], sw2[12*32], sb2[12];
    int tid = threadIdx.x;
    if (tid < 64) sw1[tid] = w1[tid];
    if (tid >= 64 && tid < 96) sb1[tid - 64] = b1[tid - 64];
    if (tid >= 96 && tid < 108) sb2[tid - 96] = b2[tid - 96];
    for (int i = tid; i < 384; i += 256) sw2[i] = w2[i];
    __syncthreads();
    int idx = blockIdx.x * 256 + tid;
    if (idx >= NKp) return;
    float f0 = feats[2*idx], f1 = feats[2*idx + 1];
    float m = mask[idx];
    float acc[12];
    #pragma unroll
    for (int h = 0; h < 12; h++) acc[h] = sb2[h];
    #pragma unroll
    for (int j = 0; j < 32; j++) {
        float tt = f0 * sw1[2*j] + f1 * sw1[2*j + 1] + sb1[j];
        float g = 0.5f * tt * (1.0f + erff(tt * 0.7071067811865475f));
        #pragma unroll
        for (int h = 0; h < 12; h++) acc[h] += sw2[h*32 + j] * g;
    }
    #pragma unroll
    for (int h = 0; h < 12; h++) bias[(size_t)h * NKp + idx] = acc[h] * m;
}

// ---------------------------------------------------------------------------
// cp.async double-buffered fp16 GEMM. Block 128(M) x 256(N), K-chunk 32.
// 8 warps 2x4, warp tile 64x64, single-pass fp16 MMA, fp32 accumulate.
// smem stage: A[128][20] B[256][20] (uint32, pad 4)
// ---------------------------------------------------------------------------
#define GST   20
#define AB_U32 (128*GST)               // 2560
#define BB_U32 (256*GST)               // 5120
#define STG_U32 (AB_U32 + BB_U32)      // 7680
#define STG_B  (STG_U32*4)             // 30720

__global__ void __launch_bounds__(256)
gemm_cp(const uint32_t* __restrict__ Ah, const uint32_t* __restrict__ Wh,
        const float* __restrict__ bias, float* __restrict__ C,
        int M, int Nn, int Kd) {
    extern __shared__ uint32_t smu[];
    uint32_t sb = s2u(smu);
    int tid = threadIdx.x, warp = tid >> 5, lane = tid & 31;
    int wm = warp & 1, wn = warp >> 1;
    int r = lane >> 2, c = lane & 3;
    int row0 = blockIdx.y * 128, col0 = blockIdx.x * 256;
    int KPu = Kd >> 1;
    int nchk = Kd / 32;

    float acc[4][8][4];
    #pragma unroll
    for (int mt = 0; mt < 4; mt++)
        #pragma unroll
        for (int nt = 0; nt < 8; nt++)
            #pragma unroll
            for (int i = 0; i < 4; i++) acc[mt][nt][i] = 0.f;

    auto stage_load = [&](int s, int kc) {
        uint32_t stb = sb + s * STG_B;
        #pragma unroll
        for (int i = 0; i < 2; i++) {          // A: 128 rows x 4 chunks of 16B
            int cid = i * 256 + tid;
            int row = cid >> 2, kj = cid & 3;
            const uint32_t* sh = Ah + (size_t)(row0 + row) * KPu + kc + kj * 4;
            uint32_t dst = stb + (row * GST + kj * 4) * 4;
            int sz = (row0 + row < M) ? 16 : 0;
            CP16(dst, sh, sz);
        }
        #pragma unroll
        for (int i = 0; i < 4; i++) {          // B: 256 rows x 4 chunks
            int cid = i * 256 + tid;
            int row = cid >> 2, kj = cid & 3;
            const uint32_t* sh = Wh + (size_t)(col0 + row) * KPu + kc + kj * 4;
            uint32_t dst = stb + (AB_U32 + row * GST + kj * 4) * 4;
            CP16(dst, sh, 16);
        }
        CP_COMMIT();
    };

    stage_load(0, 0);

    for (int ch = 0; ch < nchk; ch++) {
        if (ch + 1 < nchk) { stage_load((ch + 1) & 1, (ch + 1) * 16); CP_WAIT1(); }
        else               { CP_WAIT0(); }
        __syncthreads();

        const uint32_t* ap = smu + (ch & 1) * STG_U32;
        const uint32_t* bp = ap + AB_U32;

        #pragma unroll
        for (int kk = 0; kk < 2; kk++) {
            int kb = kk * 8;
            uint32_t fah[4][4];
            #pragma unroll
            for (int mt = 0; mt < 4; mt++) {
                int mrow = wm * 64 + mt * 16;
                fah[mt][0] = ap[(mrow + r)     * GST + kb + c];
                fah[mt][1] = ap[(mrow + r + 8) * GST + kb + c];
                fah[mt][2] = ap[(mrow + r)     * GST + kb + c + 4];
                fah[mt][3] = ap[(mrow + r + 8) * GST + kb + c + 4];
            }
            #pragma unroll
            for (int nt = 0; nt < 8; nt++) {
                int nrow = wn * 64 + nt * 8;
                uint32_t b0 = bp[(nrow + r) * GST + kb + c];
                uint32_t b1 = bp[(nrow + r) * GST + kb + c + 4];
                #pragma unroll
                for (int mt = 0; mt < 4; mt++) mma16h(acc[mt][nt], fah[mt], b0, b1);
            }
        }
        __syncthreads();
    }

    #pragma unroll
    for (int mt = 0; mt < 4; mt++) {
        int rowa = row0 + wm * 64 + mt * 16 + r;
        #pragma unroll
        for (int nt = 0; nt < 8; nt++) {
            int colb = col0 + wn * 64 + nt * 8 + 2 * c;
            float bv0 = bias ? bias[colb]     : 0.f;
            float bv1 = bias ? bias[colb + 1] : 0.f;
            if (rowa < M) {
                float2 v = make_float2(acc[mt][nt][0] + bv0, acc[mt][nt][1] + bv1);
                *(float2*)&C[(size_t)rowa * Nn + colb] = v;
            }
            if (rowa + 8 < M) {
                float2 v = make_float2(acc[mt][nt][2] + bv0, acc[mt][nt][3] + bv1);
                *(float2*)&C[(size_t)(rowa + 8) * Nn + colb] = v;
            }
        }
    }
}

// ---------------------------------------------------------------------------
// fp16 tensor-core attention. One block per (b,h); 9 query tiles of 128.
// K (kpos-major) / V^T (d-major) / Q staged in smem as packed fp16.
// Logits in register C-frags; softmax in-register; P folds to A-frags.
// Emits packed fp16 output for the final projection.
// ---------------------------------------------------------------------------
#define SPQ 36
#define SPV 140

__global__ void __launch_bounds__(256)
attn_mma(const float* __restrict__ Q, const float* __restrict__ KV,
         const float* __restrict__ biasb, uint32_t* __restrict__ Oh) {
    extern __shared__ uint32_t sm4[];
    uint32_t* Kh = sm4;                  // [272][36]
    uint32_t* Vh = Kh + 272 * SPQ;       // [64][140]
    uint32_t* Qh = Vh + 64 * SPV;        // [128][36]
    __half* Khb = (__half*)Kh;
    __half* Vhb = (__half*)Vh;
    __half* Qhb = (__half*)Qh;

    int bh = blockIdx.x;
    int b = bh / Hh, h = bh - b * Hh;
    int tid = threadIdx.x, wr = tid >> 5, lane = tid & 31;
    int r = lane >> 2, c = lane & 3;

    const float* kv = KV + (size_t)b * Kc * (2*Dk) + h * dh;
    for (int i = tid; i < 272 * 64; i += 256) {
        int kpos = i >> 6, d = i & 63;
        float fk = 0.f, fv = 0.f;
        if (kpos < Kc) {
            const float* p = kv + (size_t)kpos * (2*Dk) + d;
            fk = p[0]; fv = p[Dk];
        }
        Khb[kpos * 72 + d]  = __float2half_rn(fk);
        Vhb[d * 280 + kpos] = __float2half_rn(fv);
    }

    #pragma unroll 1
    for (int bx = 0; bx < 9; bx++) {
        int n0 = bx * 128;
        __syncthreads();
        for (int i = tid; i < 128 * 64; i += 256) {
            int rl = i >> 6, d = i & 63;
            int n = n0 + rl; if (n > 1024) n = 1024;
            float f = Q[((size_t)b * Nk + n) * Dk + h * dh + d];
            Qhb[rl * 72 + d] = __float2half_rn(f);
        }
        __syncthreads();

        int m0 = wr * 16;
        uint32_t qfh[4][4];
        #pragma unroll
        for (int kt = 0; kt < 4; kt++) {
            qfh[kt][0] = Qh[(m0+r)*SPQ   + kt*8 + c];
            qfh[kt][1] = Qh[(m0+r+8)*SPQ + kt*8 + c];
            qfh[kt][2] = Qh[(m0+r)*SPQ   + kt*8 + c + 4];
            qfh[kt][3] = Qh[(m0+r+8)*SPQ + kt*8 + c + 4];
        }

        float lg[33][4];
        #pragma unroll
        for (int nt = 0; nt < 33; nt++)
            #pragma unroll
            for (int i = 0; i < 4; i++) lg[nt][i] = 0.f;

        // QK^T: groups of 4 nt
        #pragma unroll
        for (int gq = 0; gq < 8; gq++) {
            #pragma unroll
            for (int kt = 0; kt < 4; kt++) {
                uint32_t kfh[4][2];
                #pragma unroll
                for (int x = 0; x < 4; x++) {
                    int kr = ((gq*4 + x)*8 + r) * SPQ + kt*8 + c;
                    kfh[x][0] = Kh[kr]; kfh[x][1] = Kh[kr + 4];
                }
                #pragma unroll
                for (int x = 0; x < 4; x++)
                    mma16h(lg[gq*4 + x], qfh[kt], kfh[x][0], kfh[x][1]);
            }
        }
        #pragma unroll
        for (int kt = 0; kt < 4; kt++) {
            int kr = (32*8 + r) * SPQ + kt*8 + c;
            mma16h(lg[32], qfh[kt], Kh[kr], Kh[kr + 4]);
        }

        int nr  = n0 + m0 + r;
        int nr8 = nr + 8;
        const float* bp0 = biasb + ((size_t)h * Nk + (nr  > 1024 ? 1024 : nr )) * Kc;
        const float* bp1 = biasb + ((size_t)h * Nk + (nr8 > 1024 ? 1024 : nr8)) * Kc;
        #pragma unroll
        for (int nt = 0; nt < 33; nt++) {
            int k0 = nt*8 + 2*c, k1 = k0 + 1;
            lg[nt][0] = (k0 < Kc) ? lg[nt][0] * 0.125f + bp0[k0] : -1e30f;
            lg[nt][1] = (k1 < Kc) ? lg[nt][1] * 0.125f + bp0[k1] : -1e30f;
            lg[nt][2] = (k0 < Kc) ? lg[nt][2] * 0.125f + bp1[k0] : -1e30f;
            lg[nt][3] = (k1 < Kc) ? lg[nt][3] * 0.125f + bp1[k1] : -1e30f;
        }

        float mx0 = -1e30f, mx1 = -1e30f;
        #pragma unroll
        for (int nt = 0; nt < 33; nt++) {
            mx0 = fmaxf(mx0, fmaxf(lg[nt][0], lg[nt][1]));
            mx1 = fmaxf(mx1, fmaxf(lg[nt][2], lg[nt][3]));
        }
        mx0 = fmaxf(mx0, __shfl_xor_sync(0xffffffffu, mx0, 1));
        mx0 = fmaxf(mx0, __shfl_xor_sync(0xffffffffu, mx0, 2));
        mx1 = fmaxf(mx1, __shfl_xor_sync(0xffffffffu, mx1, 1));
        mx1 = fmaxf(mx1, __shfl_xor_sync(0xffffffffu, mx1, 2));
        float s0 = 0.f, s1 = 0.f;
        #pragma unroll
        for (int nt = 0; nt < 33; nt++) {
            lg[nt][0] = __expf(lg[nt][0] - mx0); s0 += lg[nt][0];
            lg[nt][1] = __expf(lg[nt][1] - mx0); s0 += lg[nt][1];
            lg[nt][2] = __expf(lg[nt][2] - mx1); s1 += lg[nt][2];
            lg[nt][3] = __expf(lg[nt][3] - mx1); s1 += lg[nt][3];
        }
        s0 += __shfl_xor_sync(0xffffffffu, s0, 1);
        s0 += __shfl_xor_sync(0xffffffffu, s0, 2);
        s1 += __shfl_xor_sync(0xffffffffu, s1, 1);
        s1 += __shfl_xor_sync(0xffffffffu, s1, 2);
        float inv0 = 1.f / s0, inv1 = 1.f / s1;

        float oacc[8][4];
        #pragma unroll
        for (int nt = 0; nt < 8; nt++)
            #pragma unroll
            for (int i = 0; i < 4; i++) oacc[nt][i] = 0.f;

        // PV: C-frag pairs fold into fp16 A-frags, single pass
        #pragma unroll
        for (int kt2 = 0; kt2 < 17; kt2++) {
            uint32_t ph[4];
            int e0 = 2*kt2, e1 = 2*kt2 + 1;
            ph[0] = h2u(lg[e0][0], lg[e0][1]);
            ph[1] = h2u(lg[e0][2], lg[e0][3]);
            if (e1 < 33) {
                ph[2] = h2u(lg[e1][0], lg[e1][1]);
                ph[3] = h2u(lg[e1][2], lg[e1][3]);
            } else {
                ph[2] = ph[3] = 0u;
            }
            uint32_t vfh[8][2];
            #pragma unroll
            for (int nt = 0; nt < 8; nt++) {
                int vr = (nt*8 + r) * SPV + kt2*8 + c;
                vfh[nt][0] = Vh[vr]; vfh[nt][1] = Vh[vr + 4];
            }
            #pragma unroll
            for (int nt = 0; nt < 8; nt++)
                mma16h(oacc[nt], ph, vfh[nt][0], vfh[nt][1]);
        }

        bool v0 = (nr <= 1024), v1 = (nr8 <= 1024);
        size_t ro0 = ((size_t)b * Nk + nr ) * (Dk/2) + h * (dh/2);
        size_t ro1 = ((size_t)b * Nk + nr8) * (Dk/2) + h * (dh/2);
        #pragma unroll
        for (int nt = 0; nt < 8; nt++) {
            if (v0) Oh[ro0 + nt*4 + c] = h2u(oacc[nt][0] * inv0, oacc[nt][1] * inv0);
            if (v1) Oh[ro1 + nt*4 + c] = h2u(oacc[nt][2] * inv1, oacc[nt][3] * inv1);
        }
    }
}

// ---------------------------------------------------------------------------
// Launch
// ---------------------------------------------------------------------------
extern "C" void kernel_launch(void* const* d_in, const int* in_sizes, int n_in,
                              void* d_out, int out_size) {
    const float* x       = (const float*)d_in[0];
    const float* W_logit = (const float*)d_in[1];
    const float* Wq      = (const float*)d_in[2];
    const float* Wkv     = (const float*)d_in[3];
    const float* Wo      = (const float*)d_in[4];
    const float* bo      = (const float*)d_in[5];
    const float* cw1     = (const float*)d_in[6];
    const float* cb1     = (const float*)d_in[7];
    const float* cw2     = (const float*)d_in[8];
    const float* cb2     = (const float*)d_in[9];
    const float* feats   = (const float*)d_in[10];
    const float* maskp   = (const float*)d_in[11];
    float* out = (float*)d_out;

    float *ctx, *Qb, *KVb, *biasb;
    uint32_t *xh, *ch, *oh, *wqh, *wkvh, *woh;
    cudaGetSymbolAddress((void**)&ctx,   g_ctx);
    cudaGetSymbolAddress((void**)&Qb,    g_Q);
    cudaGetSymbolAddress((void**)&KVb,   g_KV);
    cudaGetSymbolAddress((void**)&biasb, g_bias);
    cudaGetSymbolAddress((void**)&xh,  g_xh);
    cudaGetSymbolAddress((void**)&ch,  g_ch);
    cudaGetSymbolAddress((void**)&oh,  g_oh);
    cudaGetSymbolAddress((void**)&wqh, g_wqh);
    cudaGetSymbolAddress((void**)&wkvh,g_wkvh);
    cudaGetSymbolAddress((void**)&woh, g_woh);

    const int GEMM_SMEM = 2 * STG_B;   // 61440
    cudaFuncSetAttribute(gemm_cp, cudaFuncAttributeMaxDynamicSharedMemorySize, GEMM_SMEM);

    int n4q  = Dk * Dk / 8;
    int n4kv = 2 * Dk * Dk / 8;
    int n4x  = MQ * Dk / 8;
    int n4c  = MKV * Dk / 8;

    // converts + pool, then Q GEMM early (profiling target)
    cvt_kernel<<<(n4x + 255)/256, 256>>>((const float4*)x, (uint4*)xh, n4x);
    cvt_kernel<<<(n4q + 255)/256, 256>>>((const float4*)Wq, (uint4*)wqh, n4q);
    pool_kernel<<<dim3(Tt + 1, Bk), 256>>>(x, W_logit, ctx);
    gemm_cp<<<dim3(Dk/256, (MQ + 127)/128), 256, GEMM_SMEM>>>(xh, wqh, nullptr, Qb, MQ, Dk, Dk);
    cvt_kernel<<<(n4kv + 255)/256, 256>>>((const float4*)Wkv, (uint4*)wkvh, n4kv);
    cvt_kernel<<<(n4q + 255)/256, 256>>>((const float4*)Wo, (uint4*)woh, n4q);
    cpb_kernel<<<(NKp + 255) / 256, 256>>>(feats, maskp, cw1, cb1, cw2, cb2, biasb);
    cvt_kernel<<<(n4c + 255)/256, 256>>>((const float4*)ctx, (uint4*)ch, n4c);
    gemm_cp<<<dim3((2*Dk)/256, (MKV + 127)/128), 256, GEMM_SMEM>>>(ch, wkvh, nullptr, KVb, MKV, 2*Dk, Dk);

    const size_t ATTN_SMEM = (size_t)(272*SPQ + 64*SPV + 128*SPQ) * sizeof(uint32_t); // 93440
    cudaFuncSetAttribute(attn_mma, cudaFuncAttributeMaxDynamicSharedMemorySize, (int)ATTN_SMEM);
    attn_mma<<<Bk * Hh, 256, ATTN_SMEM>>>(Qb, KVb, biasb, oh);

    gemm_cp<<<dim3(Dk/256, (MQ + 127)/128), 256, GEMM_SMEM>>>(oh, woh, bo, out, MQ, Dk, Dk);
}

// round 10
// speedup vs baseline: 5.5920x; 1.0607x over previous
#include <cuda_runtime.h>
#include <cuda_fp16.h>
#include <cstdint>

// Problem constants
#define Bk   32
#define Nk   1025
#define Dk   768
#define Hh   12
#define dh   64
#define Tt   256
#define Kc   257
#define NKp  (Nk*Kc)
#define MQ   (Bk*Nk)      // 32800
#define MKV  (Bk*Kc)      // 8224

// Scratch (device globals) — fp16 packed operands (uint32 = 2 consecutive k)
__device__ float    g_ctx [MKV*Dk];
__device__ float    g_Q   [MQ*Dk];
__device__ float    g_KV  [MKV*2*Dk];
__device__ float    g_bias[(size_t)Hh*NKp];
__device__ uint32_t g_xh [MQ*Dk/2];
__device__ uint32_t g_ch [MKV*Dk/2];
__device__ uint32_t g_oh [MQ*Dk/2];
__device__ uint32_t g_wqh [Dk*Dk/2];
__device__ uint32_t g_wkvh[Dk*Dk];
__device__ uint32_t g_woh [Dk*Dk/2];

// ---------------------------------------------------------------------------
// helpers
// ---------------------------------------------------------------------------
__device__ __forceinline__ uint32_t h2u(float f0, float f1) {
    __half2 h = __floats2half2_rn(f0, f1);
    return *reinterpret_cast<uint32_t*>(&h);
}
__device__ __forceinline__ void mma16h(float* d, const uint32_t* a, uint32_t b0, uint32_t b1) {
    asm volatile(
        "mma.sync.aligned.m16n8k16.row.col.f32.f16.f16.f32 "
        "{%0,%1,%2,%3}, {%4,%5,%6,%7}, {%8,%9}, {%0,%1,%2,%3};"
        : "+f"(d[0]), "+f"(d[1]), "+f"(d[2]), "+f"(d[3])
        : "r"(a[0]), "r"(a[1]), "r"(a[2]), "r"(a[3]), "r"(b0), "r"(b1));
}
__device__ __forceinline__ uint32_t s2u(const void* p) {
    uint32_t a;
    asm("{ .reg .u64 t; cvta.to.shared.u64 t, %1; cvt.u32.u64 %0, t; }" : "=r"(a) : "l"(p));
    return a;
}
#define CP16(dst, src, sz) \
    asm volatile("cp.async.cg.shared.global [%0], [%1], 16, %2;" \
                 :: "r"(dst), "l"(src), "r"(sz) : "memory")
#define CP_COMMIT() asm volatile("cp.async.commit_group;" ::: "memory")
#define CP_WAIT1()  asm volatile("cp.async.wait_group 1;" ::: "memory")
#define CP_WAIT0()  asm volatile("cp.async.wait_group 0;" ::: "memory")

// ---------------------------------------------------------------------------
// convert fp32 -> packed fp16 (8 elements per thread)
// ---------------------------------------------------------------------------
__global__ void cvt_kernel(const float4* __restrict__ in, uint4* __restrict__ out, int n4) {
    int i = blockIdx.x * 256 + threadIdx.x;
    if (i >= n4) return;
    float4 a = in[2*i], b = in[2*i + 1];
    uint4 H;
    H.x = h2u(a.x, a.y);
    H.y = h2u(a.z, a.w);
    H.z = h2u(b.x, b.y);
    H.w = h2u(b.z, b.w);
    out[i] = H;
}

// ---------------------------------------------------------------------------
// Pooling (unchanged)
// ---------------------------------------------------------------------------
__global__ void pool_kernel(const float* __restrict__ x,
                            const float* __restrict__ wl,
                            float* __restrict__ ctx) {
    int t = blockIdx.x;
    int b = blockIdx.y;
    int tid = threadIdx.x;
    const float* xb = x + (size_t)b * Nk * Dk;
    if (t == Tt) {
        float* dst = ctx + (size_t)b * Kc * Dk;
        for (int dd = tid; dd < Dk; dd += 256) dst[dd] = xb[dd];
        return;
    }
    int gy = t >> 4, gx = t & 15;
    int n0 = 1 + (gy * 2) * 32 + gx * 2;
    int rows[4] = { n0, n0 + 1, n0 + 32, n0 + 33 };

    float p[4] = {0.f, 0.f, 0.f, 0.f};
    for (int dd = tid; dd < Dk; dd += 256) {
        float wv = wl[dd];
        p[0] += xb[(size_t)rows[0]*Dk + dd] * wv;
        p[1] += xb[(size_t)rows[1]*Dk + dd] * wv;
        p[2] += xb[(size_t)rows[2]*Dk + dd] * wv;
        p[3] += xb[(size_t)rows[3]*Dk + dd] * wv;
    }
    __shared__ float wred[4][8];
    __shared__ float sw4[4];
    int lane = tid & 31, w = tid >> 5;
    #pragma unroll
    for (int i = 0; i < 4; i++) {
        float v = p[i];
        #pragma unroll
        for (int off = 16; off; off >>= 1) v += __shfl_xor_sync(0xffffffffu, v, off);
        if (lane == 0) wred[i][w] = v;
    }
    __syncthreads();
    if (tid == 0) {
        float s[4];
        #pragma unroll
        for (int i = 0; i < 4; i++) {
            float a = 0.f;
            for (int ww = 0; ww < 8; ww++) a += wred[i][ww];
            s[i] = a;
        }
        float m = fmaxf(fmaxf(s[0], s[1]), fmaxf(s[2], s[3]));
        float e[4], su = 0.f;
        #pragma unroll
        for (int i = 0; i < 4; i++) { e[i] = expf(s[i] - m); su += e[i]; }
        float inv = 1.f / su;
        #pragma unroll
        for (int i = 0; i < 4; i++) sw4[i] = e[i] * inv;
    }
    __syncthreads();
    float w0 = sw4[0], w1 = sw4[1], w2 = sw4[2], w3 = sw4[3];
    float* dst = ctx + ((size_t)b * Kc + 1 + t) * Dk;
    for (int dd = tid; dd < Dk; dd += 256)
        dst[dd] = w0 * xb[(size_t)rows[0]*Dk + dd] + w1 * xb[(size_t)rows[1]*Dk + dd]
                + w2 * xb[(size_t)rows[2]*Dk + dd] + w3 * xb[(size_t)rows[3]*Dk + dd];
}

// ---------------------------------------------------------------------------
// CPB bias (unchanged)
// ---------------------------------------------------------------------------
__global__ void cpb_kernel(const float* __restrict__ feats, const float* __restrict__ mask,
                           const float* __restrict__ w1, const float* __restrict__ b1,
                           const float* __restrict__ w2, const float* __restrict__ b2,
                           float* __restrict__ bias) {
    __shared__ float sw1[64], sb1[32], sw2[12*32], sb2[12];
    int tid = threadIdx.x;
    if (tid < 64) sw1[tid] = w1[tid];
    if (tid >= 64 && tid < 96) sb1[tid - 64] = b1[tid - 64];
    if (tid >= 96 && tid < 108) sb2[tid - 96] = b2[tid - 96];
    for (int i = tid; i < 384; i += 256) sw2[i] = w2[i];
    __syncthreads();
    int idx = blockIdx.x * 256 + tid;
    if (idx >= NKp) return;
    float f0 = feats[2*idx], f1 = feats[2*idx + 1];
    float m = mask[idx];
    float acc[12];
    #pragma unroll
    for (int h = 0; h < 12; h++) acc[h] = sb2[h];
    #pragma unroll
    for (int j = 0; j < 32; j++) {
        float tt = f0 * sw1[2*j] + f1 * sw1[2*j + 1] + sb1[j];
        float g = 0.5f * tt * (1.0f + erff(tt * 0.7071067811865475f));
        #pragma unroll
        for (int h = 0; h < 12; h++) acc[h] += sw2[h*32 + j] * g;
    }
    #pragma unroll
    for (int h = 0; h < 12; h++) bias[(size_t)h * NKp + idx] = acc[h] * m;
}

// ---------------------------------------------------------------------------
// cp.async double-buffered fp16 GEMM. Block 128(M) x 256(N), K-chunk 64.
// 512 threads, 16 warps in 2(M) x 8(N) grid, warp tile 64x32.
// smem stage: A[128][36] B[256][36] (uint32, pad 4)
// ---------------------------------------------------------------------------
#define GST   36
#define AB_U32 (128*GST)               // 4608
#define BB_U32 (256*GST)               // 9216
#define STG_U32 (AB_U32 + BB_U32)      // 13824
#define STG_B  (STG_U32*4)             // 55296

__global__ void __launch_bounds__(512)
gemm_cp(const uint32_t* __restrict__ Ah, const uint32_t* __restrict__ Wh,
        const float* __restrict__ bias, float* __restrict__ C,
        int M, int Nn, int Kd) {
    extern __shared__ uint32_t smu[];
    uint32_t sb = s2u(smu);
    int tid = threadIdx.x, warp = tid >> 5, lane = tid & 31;
    int wm = warp & 1, wn = warp >> 1;     // 2 x 8 warp grid
    int r = lane >> 2, c = lane & 3;
    int row0 = blockIdx.y * 128, col0 = blockIdx.x * 256;
    int KPu = Kd >> 1;
    int nchk = Kd / 64;

    float acc[4][4][4];
    #pragma unroll
    for (int mt = 0; mt < 4; mt++)
        #pragma unroll
        for (int nt = 0; nt < 4; nt++)
            #pragma unroll
            for (int i = 0; i < 4; i++) acc[mt][nt][i] = 0.f;

    auto stage_load = [&](int s, int kcu) {
        uint32_t stb = sb + s * STG_B;
        #pragma unroll
        for (int i = 0; i < 2; i++) {          // A: 128 rows x 8 chunks of 16B
            int cid = i * 512 + tid;
            int row = cid >> 3, kj = cid & 7;
            const uint32_t* sh = Ah + (size_t)(row0 + row) * KPu + kcu + kj * 4;
            uint32_t dst = stb + (row * GST + kj * 4) * 4;
            int sz = (row0 + row < M) ? 16 : 0;
            CP16(dst, sh, sz);
        }
        #pragma unroll
        for (int i = 0; i < 4; i++) {          // B: 256 rows x 8 chunks
            int cid = i * 512 + tid;
            int row = cid >> 3, kj = cid & 7;
            const uint32_t* sh = Wh + (size_t)(col0 + row) * KPu + kcu + kj * 4;
            uint32_t dst = stb + (AB_U32 + row * GST + kj * 4) * 4;
            CP16(dst, sh, 16);
        }
        CP_COMMIT();
    };

    stage_load(0, 0);

    for (int ch = 0; ch < nchk; ch++) {
        if (ch + 1 < nchk) { stage_load((ch + 1) & 1, (ch + 1) * 32); CP_WAIT1(); }
        else               { CP_WAIT0(); }
        __syncthreads();

        const uint32_t* ap = smu + (ch & 1) * STG_U32;
        const uint32_t* bp = ap + AB_U32;

        #pragma unroll
        for (int kk = 0; kk < 4; kk++) {
            int kb = kk * 8;
            uint32_t fah[4][4];
            #pragma unroll
            for (int mt = 0; mt < 4; mt++) {
                int mrow = wm * 64 + mt * 16;
                fah[mt][0] = ap[(mrow + r)     * GST + kb + c];
                fah[mt][1] = ap[(mrow + r + 8) * GST + kb + c];
                fah[mt][2] = ap[(mrow + r)     * GST + kb + c + 4];
                fah[mt][3] = ap[(mrow + r + 8) * GST + kb + c + 4];
            }
            #pragma unroll
            for (int nt = 0; nt < 4; nt++) {
                int nrow = wn * 32 + nt * 8;
                uint32_t b0 = bp[(nrow + r) * GST + kb + c];
                uint32_t b1 = bp[(nrow + r) * GST + kb + c + 4];
                #pragma unroll
                for (int mt = 0; mt < 4; mt++) mma16h(acc[mt][nt], fah[mt], b0, b1);
            }
        }
        __syncthreads();
    }

    #pragma unroll
    for (int mt = 0; mt < 4; mt++) {
        int rowa = row0 + wm * 64 + mt * 16 + r;
        #pragma unroll
        for (int nt = 0; nt < 4; nt++) {
            int colb = col0 + wn * 32 + nt * 8 + 2 * c;
            float bv0 = bias ? bias[colb]     : 0.f;
            float bv1 = bias ? bias[colb + 1] : 0.f;
            if (rowa < M) {
                float2 v = make_float2(acc[mt][nt][0] + bv0, acc[mt][nt][1] + bv1);
                *(float2*)&C[(size_t)rowa * Nn + colb] = v;
            }
            if (rowa + 8 < M) {
                float2 v = make_float2(acc[mt][nt][2] + bv0, acc[mt][nt][3] + bv1);
                *(float2*)&C[(size_t)(rowa + 8) * Nn + colb] = v;
            }
        }
    }
}

// ---------------------------------------------------------------------------
// fp16 tensor-core attention (unchanged from R8)
// ---------------------------------------------------------------------------
#define SPQ 36
#define SPV 140

__global__ void __launch_bounds__(256)
attn_mma(const float* __restrict__ Q, const float* __restrict__ KV,
         const float* __restrict__ biasb, uint32_t* __restrict__ Oh) {
    extern __shared__ uint32_t sm4[];
    uint32_t* Kh = sm4;
    uint32_t* Vh = Kh + 272 * SPQ;
    uint32_t* Qh = Vh + 64 * SPV;
    __half* Khb = (__half*)Kh;
    __half* Vhb = (__half*)Vh;
    __half* Qhb = (__half*)Qh;

    int bh = blockIdx.x;
    int b = bh / Hh, h = bh - b * Hh;
    int tid = threadIdx.x, wr = tid >> 5, lane = tid & 31;
    int r = lane >> 2, c = lane & 3;

    const float* kv = KV + (size_t)b * Kc * (2*Dk) + h * dh;
    for (int i = tid; i < 272 * 64; i += 256) {
        int kpos = i >> 6, d = i & 63;
        float fk = 0.f, fv = 0.f;
        if (kpos < Kc) {
            const float* p = kv + (size_t)kpos * (2*Dk) + d;
            fk = p[0]; fv = p[Dk];
        }
        Khb[kpos * 72 + d]  = __float2half_rn(fk);
        Vhb[d * 280 + kpos] = __float2half_rn(fv);
    }

    #pragma unroll 1
    for (int bx = 0; bx < 9; bx++) {
        int n0 = bx * 128;
        __syncthreads();
        for (int i = tid; i < 128 * 64; i += 256) {
            int rl = i >> 6, d = i & 63;
            int n = n0 + rl; if (n > 1024) n = 1024;
            float f = Q[((size_t)b * Nk + n) * Dk + h * dh + d];
            Qhb[rl * 72 + d] = __float2half_rn(f);
        }
        __syncthreads();

        int m0 = wr * 16;
        uint32_t qfh[4][4];
        #pragma unroll
        for (int kt = 0; kt < 4; kt++) {
            qfh[kt][0] = Qh[(m0+r)*SPQ   + kt*8 + c];
            qfh[kt][1] = Qh[(m0+r+8)*SPQ + kt*8 + c];
            qfh[kt][2] = Qh[(m0+r)*SPQ   + kt*8 + c + 4];
            qfh[kt][3] = Qh[(m0+r+8)*SPQ + kt*8 + c + 4];
        }

        float lg[33][4];
        #pragma unroll
        for (int nt = 0; nt < 33; nt++)
            #pragma unroll
            for (int i = 0; i < 4; i++) lg[nt][i] = 0.f;

        #pragma unroll
        for (int gq = 0; gq < 8; gq++) {
            #pragma unroll
            for (int kt = 0; kt < 4; kt++) {
                uint32_t kfh[4][2];
                #pragma unroll
                for (int x = 0; x < 4; x++) {
                    int kr = ((gq*4 + x)*8 + r) * SPQ + kt*8 + c;
                    kfh[x][0] = Kh[kr]; kfh[x][1] = Kh[kr + 4];
                }
                #pragma unroll
                for (int x = 0; x < 4; x++)
                    mma16h(lg[gq*4 + x], qfh[kt], kfh[x][0], kfh[x][1]);
            }
        }
        #pragma unroll
        for (int kt = 0; kt < 4; kt++) {
            int kr = (32*8 + r) * SPQ + kt*8 + c;
            mma16h(lg[32], qfh[kt], Kh[kr], Kh[kr + 4]);
        }

        int nr  = n0 + m0 + r;
        int nr8 = nr + 8;
        const float* bp0 = biasb + ((size_t)h * Nk + (nr  > 1024 ? 1024 : nr )) * Kc;
        const float* bp1 = biasb + ((size_t)h * Nk + (nr8 > 1024 ? 1024 : nr8)) * Kc;
        #pragma unroll
        for (int nt = 0; nt < 33; nt++) {
            int k0 = nt*8 + 2*c, k1 = k0 + 1;
            lg[nt][0] = (k0 < Kc) ? lg[nt][0] * 0.125f + bp0[k0] : -1e30f;
            lg[nt][1] = (k1 < Kc) ? lg[nt][1] * 0.125f + bp0[k1] : -1e30f;
            lg[nt][2] = (k0 < Kc) ? lg[nt][2] * 0.125f + bp1[k0] : -1e30f;
            lg[nt][3] = (k1 < Kc) ? lg[nt][3] * 0.125f + bp1[k1] : -1e30f;
        }

        float mx0 = -1e30f, mx1 = -1e30f;
        #pragma unroll
        for (int nt = 0; nt < 33; nt++) {
            mx0 = fmaxf(mx0, fmaxf(lg[nt][0], lg[nt][1]));
            mx1 = fmaxf(mx1, fmaxf(lg[nt][2], lg[nt][3]));
        }
        mx0 = fmaxf(mx0, __shfl_xor_sync(0xffffffffu, mx0, 1));
        mx0 = fmaxf(mx0, __shfl_xor_sync(0xffffffffu, mx0, 2));
        mx1 = fmaxf(mx1, __shfl_xor_sync(0xffffffffu, mx1, 1));
        mx1 = fmaxf(mx1, __shfl_xor_sync(0xffffffffu, mx1, 2));
        float s0 = 0.f, s1 = 0.f;
        #pragma unroll
        for (int nt = 0; nt < 33; nt++) {
            lg[nt][0] = __expf(lg[nt][0] - mx0); s0 += lg[nt][0];
            lg[nt][1] = __expf(lg[nt][1] - mx0); s0 += lg[nt][1];
            lg[nt][2] = __expf(lg[nt][2] - mx1); s1 += lg[nt][2];
            lg[nt][3] = __expf(lg[nt][3] - mx1); s1 += lg[nt][3];
        }
        s0 += __shfl_xor_sync(0xffffffffu, s0, 1);
        s0 += __shfl_xor_sync(0xffffffffu, s0, 2);
        s1 += __shfl_xor_sync(0xffffffffu, s1, 1);
        s1 += __shfl_xor_sync(0xffffffffu, s1, 2);
        float inv0 = 1.f / s0, inv1 = 1.f / s1;

        float oacc[8][4];
        #pragma unroll
        for (int nt = 0; nt < 8; nt++)
            #pragma unroll
            for (int i = 0; i < 4; i++) oacc[nt][i] = 0.f;

        #pragma unroll
        for (int kt2 = 0; kt2 < 17; kt2++) {
            uint32_t ph[4];
            int e0 = 2*kt2, e1 = 2*kt2 + 1;
            ph[0] = h2u(lg[e0][0], lg[e0][1]);
            ph[1] = h2u(lg[e0][2], lg[e0][3]);
            if (e1 < 33) {
                ph[2] = h2u(lg[e1][0], lg[e1][1]);
                ph[3] = h2u(lg[e1][2], lg[e1][3]);
            } else {
                ph[2] = ph[3] = 0u;
            }
            uint32_t vfh[8][2];
            #pragma unroll
            for (int nt = 0; nt < 8; nt++) {
                int vr = (nt*8 + r) * SPV + kt2*8 + c;
                vfh[nt][0] = Vh[vr]; vfh[nt][1] = Vh[vr + 4];
            }
            #pragma unroll
            for (int nt = 0; nt < 8; nt++)
                mma16h(oacc[nt], ph, vfh[nt][0], vfh[nt][1]);
        }

        bool v0 = (nr <= 1024), v1 = (nr8 <= 1024);
        size_t ro0 = ((size_t)b * Nk + nr ) * (Dk/2) + h * (dh/2);
        size_t ro1 = ((size_t)b * Nk + nr8) * (Dk/2) + h * (dh/2);
        #pragma unroll
        for (int nt = 0; nt < 8; nt++) {
            if (v0) Oh[ro0 + nt*4 + c] = h2u(oacc[nt][0] * inv0, oacc[nt][1] * inv0);
            if (v1) Oh[ro1 + nt*4 + c] = h2u(oacc[nt][2] * inv1, oacc[nt][3] * inv1);
        }
    }
}

// ---------------------------------------------------------------------------
// Launch
// ---------------------------------------------------------------------------
extern "C" void kernel_launch(void* const* d_in, const int* in_sizes, int n_in,
                              void* d_out, int out_size) {
    const float* x       = (const float*)d_in[0];
    const float* W_logit = (const float*)d_in[1];
    const float* Wq      = (const float*)d_in[2];
    const float* Wkv     = (const float*)d_in[3];
    const float* Wo      = (const float*)d_in[4];
    const float* bo      = (const float*)d_in[5];
    const float* cw1     = (const float*)d_in[6];
    const float* cb1     = (const float*)d_in[7];
    const float* cw2     = (const float*)d_in[8];
    const float* cb2     = (const float*)d_in[9];
    const float* feats   = (const float*)d_in[10];
    const float* maskp   = (const float*)d_in[11];
    float* out = (float*)d_out;

    float *ctx, *Qb, *KVb, *biasb;
    uint32_t *xh, *ch, *oh, *wqh, *wkvh, *woh;
    cudaGetSymbolAddress((void**)&ctx,   g_ctx);
    cudaGetSymbolAddress((void**)&Qb,    g_Q);
    cudaGetSymbolAddress((void**)&KVb,   g_KV);
    cudaGetSymbolAddress((void**)&biasb, g_bias);
    cudaGetSymbolAddress((void**)&xh,  g_xh);
    cudaGetSymbolAddress((void**)&ch,  g_ch);
    cudaGetSymbolAddress((void**)&oh,  g_oh);
    cudaGetSymbolAddress((void**)&wqh, g_wqh);
    cudaGetSymbolAddress((void**)&wkvh,g_wkvh);
    cudaGetSymbolAddress((void**)&woh, g_woh);

    const int GEMM_SMEM = 2 * STG_B;   // 110592
    cudaFuncSetAttribute(gemm_cp, cudaFuncAttributeMaxDynamicSharedMemorySize, GEMM_SMEM);

    int n4q  = Dk * Dk / 8;
    int n4kv = 2 * Dk * Dk / 8;
    int n4x  = MQ * Dk / 8;
    int n4c  = MKV * Dk / 8;

    cvt_kernel<<<(n4x + 255)/256, 256>>>((const float4*)x, (uint4*)xh, n4x);
    cvt_kernel<<<(n4q + 255)/256, 256>>>((const float4*)Wq, (uint4*)wqh, n4q);
    pool_kernel<<<dim3(Tt + 1, Bk), 256>>>(x, W_logit, ctx);
    gemm_cp<<<dim3(Dk/256, (MQ + 127)/128), 512, GEMM_SMEM>>>(xh, wqh, nullptr, Qb, MQ, Dk, Dk);
    cvt_kernel<<<(n4kv + 255)/256, 256>>>((const float4*)Wkv, (uint4*)wkvh, n4kv);
    cvt_kernel<<<(n4q + 255)/256, 256>>>((const float4*)Wo, (uint4*)woh, n4q);
    cpb_kernel<<<(NKp + 255) / 256, 256>>>(feats, maskp, cw1, cb1, cw2, cb2, biasb);
    cvt_kernel<<<(n4c + 255)/256, 256>>>((const float4*)ctx, (uint4*)ch, n4c);
    gemm_cp<<<dim3((2*Dk)/256, (MKV + 127)/128), 512, GEMM_SMEM>>>(ch, wkvh, nullptr, KVb, MKV, 2*Dk, Dk);

    const size_t ATTN_SMEM = (size_t)(272*SPQ + 64*SPV + 128*SPQ) * sizeof(uint32_t); // 93440
    cudaFuncSetAttribute(attn_mma, cudaFuncAttributeMaxDynamicSharedMemorySize, (int)ATTN_SMEM);
    attn_mma<<<Bk * Hh, 256, ATTN_SMEM>>>(Qb, KVb, biasb, oh);

    gemm_cp<<<dim3(Dk/256, (MQ + 127)/128), 512, GEMM_SMEM>>>(oh, woh, bo, out, MQ, Dk, Dk);
}

// round 11
// speedup vs baseline: 5.9221x; 1.0590x over previous
#include <cuda_runtime.h>
#include <cuda_fp16.h>
#include <cstdint>

// Problem constants
#define Bk   32
#define Nk   1025
#define Dk   768
#define Hh   12
#define dh   64
#define Tt   256
#define Kc   257
#define NKp  (Nk*Kc)
#define MQ   (Bk*Nk)      // 32800
#define MKV  (Bk*Kc)      // 8224

// Scratch (device globals) — fp16 packed operands (uint32 = 2 consecutive k)
__device__ float    g_ctx [MKV*Dk];
__device__ float    g_Q   [MQ*Dk];
__device__ float    g_KV  [MKV*2*Dk];
__device__ float    g_bias[(size_t)Hh*NKp];
__device__ uint32_t g_xh [MQ*Dk/2];
__device__ uint32_t g_ch [MKV*Dk/2];
__device__ uint32_t g_oh [MQ*Dk/2];
__device__ uint32_t g_wqh [Dk*Dk/2];
__device__ uint32_t g_wkvh[Dk*Dk];
__device__ uint32_t g_woh [Dk*Dk/2];

// ---------------------------------------------------------------------------
// helpers
// ---------------------------------------------------------------------------
__device__ __forceinline__ uint32_t h2u(float f0, float f1) {
    __half2 h = __floats2half2_rn(f0, f1);
    return *reinterpret_cast<uint32_t*>(&h);
}
__device__ __forceinline__ void mma16h(float* d, const uint32_t* a, uint32_t b0, uint32_t b1) {
    asm volatile(
        "mma.sync.aligned.m16n8k16.row.col.f32.f16.f16.f32 "
        "{%0,%1,%2,%3}, {%4,%5,%6,%7}, {%8,%9}, {%0,%1,%2,%3};"
        : "+f"(d[0]), "+f"(d[1]), "+f"(d[2]), "+f"(d[3])
        : "r"(a[0]), "r"(a[1]), "r"(a[2]), "r"(a[3]), "r"(b0), "r"(b1));
}
__device__ __forceinline__ void ldsm4(uint32_t* d, uint32_t addr) {
    asm volatile("ldmatrix.sync.aligned.m8n8.x4.shared.b16 {%0,%1,%2,%3}, [%4];"
        : "=r"(d[0]), "=r"(d[1]), "=r"(d[2]), "=r"(d[3]) : "r"(addr));
}
__device__ __forceinline__ uint32_t s2u(const void* p) {
    uint32_t a;
    asm("{ .reg .u64 t; cvta.to.shared.u64 t, %1; cvt.u32.u64 %0, t; }" : "=r"(a) : "l"(p));
    return a;
}
#define CP16(dst, src, sz) \
    asm volatile("cp.async.cg.shared.global [%0], [%1], 16, %2;" \
                 :: "r"(dst), "l"(src), "r"(sz) : "memory")
#define CP_COMMIT() asm volatile("cp.async.commit_group;" ::: "memory")
#define CP_WAIT1()  asm volatile("cp.async.wait_group 1;" ::: "memory")
#define CP_WAIT0()  asm volatile("cp.async.wait_group 0;" ::: "memory")

// ---------------------------------------------------------------------------
// convert fp32 -> packed fp16 (8 elements per thread)
// ---------------------------------------------------------------------------
__global__ void cvt_kernel(const float4* __restrict__ in, uint4* __restrict__ out, int n4) {
    int i = blockIdx.x * 256 + threadIdx.x;
    if (i >= n4) return;
    float4 a = in[2*i], b = in[2*i + 1];
    uint4 H;
    H.x = h2u(a.x, a.y);
    H.y = h2u(a.z, a.w);
    H.z = h2u(b.x, b.y);
    H.w = h2u(b.z, b.w);
    out[i] = H;
}

// ---------------------------------------------------------------------------
// Pooling (unchanged)
// ---------------------------------------------------------------------------
__global__ void pool_kernel(const float* __restrict__ x,
                            const float* __restrict__ wl,
                            float* __restrict__ ctx) {
    int t = blockIdx.x;
    int b = blockIdx.y;
    int tid = threadIdx.x;
    const float* xb = x + (size_t)b * Nk * Dk;
    if (t == Tt) {
        float* dst = ctx + (size_t)b * Kc * Dk;
        for (int dd = tid; dd < Dk; dd += 256) dst[dd] = xb[dd];
        return;
    }
    int gy = t >> 4, gx = t & 15;
    int n0 = 1 + (gy * 2) * 32 + gx * 2;
    int rows[4] = { n0, n0 + 1, n0 + 32, n0 + 33 };

    float p[4] = {0.f, 0.f, 0.f, 0.f};
    for (int dd = tid; dd < Dk; dd += 256) {
        float wv = wl[dd];
        p[0] += xb[(size_t)rows[0]*Dk + dd] * wv;
        p[1] += xb[(size_t)rows[1]*Dk + dd] * wv;
        p[2] += xb[(size_t)rows[2]*Dk + dd] * wv;
        p[3] += xb[(size_t)rows[3]*Dk + dd] * wv;
    }
    __shared__ float wred[4][8];
    __shared__ float sw4[4];
    int lane = tid & 31, w = tid >> 5;
    #pragma unroll
    for (int i = 0; i < 4; i++) {
        float v = p[i];
        #pragma unroll
        for (int off = 16; off; off >>= 1) v += __shfl_xor_sync(0xffffffffu, v, off);
        if (lane == 0) wred[i][w] = v;
    }
    __syncthreads();
    if (tid == 0) {
        float s[4];
        #pragma unroll
        for (int i = 0; i < 4; i++) {
            float a = 0.f;
            for (int ww = 0; ww < 8; ww++) a += wred[i][ww];
            s[i] = a;
        }
        float m = fmaxf(fmaxf(s[0], s[1]), fmaxf(s[2], s[3]));
        float e[4], su = 0.f;
        #pragma unroll
        for (int i = 0; i < 4; i++) { e[i] = expf(s[i] - m); su += e[i]; }
        float inv = 1.f / su;
        #pragma unroll
        for (int i = 0; i < 4; i++) sw4[i] = e[i] * inv;
    }
    __syncthreads();
    float w0 = sw4[0], w1 = sw4[1], w2 = sw4[2], w3 = sw4[3];
    float* dst = ctx + ((size_t)b * Kc + 1 + t) * Dk;
    for (int dd = tid; dd < Dk; dd += 256)
        dst[dd] = w0 * xb[(size_t)rows[0]*Dk + dd] + w1 * xb[(size_t)rows[1]*Dk + dd]
                + w2 * xb[(size_t)rows[2]*Dk + dd] + w3 * xb[(size_t)rows[3]*Dk + dd];
}

// ---------------------------------------------------------------------------
// CPB bias (unchanged)
// ---------------------------------------------------------------------------
__global__ void cpb_kernel(const float* __restrict__ feats, const float* __restrict__ mask,
                           const float* __restrict__ w1, const float* __restrict__ b1,
                           const float* __restrict__ w2, const float* __restrict__ b2,
                           float* __restrict__ bias) {
    __shared__ float sw1[64], sb1[32], sw2[12*32], sb2[12];
    int tid = threadIdx.x;
    if (tid < 64) sw1[tid] = w1[tid];
    if (tid >= 64 && tid < 96) sb1[tid - 64] = b1[tid - 64];
    if (tid >= 96 && tid < 108) sb2[tid - 96] = b2[tid - 96];
    for (int i = tid; i < 384; i += 256) sw2[i] = w2[i];
    __syncthreads();
    int idx = blockIdx.x * 256 + tid;
    if (idx >= NKp) return;
    float f0 = feats[2*idx], f1 = feats[2*idx + 1];
    float m = mask[idx];
    float acc[12];
    #pragma unroll
    for (int h = 0; h < 12; h++) acc[h] = sb2[h];
    #pragma unroll
    for (int j = 0; j < 32; j++) {
        float tt = f0 * sw1[2*j] + f1 * sw1[2*j + 1] + sb1[j];
        float g = 0.5f * tt * (1.0f + erff(tt * 0.7071067811865475f));
        #pragma unroll
        for (int h = 0; h < 12; h++) acc[h] += sw2[h*32 + j] * g;
    }
    #pragma unroll
    for (int h = 0; h < 12; h++) bias[(size_t)h * NKp + idx] = acc[h] * m;
}

// ---------------------------------------------------------------------------
// cp.async double-buffered fp16 GEMM with ldmatrix fragment loads.
// Block 128(M) x 256(N), K-chunk 64, 512 threads, 16 warps 2x8, warp 64x32.
// ---------------------------------------------------------------------------
#define GST   36
#define AB_U32 (128*GST)               // 4608
#define BB_U32 (256*GST)               // 9216
#define STG_U32 (AB_U32 + BB_U32)      // 13824
#define STG_B  (STG_U32*4)             // 55296

__global__ void __launch_bounds__(512)
gemm_cp(const uint32_t* __restrict__ Ah, const uint32_t* __restrict__ Wh,
        const float* __restrict__ bias, float* __restrict__ C,
        int M, int Nn, int Kd) {
    extern __shared__ uint32_t smu[];
    uint32_t sb = s2u(smu);
    int tid = threadIdx.x, warp = tid >> 5, lane = tid & 31;
    int wm = warp & 1, wn = warp >> 1;     // 2 x 8 warp grid
    int r = lane >> 2, c = lane & 3;
    int row0 = blockIdx.y * 128, col0 = blockIdx.x * 256;
    int KPu = Kd >> 1;
    int nchk = Kd / 64;

    // ldmatrix lane addressing
    int la  = lane & 15;                 // A row offset (0..15)
    int lga = (lane >> 4) * 4;           // A col offset (uint32)
    int lb  = (lane & 7) + ((lane >> 4) << 3);   // B row offset
    int lcb = ((lane >> 3) & 1) * 4;     // B col offset (uint32)

    float acc[4][4][4];
    #pragma unroll
    for (int mt = 0; mt < 4; mt++)
        #pragma unroll
        for (int nt = 0; nt < 4; nt++)
            #pragma unroll
            for (int i = 0; i < 4; i++) acc[mt][nt][i] = 0.f;

    auto stage_load = [&](int s, int kcu) {
        uint32_t stb = sb + s * STG_B;
        #pragma unroll
        for (int i = 0; i < 2; i++) {          // A: 128 rows x 8 chunks of 16B
            int cid = i * 512 + tid;
            int row = cid >> 3, kj = cid & 7;
            const uint32_t* sh = Ah + (size_t)(row0 + row) * KPu + kcu + kj * 4;
            uint32_t dst = stb + (row * GST + kj * 4) * 4;
            int sz = (row0 + row < M) ? 16 : 0;
            CP16(dst, sh, sz);
        }
        #pragma unroll
        for (int i = 0; i < 4; i++) {          // B: 256 rows x 8 chunks
            int cid = i * 512 + tid;
            int row = cid >> 3, kj = cid & 7;
            const uint32_t* sh = Wh + (size_t)(col0 + row) * KPu + kcu + kj * 4;
            uint32_t dst = stb + (AB_U32 + row * GST + kj * 4) * 4;
            CP16(dst, sh, 16);
        }
        CP_COMMIT();
    };

    stage_load(0, 0);

    for (int ch = 0; ch < nchk; ch++) {
        if (ch + 1 < nchk) { stage_load((ch + 1) & 1, (ch + 1) * 32); CP_WAIT1(); }
        else               { CP_WAIT0(); }
        __syncthreads();

        uint32_t apb = sb + (ch & 1) * STG_B;
        uint32_t bpb = apb + AB_U32 * 4;

        #pragma unroll
        for (int kk = 0; kk < 4; kk++) {
            int kb = kk * 8;
            uint32_t fah[4][4];
            #pragma unroll
            for (int mt = 0; mt < 4; mt++)
                ldsm4(fah[mt], apb + (((wm*64 + mt*16 + la) * GST) + kb + lga) * 4);
            uint32_t fb[2][4];
            #pragma unroll
            for (int p = 0; p < 2; p++)
                ldsm4(fb[p], bpb + (((wn*32 + p*16 + lb) * GST) + kb + lcb) * 4);
            #pragma unroll
            for (int nt = 0; nt < 4; nt++) {
                uint32_t b0 = fb[nt >> 1][(nt & 1) * 2];
                uint32_t b1 = fb[nt >> 1][(nt & 1) * 2 + 1];
                #pragma unroll
                for (int mt = 0; mt < 4; mt++) mma16h(acc[mt][nt], fah[mt], b0, b1);
            }
        }
        __syncthreads();
    }

    #pragma unroll
    for (int mt = 0; mt < 4; mt++) {
        int rowa = row0 + wm * 64 + mt * 16 + r;
        #pragma unroll
        for (int nt = 0; nt < 4; nt++) {
            int colb = col0 + wn * 32 + nt * 8 + 2 * c;
            float bv0 = bias ? bias[colb]     : 0.f;
            float bv1 = bias ? bias[colb + 1] : 0.f;
            if (rowa < M) {
                float2 v = make_float2(acc[mt][nt][0] + bv0, acc[mt][nt][1] + bv1);
                *(float2*)&C[(size_t)rowa * Nn + colb] = v;
            }
            if (rowa + 8 < M) {
                float2 v = make_float2(acc[mt][nt][2] + bv0, acc[mt][nt][3] + bv1);
                *(float2*)&C[(size_t)(rowa + 8) * Nn + colb] = v;
            }
        }
    }
}

// ---------------------------------------------------------------------------
// fp16 tensor-core attention with ldmatrix fragment loads.
// ---------------------------------------------------------------------------
#define SPQ 36
#define SPV 140

__global__ void __launch_bounds__(256)
attn_mma(const float* __restrict__ Q, const float* __restrict__ KV,
         const float* __restrict__ biasb, uint32_t* __restrict__ Oh) {
    extern __shared__ uint32_t sm4[];
    uint32_t* Kh = sm4;                  // [272][36]
    uint32_t* Vh = Kh + 272 * SPQ;       // [64][140]
    uint32_t* Qh = Vh + 64 * SPV;        // [128][36]
    __half* Khb = (__half*)Kh;
    __half* Vhb = (__half*)Vh;
    __half* Qhb = (__half*)Qh;

    int bh = blockIdx.x;
    int b = bh / Hh, h = bh - b * Hh;
    int tid = threadIdx.x, wr = tid >> 5, lane = tid & 31;
    int r = lane >> 2, c = lane & 3;

    // ldmatrix lane addressing
    int la  = lane & 15;
    int lga = (lane >> 4) * 4;
    int lb  = (lane & 7) + ((lane >> 4) << 3);
    int lcb = ((lane >> 3) & 1) * 4;

    uint32_t kba = s2u(Kh), vba = s2u(Vh), qba = s2u(Qh);

    const float* kv = KV + (size_t)b * Kc * (2*Dk) + h * dh;
    for (int i = tid; i < 272 * 64; i += 256) {
        int kpos = i >> 6, d = i & 63;
        float fk = 0.f, fv = 0.f;
        if (kpos < Kc) {
            const float* p = kv + (size_t)kpos * (2*Dk) + d;
            fk = p[0]; fv = p[Dk];
        }
        Khb[kpos * 72 + d]  = __float2half_rn(fk);
        Vhb[d * 280 + kpos] = __float2half_rn(fv);
    }

    #pragma unroll 1
    for (int bx = 0; bx < 9; bx++) {
        int n0 = bx * 128;
        __syncthreads();
        for (int i = tid; i < 128 * 64; i += 256) {
            int rl = i >> 6, d = i & 63;
            int n = n0 + rl; if (n > 1024) n = 1024;
            float f = Q[((size_t)b * Nk + n) * Dk + h * dh + d];
            Qhb[rl * 72 + d] = __float2half_rn(f);
        }
        __syncthreads();

        int m0 = wr * 16;
        uint32_t qfh[4][4];
        #pragma unroll
        for (int kt = 0; kt < 4; kt++)
            ldsm4(qfh[kt], qba + ((m0 + la) * SPQ + kt*8 + lga) * 4);

        float lg[33][4];
        #pragma unroll
        for (int nt = 0; nt < 33; nt++)
            #pragma unroll
            for (int i = 0; i < 4; i++) lg[nt][i] = 0.f;

        // QK^T: groups of 4 nt; K frags via ldmatrix.x4 (2 nt per LDSM)
        #pragma unroll
        for (int gq = 0; gq < 8; gq++) {
            #pragma unroll
            for (int kt = 0; kt < 4; kt++) {
                uint32_t kf[2][4];
                #pragma unroll
                for (int p = 0; p < 2; p++)
                    ldsm4(kf[p], kba + (((gq*4 + p*2)*8 + lb) * SPQ + kt*8 + lcb) * 4);
                #pragma unroll
                for (int x = 0; x < 4; x++) {
                    uint32_t b0 = kf[x >> 1][(x & 1) * 2];
                    uint32_t b1 = kf[x >> 1][(x & 1) * 2 + 1];
                    mma16h(lg[gq*4 + x], qfh[kt], b0, b1);
                }
            }
        }
        // tail nt = 32 (scalar loads)
        #pragma unroll
        for (int kt = 0; kt < 4; kt++) {
            int kr = (32*8 + r) * SPQ + kt*8 + c;
            mma16h(lg[32], qfh[kt], Kh[kr], Kh[kr + 4]);
        }

        int nr  = n0 + m0 + r;
        int nr8 = nr + 8;
        const float* bp0 = biasb + ((size_t)h * Nk + (nr  > 1024 ? 1024 : nr )) * Kc;
        const float* bp1 = biasb + ((size_t)h * Nk + (nr8 > 1024 ? 1024 : nr8)) * Kc;
        #pragma unroll
        for (int nt = 0; nt < 33; nt++) {
            int k0 = nt*8 + 2*c, k1 = k0 + 1;
            lg[nt][0] = (k0 < Kc) ? lg[nt][0] * 0.125f + bp0[k0] : -1e30f;
            lg[nt][1] = (k1 < Kc) ? lg[nt][1] * 0.125f + bp0[k1] : -1e30f;
            lg[nt][2] = (k0 < Kc) ? lg[nt][2] * 0.125f + bp1[k0] : -1e30f;
            lg[nt][3] = (k1 < Kc) ? lg[nt][3] * 0.125f + bp1[k1] : -1e30f;
        }

        float mx0 = -1e30f, mx1 = -1e30f;
        #pragma unroll
        for (int nt = 0; nt < 33; nt++) {
            mx0 = fmaxf(mx0, fmaxf(lg[nt][0], lg[nt][1]));
            mx1 = fmaxf(mx1, fmaxf(lg[nt][2], lg[nt][3]));
        }
        mx0 = fmaxf(mx0, __shfl_xor_sync(0xffffffffu, mx0, 1));
        mx0 = fmaxf(mx0, __shfl_xor_sync(0xffffffffu, mx0, 2));
        mx1 = fmaxf(mx1, __shfl_xor_sync(0xffffffffu, mx1, 1));
        mx1 = fmaxf(mx1, __shfl_xor_sync(0xffffffffu, mx1, 2));
        float s0 = 0.f, s1 = 0.f;
        #pragma unroll
        for (int nt = 0; nt < 33; nt++) {
            lg[nt][0] = __expf(lg[nt][0] - mx0); s0 += lg[nt][0];
            lg[nt][1] = __expf(lg[nt][1] - mx0); s0 += lg[nt][1];
            lg[nt][2] = __expf(lg[nt][2] - mx1); s1 += lg[nt][2];
            lg[nt][3] = __expf(lg[nt][3] - mx1); s1 += lg[nt][3];
        }
        s0 += __shfl_xor_sync(0xffffffffu, s0, 1);
        s0 += __shfl_xor_sync(0xffffffffu, s0, 2);
        s1 += __shfl_xor_sync(0xffffffffu, s1, 1);
        s1 += __shfl_xor_sync(0xffffffffu, s1, 2);
        float inv0 = 1.f / s0, inv1 = 1.f / s1;

        float oacc[8][4];
        #pragma unroll
        for (int nt = 0; nt < 8; nt++)
            #pragma unroll
            for (int i = 0; i < 4; i++) oacc[nt][i] = 0.f;

        // PV: P folds to A-frags; V frags via ldmatrix.x4 (2 nt per LDSM)
        #pragma unroll
        for (int kt2 = 0; kt2 < 17; kt2++) {
            uint32_t ph[4];
            int e0 = 2*kt2, e1 = 2*kt2 + 1;
            ph[0] = h2u(lg[e0][0], lg[e0][1]);
            ph[1] = h2u(lg[e0][2], lg[e0][3]);
            if (e1 < 33) {
                ph[2] = h2u(lg[e1][0], lg[e1][1]);
                ph[3] = h2u(lg[e1][2], lg[e1][3]);
            } else {
                ph[2] = ph[3] = 0u;
            }
            uint32_t vf[4][4];
            #pragma unroll
            for (int p = 0; p < 4; p++)
                ldsm4(vf[p], vba + ((p*16 + lb) * SPV + kt2*8 + lcb) * 4);
            #pragma unroll
            for (int nt = 0; nt < 8; nt++) {
                uint32_t b0 = vf[nt >> 1][(nt & 1) * 2];
                uint32_t b1 = vf[nt >> 1][(nt & 1) * 2 + 1];
                mma16h(oacc[nt], ph, b0, b1);
            }
        }

        bool v0 = (nr <= 1024), v1 = (nr8 <= 1024);
        size_t ro0 = ((size_t)b * Nk + nr ) * (Dk/2) + h * (dh/2);
        size_t ro1 = ((size_t)b * Nk + nr8) * (Dk/2) + h * (dh/2);
        #pragma unroll
        for (int nt = 0; nt < 8; nt++) {
            if (v0) Oh[ro0 + nt*4 + c] = h2u(oacc[nt][0] * inv0, oacc[nt][1] * inv0);
            if (v1) Oh[ro1 + nt*4 + c] = h2u(oacc[nt][2] * inv1, oacc[nt][3] * inv1);
        }
    }
}

// ---------------------------------------------------------------------------
// Launch
// ---------------------------------------------------------------------------
extern "C" void kernel_launch(void* const* d_in, const int* in_sizes, int n_in,
                              void* d_out, int out_size) {
    const float* x       = (const float*)d_in[0];
    const float* W_logit = (const float*)d_in[1];
    const float* Wq      = (const float*)d_in[2];
    const float* Wkv     = (const float*)d_in[3];
    const float* Wo      = (const float*)d_in[4];
    const float* bo      = (const float*)d_in[5];
    const float* cw1     = (const float*)d_in[6];
    const float* cb1     = (const float*)d_in[7];
    const float* cw2     = (const float*)d_in[8];
    const float* cb2     = (const float*)d_in[9];
    const float* feats   = (const float*)d_in[10];
    const float* maskp   = (const float*)d_in[11];
    float* out = (float*)d_out;

    float *ctx, *Qb, *KVb, *biasb;
    uint32_t *xh, *ch, *oh, *wqh, *wkvh, *woh;
    cudaGetSymbolAddress((void**)&ctx,   g_ctx);
    cudaGetSymbolAddress((void**)&Qb,    g_Q);
    cudaGetSymbolAddress((void**)&KVb,   g_KV);
    cudaGetSymbolAddress((void**)&biasb, g_bias);
    cudaGetSymbolAddress((void**)&xh,  g_xh);
    cudaGetSymbolAddress((void**)&ch,  g_ch);
    cudaGetSymbolAddress((void**)&oh,  g_oh);
    cudaGetSymbolAddress((void**)&wqh, g_wqh);
    cudaGetSymbolAddress((void**)&wkvh,g_wkvh);
    cudaGetSymbolAddress((void**)&woh, g_woh);

    const int GEMM_SMEM = 2 * STG_B;   // 110592
    cudaFuncSetAttribute(gemm_cp, cudaFuncAttributeMaxDynamicSharedMemorySize, GEMM_SMEM);

    int n4q  = Dk * Dk / 8;
    int n4kv = 2 * Dk * Dk / 8;
    int n4x  = MQ * Dk / 8;
    int n4c  = MKV * Dk / 8;

    cvt_kernel<<<(n4x + 255)/256, 256>>>((const float4*)x, (uint4*)xh, n4x);
    cvt_kernel<<<(n4q + 255)/256, 256>>>((const float4*)Wq, (uint4*)wqh, n4q);
    pool_kernel<<<dim3(Tt + 1, Bk), 256>>>(x, W_logit, ctx);
    gemm_cp<<<dim3(Dk/256, (MQ + 127)/128), 512, GEMM_SMEM>>>(xh, wqh, nullptr, Qb, MQ, Dk, Dk);
    cvt_kernel<<<(n4kv + 255)/256, 256>>>((const float4*)Wkv, (uint4*)wkvh, n4kv);
    cvt_kernel<<<(n4q + 255)/256, 256>>>((const float4*)Wo, (uint4*)woh, n4q);
    cpb_kernel<<<(NKp + 255) / 256, 256>>>(feats, maskp, cw1, cb1, cw2, cb2, biasb);
    cvt_kernel<<<(n4c + 255)/256, 256>>>((const float4*)ctx, (uint4*)ch, n4c);
    gemm_cp<<<dim3((2*Dk)/256, (MKV + 127)/128), 512, GEMM_SMEM>>>(ch, wkvh, nullptr, KVb, MKV, 2*Dk, Dk);

    const size_t ATTN_SMEM = (size_t)(272*SPQ + 64*SPV + 128*SPQ) * sizeof(uint32_t); // 93440
    cudaFuncSetAttribute(attn_mma, cudaFuncAttributeMaxDynamicSharedMemorySize, (int)ATTN_SMEM);
    attn_mma<<<Bk * Hh, 256, ATTN_SMEM>>>(Qb, KVb, biasb, oh);

    gemm_cp<<<dim3(Dk/256, (MQ + 127)/128), 512, GEMM_SMEM>>>(oh, woh, bo, out, MQ, Dk, Dk);
}

// round 12
// speedup vs baseline: 6.0694x; 1.0249x over previous
#include <cuda_runtime.h>
#include <cuda_fp16.h>
#include <cstdint>

// Problem constants
#define Bk   32
#define Nk   1025
#define Dk   768
#define Hh   12
#define dh   64
#define Tt   256
#define Kc   257
#define NKp  (Nk*Kc)
#define MQ   (Bk*Nk)      // 32800
#define MKV  (Bk*Kc)      // 8224

// Scratch (device globals) — fp16 packed operands (uint32 = 2 consecutive k)
__device__ float    g_ctx [MKV*Dk];
__device__ float    g_Q   [MQ*Dk];
__device__ float    g_KV  [MKV*2*Dk];
__device__ float    g_bias[(size_t)Hh*NKp];
__device__ uint32_t g_xh [MQ*Dk/2];
__device__ uint32_t g_ch [MKV*Dk/2];
__device__ uint32_t g_oh [MQ*Dk/2];
__device__ uint32_t g_wqh [Dk*Dk/2];
__device__ uint32_t g_wkvh[Dk*Dk];
__device__ uint32_t g_woh [Dk*Dk/2];

// ---------------------------------------------------------------------------
// helpers
// ---------------------------------------------------------------------------
__device__ __forceinline__ uint32_t h2u(float f0, float f1) {
    __half2 h = __floats2half2_rn(f0, f1);
    return *reinterpret_cast<uint32_t*>(&h);
}
__device__ __forceinline__ void mma16h(float* d, const uint32_t* a, uint32_t b0, uint32_t b1) {
    asm volatile(
        "mma.sync.aligned.m16n8k16.row.col.f32.f16.f16.f32 "
        "{%0,%1,%2,%3}, {%4,%5,%6,%7}, {%8,%9}, {%0,%1,%2,%3};"
        : "+f"(d[0]), "+f"(d[1]), "+f"(d[2]), "+f"(d[3])
        : "r"(a[0]), "r"(a[1]), "r"(a[2]), "r"(a[3]), "r"(b0), "r"(b1));
}
__device__ __forceinline__ void ldsm4(uint32_t* d, uint32_t addr) {
    asm volatile("ldmatrix.sync.aligned.m8n8.x4.shared.b16 {%0,%1,%2,%3}, [%4];"
        : "=r"(d[0]), "=r"(d[1]), "=r"(d[2]), "=r"(d[3]) : "r"(addr));
}
__device__ __forceinline__ uint32_t s2u(const void* p) {
    uint32_t a;
    asm("{ .reg .u64 t; cvta.to.shared.u64 t, %1; cvt.u32.u64 %0, t; }" : "=r"(a) : "l"(p));
    return a;
}
#define CP16(dst, src, sz) \
    asm volatile("cp.async.cg.shared.global [%0], [%1], 16, %2;" \
                 :: "r"(dst), "l"(src), "r"(sz) : "memory")
#define CP_COMMIT() asm volatile("cp.async.commit_group;" ::: "memory")
#define CP_WAIT1()  asm volatile("cp.async.wait_group 1;" ::: "memory")
#define CP_WAIT0()  asm volatile("cp.async.wait_group 0;" ::: "memory")

// ---------------------------------------------------------------------------
// convert fp32 -> packed fp16 (8 elements per thread)
// ---------------------------------------------------------------------------
__global__ void cvt_kernel(const float4* __restrict__ in, uint4* __restrict__ out, int n4) {
    int i = blockIdx.x * 256 + threadIdx.x;
    if (i >= n4) return;
    float4 a = in[2*i], b = in[2*i + 1];
    uint4 H;
    H.x = h2u(a.x, a.y);
    H.y = h2u(a.z, a.w);
    H.z = h2u(b.x, b.y);
    H.w = h2u(b.z, b.w);
    out[i] = H;
}

// ---------------------------------------------------------------------------
// Pooling (unchanged)
// ---------------------------------------------------------------------------
__global__ void pool_kernel(const float* __restrict__ x,
                            const float* __restrict__ wl,
                            float* __restrict__ ctx) {
    int t = blockIdx.x;
    int b = blockIdx.y;
    int tid = threadIdx.x;
    const float* xb = x + (size_t)b * Nk * Dk;
    if (t == Tt) {
        float* dst = ctx + (size_t)b * Kc * Dk;
        for (int dd = tid; dd < Dk; dd += 256) dst[dd] = xb[dd];
        return;
    }
    int gy = t >> 4, gx = t & 15;
    int n0 = 1 + (gy * 2) * 32 + gx * 2;
    int rows[4] = { n0, n0 + 1, n0 + 32, n0 + 33 };

    float p[4] = {0.f, 0.f, 0.f, 0.f};
    for (int dd = tid; dd < Dk; dd += 256) {
        float wv = wl[dd];
        p[0] += xb[(size_t)rows[0]*Dk + dd] * wv;
        p[1] += xb[(size_t)rows[1]*Dk + dd] * wv;
        p[2] += xb[(size_t)rows[2]*Dk + dd] * wv;
        p[3] += xb[(size_t)rows[3]*Dk + dd] * wv;
    }
    __shared__ float wred[4][8];
    __shared__ float sw4[4];
    int lane = tid & 31, w = tid >> 5;
    #pragma unroll
    for (int i = 0; i < 4; i++) {
        float v = p[i];
        #pragma unroll
        for (int off = 16; off; off >>= 1) v += __shfl_xor_sync(0xffffffffu, v, off);
        if (lane == 0) wred[i][w] = v;
    }
    __syncthreads();
    if (tid == 0) {
        float s[4];
        #pragma unroll
        for (int i = 0; i < 4; i++) {
            float a = 0.f;
            for (int ww = 0; ww < 8; ww++) a += wred[i][ww];
            s[i] = a;
        }
        float m = fmaxf(fmaxf(s[0], s[1]), fmaxf(s[2], s[3]));
        float e[4], su = 0.f;
        #pragma unroll
        for (int i = 0; i < 4; i++) { e[i] = expf(s[i] - m); su += e[i]; }
        float inv = 1.f / su;
        #pragma unroll
        for (int i = 0; i < 4; i++) sw4[i] = e[i] * inv;
    }
    __syncthreads();
    float w0 = sw4[0], w1 = sw4[1], w2 = sw4[2], w3 = sw4[3];
    float* dst = ctx + ((size_t)b * Kc + 1 + t) * Dk;
    for (int dd = tid; dd < Dk; dd += 256)
        dst[dd] = w0 * xb[(size_t)rows[0]*Dk + dd] + w1 * xb[(size_t)rows[1]*Dk + dd]
                + w2 * xb[(size_t)rows[2]*Dk + dd] + w3 * xb[(size_t)rows[3]*Dk + dd];
}

// ---------------------------------------------------------------------------
// CPB bias (unchanged)
// ---------------------------------------------------------------------------
__global__ void cpb_kernel(const float* __restrict__ feats, const float* __restrict__ mask,
                           const float* __restrict__ w1, const float* __restrict__ b1,
                           const float* __restrict__ w2, const float* __restrict__ b2,
                           float* __restrict__ bias) {
    __shared__ float sw1[64], sb1[32], sw2[12*32], sb2[12];
    int tid = threadIdx.x;
    if (tid < 64) sw1[tid] = w1[tid];
    if (tid >= 64 && tid < 96) sb1[tid - 64] = b1[tid - 64];
    if (tid >= 96 && tid < 108) sb2[tid - 96] = b2[tid - 96];
    for (int i = tid; i < 384; i += 256) sw2[i] = w2[i];
    __syncthreads();
    int idx = blockIdx.x * 256 + tid;
    if (idx >= NKp) return;
    float f0 = feats[2*idx], f1 = feats[2*idx + 1];
    float m = mask[idx];
    float acc[12];
    #pragma unroll
    for (int h = 0; h < 12; h++) acc[h] = sb2[h];
    #pragma unroll
    for (int j = 0; j < 32; j++) {
        float tt = f0 * sw1[2*j] + f1 * sw1[2*j + 1] + sb1[j];
        float g = 0.5f * tt * (1.0f + erff(tt * 0.7071067811865475f));
        #pragma unroll
        for (int h = 0; h < 12; h++) acc[h] += sw2[h*32 + j] * g;
    }
    #pragma unroll
    for (int h = 0; h < 12; h++) bias[(size_t)h * NKp + idx] = acc[h] * m;
}

// ---------------------------------------------------------------------------
// cp.async double-buffered fp16 GEMM, 2 CTAs/SM.
// Block 128(M) x 128(N), K-chunk 32, 256 threads, 8 warps 2x4, warp 64x32.
// smem stage: A[128][20] B[128][20] (uint32, pad 4) = 20KB; 2 stages = 40KB.
// ---------------------------------------------------------------------------
#define GST   20
#define AB_U32 (128*GST)               // 2560
#define BB_U32 (128*GST)               // 2560
#define STG_U32 (AB_U32 + BB_U32)      // 5120
#define STG_B  (STG_U32*4)             // 20480

__global__ void __launch_bounds__(256, 2)
gemm_cp(const uint32_t* __restrict__ Ah, const uint32_t* __restrict__ Wh,
        const float* __restrict__ bias, float* __restrict__ C,
        int M, int Nn, int Kd) {
    extern __shared__ uint32_t smu[];
    uint32_t sb = s2u(smu);
    int tid = threadIdx.x, warp = tid >> 5, lane = tid & 31;
    int wm = warp & 1, wn = warp >> 1;     // 2 x 4 warp grid
    int r = lane >> 2, c = lane & 3;
    int row0 = blockIdx.y * 128, col0 = blockIdx.x * 128;
    int KPu = Kd >> 1;
    int nchk = Kd / 32;

    // ldmatrix lane addressing
    int la  = lane & 15;                 // A row offset (0..15)
    int lga = (lane >> 4) * 4;           // A col offset (uint32)
    int lb  = (lane & 7) + ((lane >> 4) << 3);   // B row offset
    int lcb = ((lane >> 3) & 1) * 4;     // B col offset (uint32)

    float acc[4][4][4];
    #pragma unroll
    for (int mt = 0; mt < 4; mt++)
        #pragma unroll
        for (int nt = 0; nt < 4; nt++)
            #pragma unroll
            for (int i = 0; i < 4; i++) acc[mt][nt][i] = 0.f;

    auto stage_load = [&](int s, int kcu) {
        uint32_t stb = sb + s * STG_B;
        #pragma unroll
        for (int i = 0; i < 2; i++) {          // A: 128 rows x 4 chunks of 16B
            int cid = i * 256 + tid;
            int row = cid >> 2, kj = cid & 3;
            const uint32_t* sh = Ah + (size_t)(row0 + row) * KPu + kcu + kj * 4;
            uint32_t dst = stb + (row * GST + kj * 4) * 4;
            int sz = (row0 + row < M) ? 16 : 0;
            CP16(dst, sh, sz);
        }
        #pragma unroll
        for (int i = 0; i < 2; i++) {          // B: 128 rows x 4 chunks
            int cid = i * 256 + tid;
            int row = cid >> 2, kj = cid & 3;
            const uint32_t* sh = Wh + (size_t)(col0 + row) * KPu + kcu + kj * 4;
            uint32_t dst = stb + (AB_U32 + row * GST + kj * 4) * 4;
            CP16(dst, sh, 16);
        }
        CP_COMMIT();
    };

    stage_load(0, 0);

    for (int ch = 0; ch < nchk; ch++) {
        if (ch + 1 < nchk) { stage_load((ch + 1) & 1, (ch + 1) * 16); CP_WAIT1(); }
        else               { CP_WAIT0(); }
        __syncthreads();

        uint32_t apb = sb + (ch & 1) * STG_B;
        uint32_t bpb = apb + AB_U32 * 4;

        #pragma unroll
        for (int kk = 0; kk < 2; kk++) {
            int kb = kk * 8;
            uint32_t fah[4][4];
            #pragma unroll
            for (int mt = 0; mt < 4; mt++)
                ldsm4(fah[mt], apb + (((wm*64 + mt*16 + la) * GST) + kb + lga) * 4);
            uint32_t fb[2][4];
            #pragma unroll
            for (int p = 0; p < 2; p++)
                ldsm4(fb[p], bpb + (((wn*32 + p*16 + lb) * GST) + kb + lcb) * 4);
            #pragma unroll
            for (int nt = 0; nt < 4; nt++) {
                uint32_t b0 = fb[nt >> 1][(nt & 1) * 2];
                uint32_t b1 = fb[nt >> 1][(nt & 1) * 2 + 1];
                #pragma unroll
                for (int mt = 0; mt < 4; mt++) mma16h(acc[mt][nt], fah[mt], b0, b1);
            }
        }
        __syncthreads();
    }

    #pragma unroll
    for (int mt = 0; mt < 4; mt++) {
        int rowa = row0 + wm * 64 + mt * 16 + r;
        #pragma unroll
        for (int nt = 0; nt < 4; nt++) {
            int colb = col0 + wn * 32 + nt * 8 + 2 * c;
            float bv0 = bias ? bias[colb]     : 0.f;
            float bv1 = bias ? bias[colb + 1] : 0.f;
            if (rowa < M) {
                float2 v = make_float2(acc[mt][nt][0] + bv0, acc[mt][nt][1] + bv1);
                *(float2*)&C[(size_t)rowa * Nn + colb] = v;
            }
            if (rowa + 8 < M) {
                float2 v = make_float2(acc[mt][nt][2] + bv0, acc[mt][nt][3] + bv1);
                *(float2*)&C[(size_t)(rowa + 8) * Nn + colb] = v;
            }
        }
    }
}

// ---------------------------------------------------------------------------
// fp16 tensor-core attention with ldmatrix fragment loads (unchanged from R11)
// ---------------------------------------------------------------------------
#define SPQ 36
#define SPV 140

__global__ void __launch_bounds__(256)
attn_mma(const float* __restrict__ Q, const float* __restrict__ KV,
         const float* __restrict__ biasb, uint32_t* __restrict__ Oh) {
    extern __shared__ uint32_t sm4[];
    uint32_t* Kh = sm4;                  // [272][36]
    uint32_t* Vh = Kh + 272 * SPQ;       // [64][140]
    uint32_t* Qh = Vh + 64 * SPV;        // [128][36]
    __half* Khb = (__half*)Kh;
    __half* Vhb = (__half*)Vh;
    __half* Qhb = (__half*)Qh;

    int bh = blockIdx.x;
    int b = bh / Hh, h = bh - b * Hh;
    int tid = threadIdx.x, wr = tid >> 5, lane = tid & 31;
    int r = lane >> 2, c = lane & 3;

    // ldmatrix lane addressing
    int la  = lane & 15;
    int lga = (lane >> 4) * 4;
    int lb  = (lane & 7) + ((lane >> 4) << 3);
    int lcb = ((lane >> 3) & 1) * 4;

    uint32_t kba = s2u(Kh), vba = s2u(Vh), qba = s2u(Qh);

    const float* kv = KV + (size_t)b * Kc * (2*Dk) + h * dh;
    for (int i = tid; i < 272 * 64; i += 256) {
        int kpos = i >> 6, d = i & 63;
        float fk = 0.f, fv = 0.f;
        if (kpos < Kc) {
            const float* p = kv + (size_t)kpos * (2*Dk) + d;
            fk = p[0]; fv = p[Dk];
        }
        Khb[kpos * 72 + d]  = __float2half_rn(fk);
        Vhb[d * 280 + kpos] = __float2half_rn(fv);
    }

    #pragma unroll 1
    for (int bx = 0; bx < 9; bx++) {
        int n0 = bx * 128;
        __syncthreads();
        for (int i = tid; i < 128 * 64; i += 256) {
            int rl = i >> 6, d = i & 63;
            int n = n0 + rl; if (n > 1024) n = 1024;
            float f = Q[((size_t)b * Nk + n) * Dk + h * dh + d];
            Qhb[rl * 72 + d] = __float2half_rn(f);
        }
        __syncthreads();

        int m0 = wr * 16;
        uint32_t qfh[4][4];
        #pragma unroll
        for (int kt = 0; kt < 4; kt++)
            ldsm4(qfh[kt], qba + ((m0 + la) * SPQ + kt*8 + lga) * 4);

        float lg[33][4];
        #pragma unroll
        for (int nt = 0; nt < 33; nt++)
            #pragma unroll
            for (int i = 0; i < 4; i++) lg[nt][i] = 0.f;

        #pragma unroll
        for (int gq = 0; gq < 8; gq++) {
            #pragma unroll
            for (int kt = 0; kt < 4; kt++) {
                uint32_t kf[2][4];
                #pragma unroll
                for (int p = 0; p < 2; p++)
                    ldsm4(kf[p], kba + (((gq*4 + p*2)*8 + lb) * SPQ + kt*8 + lcb) * 4);
                #pragma unroll
                for (int x = 0; x < 4; x++) {
                    uint32_t b0 = kf[x >> 1][(x & 1) * 2];
                    uint32_t b1 = kf[x >> 1][(x & 1) * 2 + 1];
                    mma16h(lg[gq*4 + x], qfh[kt], b0, b1);
                }
            }
        }
        #pragma unroll
        for (int kt = 0; kt < 4; kt++) {
            int kr = (32*8 + r) * SPQ + kt*8 + c;
            mma16h(lg[32], qfh[kt], Kh[kr], Kh[kr + 4]);
        }

        int nr  = n0 + m0 + r;
        int nr8 = nr + 8;
        const float* bp0 = biasb + ((size_t)h * Nk + (nr  > 1024 ? 1024 : nr )) * Kc;
        const float* bp1 = biasb + ((size_t)h * Nk + (nr8 > 1024 ? 1024 : nr8)) * Kc;
        #pragma unroll
        for (int nt = 0; nt < 33; nt++) {
            int k0 = nt*8 + 2*c, k1 = k0 + 1;
            lg[nt][0] = (k0 < Kc) ? lg[nt][0] * 0.125f + bp0[k0] : -1e30f;
            lg[nt][1] = (k1 < Kc) ? lg[nt][1] * 0.125f + bp0[k1] : -1e30f;
            lg[nt][2] = (k0 < Kc) ? lg[nt][2] * 0.125f + bp1[k0] : -1e30f;
            lg[nt][3] = (k1 < Kc) ? lg[nt][3] * 0.125f + bp1[k1] : -1e30f;
        }

        float mx0 = -1e30f, mx1 = -1e30f;
        #pragma unroll
        for (int nt = 0; nt < 33; nt++) {
            mx0 = fmaxf(mx0, fmaxf(lg[nt][0], lg[nt][1]));
            mx1 = fmaxf(mx1, fmaxf(lg[nt][2], lg[nt][3]));
        }
        mx0 = fmaxf(mx0, __shfl_xor_sync(0xffffffffu, mx0, 1));
        mx0 = fmaxf(mx0, __shfl_xor_sync(0xffffffffu, mx0, 2));
        mx1 = fmaxf(mx1, __shfl_xor_sync(0xffffffffu, mx1, 1));
        mx1 = fmaxf(mx1, __shfl_xor_sync(0xffffffffu, mx1, 2));
        float s0 = 0.f, s1 = 0.f;
        #pragma unroll
        for (int nt = 0; nt < 33; nt++) {
            lg[nt][0] = __expf(lg[nt][0] - mx0); s0 += lg[nt][0];
            lg[nt][1] = __expf(lg[nt][1] - mx0); s0 += lg[nt][1];
            lg[nt][2] = __expf(lg[nt][2] - mx1); s1 += lg[nt][2];
            lg[nt][3] = __expf(lg[nt][3] - mx1); s1 += lg[nt][3];
        }
        s0 += __shfl_xor_sync(0xffffffffu, s0, 1);
        s0 += __shfl_xor_sync(0xffffffffu, s0, 2);
        s1 += __shfl_xor_sync(0xffffffffu, s1, 1);
        s1 += __shfl_xor_sync(0xffffffffu, s1, 2);
        float inv0 = 1.f / s0, inv1 = 1.f / s1;

        float oacc[8][4];
        #pragma unroll
        for (int nt = 0; nt < 8; nt++)
            #pragma unroll
            for (int i = 0; i < 4; i++) oacc[nt][i] = 0.f;

        #pragma unroll
        for (int kt2 = 0; kt2 < 17; kt2++) {
            uint32_t ph[4];
            int e0 = 2*kt2, e1 = 2*kt2 + 1;
            ph[0] = h2u(lg[e0][0], lg[e0][1]);
            ph[1] = h2u(lg[e0][2], lg[e0][3]);
            if (e1 < 33) {
                ph[2] = h2u(lg[e1][0], lg[e1][1]);
                ph[3] = h2u(lg[e1][2], lg[e1][3]);
            } else {
                ph[2] = ph[3] = 0u;
            }
            uint32_t vf[4][4];
            #pragma unroll
            for (int p = 0; p < 4; p++)
                ldsm4(vf[p], vba + ((p*16 + lb) * SPV + kt2*8 + lcb) * 4);
            #pragma unroll
            for (int nt = 0; nt < 8; nt++) {
                uint32_t b0 = vf[nt >> 1][(nt & 1) * 2];
                uint32_t b1 = vf[nt >> 1][(nt & 1) * 2 + 1];
                mma16h(oacc[nt], ph, b0, b1);
            }
        }

        bool v0 = (nr <= 1024), v1 = (nr8 <= 1024);
        size_t ro0 = ((size_t)b * Nk + nr ) * (Dk/2) + h * (dh/2);
        size_t ro1 = ((size_t)b * Nk + nr8) * (Dk/2) + h * (dh/2);
        #pragma unroll
        for (int nt = 0; nt < 8; nt++) {
            if (v0) Oh[ro0 + nt*4 + c] = h2u(oacc[nt][0] * inv0, oacc[nt][1] * inv0);
            if (v1) Oh[ro1 + nt*4 + c] = h2u(oacc[nt][2] * inv1, oacc[nt][3] * inv1);
        }
    }
}

// ---------------------------------------------------------------------------
// Launch
// ---------------------------------------------------------------------------
extern "C" void kernel_launch(void* const* d_in, const int* in_sizes, int n_in,
                              void* d_out, int out_size) {
    const float* x       = (const float*)d_in[0];
    const float* W_logit = (const float*)d_in[1];
    const float* Wq      = (const float*)d_in[2];
    const float* Wkv     = (const float*)d_in[3];
    const float* Wo      = (const float*)d_in[4];
    const float* bo      = (const float*)d_in[5];
    const float* cw1     = (const float*)d_in[6];
    const float* cb1     = (const float*)d_in[7];
    const float* cw2     = (const float*)d_in[8];
    const float* cb2     = (const float*)d_in[9];
    const float* feats   = (const float*)d_in[10];
    const float* maskp   = (const float*)d_in[11];
    float* out = (float*)d_out;

    float *ctx, *Qb, *KVb, *biasb;
    uint32_t *xh, *ch, *oh, *wqh, *wkvh, *woh;
    cudaGetSymbolAddress((void**)&ctx,   g_ctx);
    cudaGetSymbolAddress((void**)&Qb,    g_Q);
    cudaGetSymbolAddress((void**)&KVb,   g_KV);
    cudaGetSymbolAddress((void**)&biasb, g_bias);
    cudaGetSymbolAddress((void**)&xh,  g_xh);
    cudaGetSymbolAddress((void**)&ch,  g_ch);
    cudaGetSymbolAddress((void**)&oh,  g_oh);
    cudaGetSymbolAddress((void**)&wqh, g_wqh);
    cudaGetSymbolAddress((void**)&wkvh,g_wkvh);
    cudaGetSymbolAddress((void**)&woh, g_woh);

    const int GEMM_SMEM = 2 * STG_B;   // 40960
    cudaFuncSetAttribute(gemm_cp, cudaFuncAttributeMaxDynamicSharedMemorySize, GEMM_SMEM);

    int n4q  = Dk * Dk / 8;
    int n4kv = 2 * Dk * Dk / 8;
    int n4x  = MQ * Dk / 8;
    int n4c  = MKV * Dk / 8;

    cvt_kernel<<<(n4x + 255)/256, 256>>>((const float4*)x, (uint4*)xh, n4x);
    cvt_kernel<<<(n4q + 255)/256, 256>>>((const float4*)Wq, (uint4*)wqh, n4q);
    pool_kernel<<<dim3(Tt + 1, Bk), 256>>>(x, W_logit, ctx);
    gemm_cp<<<dim3(Dk/128, (MQ + 127)/128), 256, GEMM_SMEM>>>(xh, wqh, nullptr, Qb, MQ, Dk, Dk);
    cvt_kernel<<<(n4kv + 255)/256, 256>>>((const float4*)Wkv, (uint4*)wkvh, n4kv);
    cvt_kernel<<<(n4q + 255)/256, 256>>>((const float4*)Wo, (uint4*)woh, n4q);
    cpb_kernel<<<(NKp + 255) / 256, 256>>>(feats, maskp, cw1, cb1, cw2, cb2, biasb);
    cvt_kernel<<<(n4c + 255)/256, 256>>>((const float4*)ctx, (uint4*)ch, n4c);
    gemm_cp<<<dim3((2*Dk)/128, (MKV + 127)/128), 256, GEMM_SMEM>>>(ch, wkvh, nullptr, KVb, MKV, 2*Dk, Dk);

    const size_t ATTN_SMEM = (size_t)(272*SPQ + 64*SPV + 128*SPQ) * sizeof(uint32_t); // 93440
    cudaFuncSetAttribute(attn_mma, cudaFuncAttributeMaxDynamicSharedMemorySize, (int)ATTN_SMEM);
    attn_mma<<<Bk * Hh, 256, ATTN_SMEM>>>(Qb, KVb, biasb, oh);

    gemm_cp<<<dim3(Dk/128, (MQ + 127)/128), 256, GEMM_SMEM>>>(oh, woh, bo, out, MQ, Dk, Dk);
}

// round 13
// speedup vs baseline: 6.6898x; 1.1022x over previous
#include <cuda_runtime.h>
#include <cuda_fp16.h>
#include <cstdint>

// Problem constants
#define Bk   32
#define Nk   1025
#define Dk   768
#define Hh   12
#define dh   64
#define Tt   256
#define Kc   257
#define NKp  (Nk*Kc)
#define MQ   (Bk*Nk)      // 32800
#define MKV  (Bk*Kc)      // 8224

// Scratch (device globals) — fp16 packed operands (uint32 = 2 consecutive elems)
__device__ float    g_bias[(size_t)Hh*NKp];
__device__ uint32_t g_xh  [MQ*Dk/2];
__device__ uint32_t g_ch  [MKV*Dk/2];     // pooled context, fp16 packed
__device__ uint32_t g_q16 [MQ*Dk/2];      // Q projection, fp16 packed
__device__ uint32_t g_kv16[MKV*Dk];       // KV projection, fp16 packed (2*Dk halves/row)
__device__ uint32_t g_oh  [MQ*Dk/2];      // attention output, fp16 packed
__device__ uint32_t g_wqh [Dk*Dk/2];
__device__ uint32_t g_wkvh[Dk*Dk];
__device__ uint32_t g_woh [Dk*Dk/2];

// ---------------------------------------------------------------------------
// helpers
// ---------------------------------------------------------------------------
__device__ __forceinline__ uint32_t h2u(float f0, float f1) {
    __half2 h = __floats2half2_rn(f0, f1);
    return *reinterpret_cast<uint32_t*>(&h);
}
__device__ __forceinline__ void mma16h(float* d, const uint32_t* a, uint32_t b0, uint32_t b1) {
    asm volatile(
        "mma.sync.aligned.m16n8k16.row.col.f32.f16.f16.f32 "
        "{%0,%1,%2,%3}, {%4,%5,%6,%7}, {%8,%9}, {%0,%1,%2,%3};"
        : "+f"(d[0]), "+f"(d[1]), "+f"(d[2]), "+f"(d[3])
        : "r"(a[0]), "r"(a[1]), "r"(a[2]), "r"(a[3]), "r"(b0), "r"(b1));
}
__device__ __forceinline__ void ldsm4(uint32_t* d, uint32_t addr) {
    asm volatile("ldmatrix.sync.aligned.m8n8.x4.shared.b16 {%0,%1,%2,%3}, [%4];"
        : "=r"(d[0]), "=r"(d[1]), "=r"(d[2]), "=r"(d[3]) : "r"(addr));
}
__device__ __forceinline__ uint32_t s2u(const void* p) {
    uint32_t a;
    asm("{ .reg .u64 t; cvta.to.shared.u64 t, %1; cvt.u32.u64 %0, t; }" : "=r"(a) : "l"(p));
    return a;
}
#define CP16(dst, src, sz) \
    asm volatile("cp.async.cg.shared.global [%0], [%1], 16, %2;" \
                 :: "r"(dst), "l"(src), "r"(sz) : "memory")
#define CP_COMMIT() asm volatile("cp.async.commit_group;" ::: "memory")
#define CP_WAIT1()  asm volatile("cp.async.wait_group 1;" ::: "memory")
#define CP_WAIT0()  asm volatile("cp.async.wait_group 0;" ::: "memory")

// ---------------------------------------------------------------------------
// convert fp32 -> packed fp16 (8 elements per thread)
// ---------------------------------------------------------------------------
__global__ void cvt_kernel(const float4* __restrict__ in, uint4* __restrict__ out, int n4) {
    int i = blockIdx.x * 256 + threadIdx.x;
    if (i >= n4) return;
    float4 a = in[2*i], b = in[2*i + 1];
    uint4 H;
    H.x = h2u(a.x, a.y);
    H.y = h2u(a.z, a.w);
    H.z = h2u(b.x, b.y);
    H.w = h2u(b.z, b.w);
    out[i] = H;
}

// ---------------------------------------------------------------------------
// Pooling — writes packed fp16 ctx directly
// ---------------------------------------------------------------------------
__global__ void pool_kernel(const float* __restrict__ x,
                            const float* __restrict__ wl,
                            uint32_t* __restrict__ ctx16) {
    int t = blockIdx.x;
    int b = blockIdx.y;
    int tid = threadIdx.x;
    const float* xb = x + (size_t)b * Nk * Dk;
    if (t == Tt) {
        uint32_t* dst = ctx16 + (size_t)b * Kc * (Dk/2);
        for (int dp = tid; dp < Dk/2; dp += 256)
            dst[dp] = h2u(xb[2*dp], xb[2*dp + 1]);
        return;
    }
    int gy = t >> 4, gx = t & 15;
    int n0 = 1 + (gy * 2) * 32 + gx * 2;
    int rows[4] = { n0, n0 + 1, n0 + 32, n0 + 33 };

    float p[4] = {0.f, 0.f, 0.f, 0.f};
    for (int dd = tid; dd < Dk; dd += 256) {
        float wv = wl[dd];
        p[0] += xb[(size_t)rows[0]*Dk + dd] * wv;
        p[1] += xb[(size_t)rows[1]*Dk + dd] * wv;
        p[2] += xb[(size_t)rows[2]*Dk + dd] * wv;
        p[3] += xb[(size_t)rows[3]*Dk + dd] * wv;
    }
    __shared__ float wred[4][8];
    __shared__ float sw4[4];
    int lane = tid & 31, w = tid >> 5;
    #pragma unroll
    for (int i = 0; i < 4; i++) {
        float v = p[i];
        #pragma unroll
        for (int off = 16; off; off >>= 1) v += __shfl_xor_sync(0xffffffffu, v, off);
        if (lane == 0) wred[i][w] = v;
    }
    __syncthreads();
    if (tid == 0) {
        float s[4];
        #pragma unroll
        for (int i = 0; i < 4; i++) {
            float a = 0.f;
            for (int ww = 0; ww < 8; ww++) a += wred[i][ww];
            s[i] = a;
        }
        float m = fmaxf(fmaxf(s[0], s[1]), fmaxf(s[2], s[3]));
        float e[4], su = 0.f;
        #pragma unroll
        for (int i = 0; i < 4; i++) { e[i] = expf(s[i] - m); su += e[i]; }
        float inv = 1.f / su;
        #pragma unroll
        for (int i = 0; i < 4; i++) sw4[i] = e[i] * inv;
    }
    __syncthreads();
    float w0 = sw4[0], w1 = sw4[1], w2 = sw4[2], w3 = sw4[3];
    uint32_t* dst = ctx16 + ((size_t)b * Kc + 1 + t) * (Dk/2);
    const float* r0 = xb + (size_t)rows[0]*Dk;
    const float* r1 = xb + (size_t)rows[1]*Dk;
    const float* r2 = xb + (size_t)rows[2]*Dk;
    const float* r3 = xb + (size_t)rows[3]*Dk;
    for (int dp = tid; dp < Dk/2; dp += 256) {
        int d0 = 2*dp, d1 = d0 + 1;
        float v0 = w0*r0[d0] + w1*r1[d0] + w2*r2[d0] + w3*r3[d0];
        float v1 = w0*r0[d1] + w1*r1[d1] + w2*r2[d1] + w3*r3[d1];
        dst[dp] = h2u(v0, v1);
    }
}

// ---------------------------------------------------------------------------
// CPB bias (unchanged)
// ---------------------------------------------------------------------------
__global__ void cpb_kernel(const float* __restrict__ feats, const float* __restrict__ mask,
                           const float* __restrict__ w1, const float* __restrict__ b1,
                           const float* __restrict__ w2, const float* __restrict__ b2,
                           float* __restrict__ bias) {
    __shared__ float sw1[64], sb1[32], sw2[12*32], sb2[12];
    int tid = threadIdx.x;
    if (tid < 64) sw1[tid] = w1[tid];
    if (tid >= 64 && tid < 96) sb1[tid - 64] = b1[tid - 64];
    if (tid >= 96 && tid < 108) sb2[tid - 96] = b2[tid - 96];
    for (int i = tid; i < 384; i += 256) sw2[i] = w2[i];
    __syncthreads();
    int idx = blockIdx.x * 256 + tid;
    if (idx >= NKp) return;
    float f0 = feats[2*idx], f1 = feats[2*idx + 1];
    float m = mask[idx];
    float acc[12];
    #pragma unroll
    for (int h = 0; h < 12; h++) acc[h] = sb2[h];
    #pragma unroll
    for (int j = 0; j < 32; j++) {
        float tt = f0 * sw1[2*j] + f1 * sw1[2*j + 1] + sb1[j];
        float g = 0.5f * tt * (1.0f + erff(tt * 0.7071067811865475f));
        #pragma unroll
        for (int h = 0; h < 12; h++) acc[h] += sw2[h*32 + j] * g;
    }
    #pragma unroll
    for (int h = 0; h < 12; h++) bias[(size_t)h * NKp + idx] = acc[h] * m;
}

// ---------------------------------------------------------------------------
// cp.async double-buffered fp16 GEMM, 2 CTAs/SM, ldmatrix fragments.
// Block 128x128, K-chunk 32, 256 threads, 8 warps 2x4, warp 64x32.
// Output: fp32 (+bias) if C16==null, else packed fp16.
// ---------------------------------------------------------------------------
#define GST   20
#define AB_U32 (128*GST)               // 2560
#define BB_U32 (128*GST)               // 2560
#define STG_U32 (AB_U32 + BB_U32)      // 5120
#define STG_B  (STG_U32*4)             // 20480

__global__ void __launch_bounds__(256, 2)
gemm_cp(const uint32_t* __restrict__ Ah, const uint32_t* __restrict__ Wh,
        const float* __restrict__ bias, float* __restrict__ C,
        uint32_t* __restrict__ C16,
        int M, int Nn, int Kd) {
    extern __shared__ uint32_t smu[];
    uint32_t sb = s2u(smu);
    int tid = threadIdx.x, warp = tid >> 5, lane = tid & 31;
    int wm = warp & 1, wn = warp >> 1;     // 2 x 4 warp grid
    int r = lane >> 2, c = lane & 3;
    int row0 = blockIdx.y * 128, col0 = blockIdx.x * 128;
    int KPu = Kd >> 1;
    int nchk = Kd / 32;

    int la  = lane & 15;
    int lga = (lane >> 4) * 4;
    int lb  = (lane & 7) + ((lane >> 4) << 3);
    int lcb = ((lane >> 3) & 1) * 4;

    float acc[4][4][4];
    #pragma unroll
    for (int mt = 0; mt < 4; mt++)
        #pragma unroll
        for (int nt = 0; nt < 4; nt++)
            #pragma unroll
            for (int i = 0; i < 4; i++) acc[mt][nt][i] = 0.f;

    auto stage_load = [&](int s, int kcu) {
        uint32_t stb = sb + s * STG_B;
        #pragma unroll
        for (int i = 0; i < 2; i++) {
            int cid = i * 256 + tid;
            int row = cid >> 2, kj = cid & 3;
            const uint32_t* sh = Ah + (size_t)(row0 + row) * KPu + kcu + kj * 4;
            uint32_t dst = stb + (row * GST + kj * 4) * 4;
            int sz = (row0 + row < M) ? 16 : 0;
            CP16(dst, sh, sz);
        }
        #pragma unroll
        for (int i = 0; i < 2; i++) {
            int cid = i * 256 + tid;
            int row = cid >> 2, kj = cid & 3;
            const uint32_t* sh = Wh + (size_t)(col0 + row) * KPu + kcu + kj * 4;
            uint32_t dst = stb + (AB_U32 + row * GST + kj * 4) * 4;
            CP16(dst, sh, 16);
        }
        CP_COMMIT();
    };

    stage_load(0, 0);

    for (int ch = 0; ch < nchk; ch++) {
        if (ch + 1 < nchk) { stage_load((ch + 1) & 1, (ch + 1) * 16); CP_WAIT1(); }
        else               { CP_WAIT0(); }
        __syncthreads();

        uint32_t apb = sb + (ch & 1) * STG_B;
        uint32_t bpb = apb + AB_U32 * 4;

        #pragma unroll
        for (int kk = 0; kk < 2; kk++) {
            int kb = kk * 8;
            uint32_t fah[4][4];
            #pragma unroll
            for (int mt = 0; mt < 4; mt++)
                ldsm4(fah[mt], apb + (((wm*64 + mt*16 + la) * GST) + kb + lga) * 4);
            uint32_t fb[2][4];
            #pragma unroll
            for (int p = 0; p < 2; p++)
                ldsm4(fb[p], bpb + (((wn*32 + p*16 + lb) * GST) + kb + lcb) * 4);
            #pragma unroll
            for (int nt = 0; nt < 4; nt++) {
                uint32_t b0 = fb[nt >> 1][(nt & 1) * 2];
                uint32_t b1 = fb[nt >> 1][(nt & 1) * 2 + 1];
                #pragma unroll
                for (int mt = 0; mt < 4; mt++) mma16h(acc[mt][nt], fah[mt], b0, b1);
            }
        }
        __syncthreads();
    }

    if (C16) {
        int Nh = Nn >> 1;
        #pragma unroll
        for (int mt = 0; mt < 4; mt++) {
            int rowa = row0 + wm * 64 + mt * 16 + r;
            #pragma unroll
            for (int nt = 0; nt < 4; nt++) {
                int cp = (col0 >> 1) + wn * 16 + nt * 4 + c;
                if (rowa < M)
                    C16[(size_t)rowa * Nh + cp] = h2u(acc[mt][nt][0], acc[mt][nt][1]);
                if (rowa + 8 < M)
                    C16[(size_t)(rowa + 8) * Nh + cp] = h2u(acc[mt][nt][2], acc[mt][nt][3]);
            }
        }
    } else {
        #pragma unroll
        for (int mt = 0; mt < 4; mt++) {
            int rowa = row0 + wm * 64 + mt * 16 + r;
            #pragma unroll
            for (int nt = 0; nt < 4; nt++) {
                int colb = col0 + wn * 32 + nt * 8 + 2 * c;
                float bv0 = bias ? bias[colb]     : 0.f;
                float bv1 = bias ? bias[colb + 1] : 0.f;
                if (rowa < M) {
                    float2 v = make_float2(acc[mt][nt][0] + bv0, acc[mt][nt][1] + bv1);
                    *(float2*)&C[(size_t)rowa * Nn + colb] = v;
                }
                if (rowa + 8 < M) {
                    float2 v = make_float2(acc[mt][nt][2] + bv0, acc[mt][nt][3] + bv1);
                    *(float2*)&C[(size_t)(rowa + 8) * Nn + colb] = v;
                }
            }
        }
    }
}

// ---------------------------------------------------------------------------
// fp16 tensor-core attention; Q/KV inputs are packed fp16.
// ---------------------------------------------------------------------------
#define SPQ 36
#define SPV 140

__global__ void __launch_bounds__(256)
attn_mma(const uint32_t* __restrict__ Q16, const uint32_t* __restrict__ KV16,
         const float* __restrict__ biasb, uint32_t* __restrict__ Oh) {
    extern __shared__ uint32_t sm4[];
    uint32_t* Kh = sm4;                  // [272][36]
    uint32_t* Vh = Kh + 272 * SPQ;       // [64][140]
    uint32_t* Qh = Vh + 64 * SPV;        // [128][36]
    __half* Vhb = (__half*)Vh;

    int bh = blockIdx.x;
    int b = bh / Hh, h = bh - b * Hh;
    int tid = threadIdx.x, wr = tid >> 5, lane = tid & 31;
    int r = lane >> 2, c = lane & 3;

    int la  = lane & 15;
    int lga = (lane >> 4) * 4;
    int lb  = (lane & 7) + ((lane >> 4) << 3);
    int lcb = ((lane >> 3) & 1) * 4;

    uint32_t kba = s2u(Kh), vba = s2u(Vh), qba = s2u(Qh);

    // KV16 row = Dk uint32 (k halves [0,384), v halves [384,768)); head offset h*32
    const uint32_t* kvb = KV16 + (size_t)b * Kc * Dk + h * 32;
    for (int i = tid; i < 272 * 32; i += 256) {
        int kpos = i >> 5, dp = i & 31;
        uint32_t uk = 0u, uv = 0u;
        if (kpos < Kc) {
            const uint32_t* p = kvb + (size_t)kpos * Dk;
            uk = p[dp];
            uv = p[384 + dp];
        }
        Kh[kpos * SPQ + dp] = uk;
        __half2 hv = *reinterpret_cast<__half2*>(&uv);
        Vhb[(2*dp)   * 280 + kpos] = __low2half(hv);
        Vhb[(2*dp+1) * 280 + kpos] = __high2half(hv);
    }

    #pragma unroll 1
    for (int bx = 0; bx < 9; bx++) {
        int n0 = bx * 128;
        __syncthreads();
        for (int i = tid; i < 128 * 32; i += 256) {
            int rl = i >> 5, dp = i & 31;
            int n = n0 + rl; if (n > 1024) n = 1024;
            Qh[rl * SPQ + dp] = Q16[((size_t)b * Nk + n) * 384 + h * 32 + dp];
        }
        __syncthreads();

        int m0 = wr * 16;
        uint32_t qfh[4][4];
        #pragma unroll
        for (int kt = 0; kt < 4; kt++)
            ldsm4(qfh[kt], qba + ((m0 + la) * SPQ + kt*8 + lga) * 4);

        float lg[33][4];
        #pragma unroll
        for (int nt = 0; nt < 33; nt++)
            #pragma unroll
            for (int i = 0; i < 4; i++) lg[nt][i] = 0.f;

        #pragma unroll
        for (int gq = 0; gq < 8; gq++) {
            #pragma unroll
            for (int kt = 0; kt < 4; kt++) {
                uint32_t kf[2][4];
                #pragma unroll
                for (int p = 0; p < 2; p++)
                    ldsm4(kf[p], kba + (((gq*4 + p*2)*8 + lb) * SPQ + kt*8 + lcb) * 4);
                #pragma unroll
                for (int x = 0; x < 4; x++) {
                    uint32_t b0 = kf[x >> 1][(x & 1) * 2];
                    uint32_t b1 = kf[x >> 1][(x & 1) * 2 + 1];
                    mma16h(lg[gq*4 + x], qfh[kt], b0, b1);
                }
            }
        }
        #pragma unroll
        for (int kt = 0; kt < 4; kt++) {
            int kr = (32*8 + r) * SPQ + kt*8 + c;
            mma16h(lg[32], qfh[kt], Kh[kr], Kh[kr + 4]);
        }

        int nr  = n0 + m0 + r;
        int nr8 = nr + 8;
        const float* bp0 = biasb + ((size_t)h * Nk + (nr  > 1024 ? 1024 : nr )) * Kc;
        const float* bp1 = biasb + ((size_t)h * Nk + (nr8 > 1024 ? 1024 : nr8)) * Kc;
        #pragma unroll
        for (int nt = 0; nt < 33; nt++) {
            int k0 = nt*8 + 2*c, k1 = k0 + 1;
            lg[nt][0] = (k0 < Kc) ? lg[nt][0] * 0.125f + bp0[k0] : -1e30f;
            lg[nt][1] = (k1 < Kc) ? lg[nt][1] * 0.125f + bp0[k1] : -1e30f;
            lg[nt][2] = (k0 < Kc) ? lg[nt][2] * 0.125f + bp1[k0] : -1e30f;
            lg[nt][3] = (k1 < Kc) ? lg[nt][3] * 0.125f + bp1[k1] : -1e30f;
        }

        float mx0 = -1e30f, mx1 = -1e30f;
        #pragma unroll
        for (int nt = 0; nt < 33; nt++) {
            mx0 = fmaxf(mx0, fmaxf(lg[nt][0], lg[nt][1]));
            mx1 = fmaxf(mx1, fmaxf(lg[nt][2], lg[nt][3]));
        }
        mx0 = fmaxf(mx0, __shfl_xor_sync(0xffffffffu, mx0, 1));
        mx0 = fmaxf(mx0, __shfl_xor_sync(0xffffffffu, mx0, 2));
        mx1 = fmaxf(mx1, __shfl_xor_sync(0xffffffffu, mx1, 1));
        mx1 = fmaxf(mx1, __shfl_xor_sync(0xffffffffu, mx1, 2));
        float s0 = 0.f, s1 = 0.f;
        #pragma unroll
        for (int nt = 0; nt < 33; nt++) {
            lg[nt][0] = __expf(lg[nt][0] - mx0); s0 += lg[nt][0];
            lg[nt][1] = __expf(lg[nt][1] - mx0); s0 += lg[nt][1];
            lg[nt][2] = __expf(lg[nt][2] - mx1); s1 += lg[nt][2];
            lg[nt][3] = __expf(lg[nt][3] - mx1); s1 += lg[nt][3];
        }
        s0 += __shfl_xor_sync(0xffffffffu, s0, 1);
        s0 += __shfl_xor_sync(0xffffffffu, s0, 2);
        s1 += __shfl_xor_sync(0xffffffffu, s1, 1);
        s1 += __shfl_xor_sync(0xffffffffu, s1, 2);
        float inv0 = 1.f / s0, inv1 = 1.f / s1;

        float oacc[8][4];
        #pragma unroll
        for (int nt = 0; nt < 8; nt++)
            #pragma unroll
            for (int i = 0; i < 4; i++) oacc[nt][i] = 0.f;

        #pragma unroll
        for (int kt2 = 0; kt2 < 17; kt2++) {
            uint32_t ph[4];
            int e0 = 2*kt2, e1 = 2*kt2 + 1;
            ph[0] = h2u(lg[e0][0], lg[e0][1]);
            ph[1] = h2u(lg[e0][2], lg[e0][3]);
            if (e1 < 33) {
                ph[2] = h2u(lg[e1][0], lg[e1][1]);
                ph[3] = h2u(lg[e1][2], lg[e1][3]);
            } else {
                ph[2] = ph[3] = 0u;
            }
            uint32_t vf[4][4];
            #pragma unroll
            for (int p = 0; p < 4; p++)
                ldsm4(vf[p], vba + ((p*16 + lb) * SPV + kt2*8 + lcb) * 4);
            #pragma unroll
            for (int nt = 0; nt < 8; nt++) {
                uint32_t b0 = vf[nt >> 1][(nt & 1) * 2];
                uint32_t b1 = vf[nt >> 1][(nt & 1) * 2 + 1];
                mma16h(oacc[nt], ph, b0, b1);
            }
        }

        bool v0 = (nr <= 1024), v1 = (nr8 <= 1024);
        size_t ro0 = ((size_t)b * Nk + nr ) * (Dk/2) + h * (dh/2);
        size_t ro1 = ((size_t)b * Nk + nr8) * (Dk/2) + h * (dh/2);
        #pragma unroll
        for (int nt = 0; nt < 8; nt++) {
            if (v0) Oh[ro0 + nt*4 + c] = h2u(oacc[nt][0] * inv0, oacc[nt][1] * inv0);
            if (v1) Oh[ro1 + nt*4 + c] = h2u(oacc[nt][2] * inv1, oacc[nt][3] * inv1);
        }
    }
}

// ---------------------------------------------------------------------------
// Launch
// ---------------------------------------------------------------------------
extern "C" void kernel_launch(void* const* d_in, const int* in_sizes, int n_in,
                              void* d_out, int out_size) {
    const float* x       = (const float*)d_in[0];
    const float* W_logit = (const float*)d_in[1];
    const float* Wq      = (const float*)d_in[2];
    const float* Wkv     = (const float*)d_in[3];
    const float* Wo      = (const float*)d_in[4];
    const float* bo      = (const float*)d_in[5];
    const float* cw1     = (const float*)d_in[6];
    const float* cb1     = (const float*)d_in[7];
    const float* cw2     = (const float*)d_in[8];
    const float* cb2     = (const float*)d_in[9];
    const float* feats   = (const float*)d_in[10];
    const float* maskp   = (const float*)d_in[11];
    float* out = (float*)d_out;

    float *biasb;
    uint32_t *xh, *ch, *q16, *kv16, *oh, *wqh, *wkvh, *woh;
    cudaGetSymbolAddress((void**)&biasb, g_bias);
    cudaGetSymbolAddress((void**)&xh,   g_xh);
    cudaGetSymbolAddress((void**)&ch,   g_ch);
    cudaGetSymbolAddress((void**)&q16,  g_q16);
    cudaGetSymbolAddress((void**)&kv16, g_kv16);
    cudaGetSymbolAddress((void**)&oh,   g_oh);
    cudaGetSymbolAddress((void**)&wqh,  g_wqh);
    cudaGetSymbolAddress((void**)&wkvh, g_wkvh);
    cudaGetSymbolAddress((void**)&woh,  g_woh);

    const int GEMM_SMEM = 2 * STG_B;   // 40960
    cudaFuncSetAttribute(gemm_cp, cudaFuncAttributeMaxDynamicSharedMemorySize, GEMM_SMEM);

    int n4q  = Dk * Dk / 8;
    int n4kv = 2 * Dk * Dk / 8;
    int n4x  = MQ * Dk / 8;

    cvt_kernel<<<(n4x + 255)/256, 256>>>((const float4*)x, (uint4*)xh, n4x);
    cvt_kernel<<<(n4q + 255)/256, 256>>>((const float4*)Wq, (uint4*)wqh, n4q);
    pool_kernel<<<dim3(Tt + 1, Bk), 256>>>(x, W_logit, ch);
    // Q = x @ Wq^T  -> fp16 packed
    gemm_cp<<<dim3(Dk/128, (MQ + 127)/128), 256, GEMM_SMEM>>>(xh, wqh, nullptr, nullptr, q16, MQ, Dk, Dk);
    cvt_kernel<<<(n4kv + 255)/256, 256>>>((const float4*)Wkv, (uint4*)wkvh, n4kv);
    cvt_kernel<<<(n4q + 255)/256, 256>>>((const float4*)Wo, (uint4*)woh, n4q);
    cpb_kernel<<<(NKp + 255) / 256, 256>>>(feats, maskp, cw1, cb1, cw2, cb2, biasb);
    // KV = ctx @ Wkv^T -> fp16 packed
    gemm_cp<<<dim3((2*Dk)/128, (MKV + 127)/128), 256, GEMM_SMEM>>>(ch, wkvh, nullptr, nullptr, kv16, MKV, 2*Dk, Dk);

    const size_t ATTN_SMEM = (size_t)(272*SPQ + 64*SPV + 128*SPQ) * sizeof(uint32_t); // 93440
    cudaFuncSetAttribute(attn_mma, cudaFuncAttributeMaxDynamicSharedMemorySize, (int)ATTN_SMEM);
    attn_mma<<<Bk * Hh, 256, ATTN_SMEM>>>(q16, kv16, biasb, oh);

    // out = O @ Wo^T + bo  (fp32)
    gemm_cp<<<dim3(Dk/128, (MQ + 127)/128), 256, GEMM_SMEM>>>(oh, woh, bo, out, nullptr, MQ, Dk, Dk);
}